// round 2
// baseline (speedup 1.0000x reference)
#include <cuda_runtime.h>
#include <cstdint>

#define BATCH    8
#define CDIM     512
#define NPOS     2048
#define HEADS    8
#define DIM_HEAD 64
#define HIDDEN   512          /* HEADS*DIM_HEAD */
#define QKV_ROWS 1536
#define EPS_LN   1e-5f

/* ---------------- scratch (static device globals; no cudaMalloc allowed) -------- */
__device__ float g_xn [BATCH * CDIM * NPOS];        /* 32 MB  normalized x        */
__device__ float g_qkv[BATCH * QKV_ROWS * NPOS];    /* 96 MB  q,k,v               */
__device__ float g_ao [BATCH * HIDDEN * NPOS];      /* 32 MB  attention output    */

/* ---------------- packed f32x2 helpers (FFMA2 doubles fp32 throughput) --------- */
__device__ __forceinline__ unsigned long long pk2(float lo, float hi) {
    unsigned long long r;
    asm("mov.b64 %0, {%1, %2};" : "=l"(r) : "f"(lo), "f"(hi));
    return r;
}
__device__ __forceinline__ void upk2(unsigned long long v, float &lo, float &hi) {
    asm("mov.b64 {%0, %1}, %2;" : "=f"(lo), "=f"(hi) : "l"(v));
}
__device__ __forceinline__ unsigned long long ffma2(unsigned long long a,
                                                    unsigned long long b,
                                                    unsigned long long c) {
    unsigned long long d;
    asm("fma.rn.f32x2 %0, %1, %2, %3;" : "=l"(d) : "l"(a), "l"(b), "l"(c));
    return d;
}
__device__ __forceinline__ unsigned long long fmul2(unsigned long long a,
                                                    unsigned long long b) {
    unsigned long long d;
    asm("mul.rn.f32x2 %0, %1, %2;" : "=l"(d) : "l"(a), "l"(b));
    return d;
}

/* =====================================================================
 * Kernel 1: channel LayerNorm.  x[b,c,n] -> xn[b,c,n]
 * block = 256 threads = 64 n-positions x 4 c-slices (128 c each).
 * ===================================================================== */
__global__ void ln_kernel(const float* __restrict__ x,
                          const float* __restrict__ g,
                          float* __restrict__ xn) {
    __shared__ float gs[CDIM];
    __shared__ float red[2][4][64];
    int t = threadIdx.x;
    for (int c = t; c < CDIM; c += 256) gs[c] = g[c];

    int nl = t & 63;          /* local n     */
    int cs = t >> 6;          /* c slice 0..3 */
    int pos0 = blockIdx.x * 64;           /* 2048 % 64 == 0: never straddles b */
    int b  = pos0 / NPOS;
    int n0 = pos0 % NPOS;

    const float* xp = x + (long)b * CDIM * NPOS + n0 + nl;
    float s = 0.f, ss = 0.f;
    #pragma unroll 8
    for (int c = cs * 128; c < cs * 128 + 128; c++) {
        float v = xp[(long)c * NPOS];
        s += v; ss += v * v;
    }
    red[0][cs][nl] = s;  red[1][cs][nl] = ss;
    __syncthreads();
    float st  = red[0][0][nl] + red[0][1][nl] + red[0][2][nl] + red[0][3][nl];
    float sst = red[1][0][nl] + red[1][1][nl] + red[1][2][nl] + red[1][3][nl];
    float mean = st * (1.f / CDIM);
    float inv  = rsqrtf(sst * (1.f / CDIM) - mean * mean + EPS_LN);

    float* op = xn + (long)b * CDIM * NPOS + n0 + nl;
    #pragma unroll 8
    for (int c = cs * 128; c < cs * 128 + 128; c++) {
        float v = xp[(long)c * NPOS];
        op[(long)c * NPOS] = (v - mean) * inv * gs[c];
    }
}

/* =====================================================================
 * Kernel 2/4: C[b,m,n] = sum_k A[m,k]*B[b,k,n] (+bias[m])
 * A row-major [M,K] (small weight), B [K,NPOS] per batch, N=NPOS.
 * Tile: 128(M) x 64(N) x 16(K), 256 threads, per-thread 8x4 via f32x2.
 * Requires M%128==0, K%16==0.
 * ===================================================================== */
__global__ void __launch_bounds__(256)
gemm_wx(const float* __restrict__ A, const float* __restrict__ Bm,
        float* __restrict__ C, const float* __restrict__ bias,
        int M, int K) {
    __shared__ float As[16][128];
    __shared__ float Bs[16][64];
    int t  = threadIdx.x;
    int m0 = blockIdx.x * 128;
    int n0 = blockIdx.y * 64;
    int b  = blockIdx.z;
    const float* Bb = Bm + (long)b * K * NPOS;
    float*       Cb = C  + (long)b * M * NPOS;

    int tm = t >> 4;            /* 0..15 */
    int tn = t & 15;            /* 0..15 */
    int mb = tm * 8, nb = tn * 4;

    unsigned long long acc[4][4];   /* [m-pair][n] */
    #pragma unroll
    for (int i = 0; i < 4; i++)
        #pragma unroll
        for (int j = 0; j < 4; j++) acc[i][j] = 0ull;

    for (int k0 = 0; k0 < K; k0 += 16) {
        /* load A tile 128x16 (transposed into smem) */
        #pragma unroll
        for (int s = 0; s < 2; s++) {
            int lin = s * 256 + t;                 /* 0..511 float4s */
            int row = lin >> 2, q = (lin & 3) * 4;
            float4 av = *(const float4*)(A + (long)(m0 + row) * K + k0 + q);
            As[q + 0][row] = av.x; As[q + 1][row] = av.y;
            As[q + 2][row] = av.z; As[q + 3][row] = av.w;
        }
        /* load B tile 16x64 */
        {
            int row = t >> 4, q = (t & 15) * 4;
            *(float4*)&Bs[row][q] =
                *(const float4*)(Bb + (long)(k0 + row) * NPOS + n0 + q);
        }
        __syncthreads();
        #pragma unroll
        for (int kk = 0; kk < 16; kk++) {
            ulonglong2 aA = *(ulonglong2*)&As[kk][mb];
            ulonglong2 aB = *(ulonglong2*)&As[kk][mb + 4];
            unsigned long long ap[4] = {aA.x, aA.y, aB.x, aB.y};
            float4 b4 = *(float4*)&Bs[kk][nb];
            unsigned long long bp[4] = {pk2(b4.x, b4.x), pk2(b4.y, b4.y),
                                        pk2(b4.z, b4.z), pk2(b4.w, b4.w)};
            #pragma unroll
            for (int mp = 0; mp < 4; mp++)
                #pragma unroll
                for (int n = 0; n < 4; n++)
                    acc[mp][n] = ffma2(ap[mp], bp[n], acc[mp][n]);
        }
        __syncthreads();
    }

    #pragma unroll
    for (int mp = 0; mp < 4; mp++) {
        float lo[4], hi[4];
        #pragma unroll
        for (int n = 0; n < 4; n++) upk2(acc[mp][n], lo[n], hi[n]);
        int m_lo = m0 + mb + 2 * mp, m_hi = m_lo + 1;
        float b0 = bias ? bias[m_lo] : 0.f;
        float b1 = bias ? bias[m_hi] : 0.f;
        float4 vlo = make_float4(lo[0] + b0, lo[1] + b0, lo[2] + b0, lo[3] + b0);
        float4 vhi = make_float4(hi[0] + b1, hi[1] + b1, hi[2] + b1, hi[3] + b1);
        *(float4*)(Cb + (long)m_lo * NPOS + n0 + nb) = vlo;
        *(float4*)(Cb + (long)m_hi * NPOS + n0 + nb) = vhi;
    }
}

/* =====================================================================
 * Kernel 3: fused flash attention per (b,h).
 * Block: 128 query positions, loops 32 kv tiles of 64.
 * smem: Qs[64][128] Ks[64][64] Vt[64][68] Ps[128][68]  = 101376 B (dynamic)
 * Thread map: ig=t>>3 (i tile of 4), jg=t&7 (8 j's in S phase / 8 d's in PV).
 * ===================================================================== */
#define QS(d,i)  Qs[(d) * 128 + (i)]
#define KS(d,j)  Ks[(d) * 64 + (j)]
#define VT(j,d)  Vt[(j) * 68 + (d)]
#define PSM(i,j) Ps[(i) * 68 + (j)]

__global__ void __launch_bounds__(256, 2)
attn_kernel(const float* __restrict__ qkv, float* __restrict__ ao) {
    extern __shared__ float sm[];
    float* Qs = sm;                       /* 8192  */
    float* Ks = sm + 8192;                /* 4096  */
    float* Vt = sm + 12288;               /* 4352  */
    float* Ps = sm + 16640;               /* 8704  */

    int t  = threadIdx.x;
    int qt = blockIdx.x;                  /* 0..15 */
    int bh = blockIdx.y;                  /* 0..63 */
    int b  = bh >> 3, h = bh & 7;
    const float scale = 0.125f;           /* DIM_HEAD^-0.5 */

    long base = (long)b * QKV_ROWS * NPOS + (long)h * DIM_HEAD * NPOS;
    const float* qp = qkv + base;
    const float* kp = qkv + base + (long)HIDDEN * NPOS;
    const float* vp = qkv + base + 2L * HIDDEN * NPOS;
    int i0 = qt * 128;

    /* load Q tile (scaled) */
    #pragma unroll
    for (int s = 0; s < 8; s++) {
        int lin = s * 256 + t;            /* 0..2047 float4s */
        int d = lin >> 5, i = (lin & 31) << 2;
        float4 v = *(const float4*)(qp + (long)d * NPOS + i0 + i);
        v.x *= scale; v.y *= scale; v.z *= scale; v.w *= scale;
        *(float4*)&QS(d, i) = v;
    }

    int ig = t >> 3, jg = t & 7;
    int i_base = ig * 4;
    int jd_base = jg * 8;                 /* j_base in S phase, d_base in PV */

    float m_i[4], l_i[4];
    unsigned long long o2[4][4];          /* O[4 rows][8 d] as d-pairs */
    #pragma unroll
    for (int r = 0; r < 4; r++) {
        m_i[r] = -1e30f; l_i[r] = 0.f;
        #pragma unroll
        for (int c = 0; c < 4; c++) o2[r][c] = 0ull;
    }

    for (int j0 = 0; j0 < NPOS; j0 += 64) {
        /* load K tile [d][j] */
        #pragma unroll
        for (int s = 0; s < 4; s++) {
            int lin = s * 256 + t;        /* 0..1023 float4s */
            int d = lin >> 4, j = (lin & 15) << 2;
            *(float4*)&KS(d, j) = *(const float4*)(kp + (long)d * NPOS + j0 + j);
        }
        /* load V tile transposed -> Vt[j][d] */
        #pragma unroll
        for (int s = 0; s < 4; s++) {
            int lin = s * 256 + t;
            int d = lin >> 4, j = (lin & 15) << 2;
            float4 v = *(const float4*)(vp + (long)d * NPOS + j0 + j);
            VT(j + 0, d) = v.x; VT(j + 1, d) = v.y;
            VT(j + 2, d) = v.z; VT(j + 3, d) = v.w;
        }
        __syncthreads();                  /* (a) tiles ready */

        /* ---- S = Q^T K : per-thread 4(i) x 8(j), j packed in pairs ---- */
        unsigned long long s2[4][4];
        #pragma unroll
        for (int r = 0; r < 4; r++)
            #pragma unroll
            for (int c = 0; c < 4; c++) s2[r][c] = 0ull;

        #pragma unroll 8
        for (int d = 0; d < 64; d++) {
            ulonglong2 k01 = *(ulonglong2*)&KS(d, jd_base);
            ulonglong2 k23 = *(ulonglong2*)&KS(d, jd_base + 4);
            unsigned long long kpair[4] = {k01.x, k01.y, k23.x, k23.y};
            float4 q4 = *(float4*)&QS(d, i_base);
            unsigned long long qq[4] = {pk2(q4.x, q4.x), pk2(q4.y, q4.y),
                                        pk2(q4.z, q4.z), pk2(q4.w, q4.w)};
            #pragma unroll
            for (int r = 0; r < 4; r++)
                #pragma unroll
                for (int c = 0; c < 4; c++)
                    s2[r][c] = ffma2(qq[r], kpair[c], s2[r][c]);
        }

        /* ---- online softmax (row groups of 8 lanes: jg = lane&7) ---- */
        #pragma unroll
        for (int r = 0; r < 4; r++) {
            float sv[8];
            upk2(s2[r][0], sv[0], sv[1]); upk2(s2[r][1], sv[2], sv[3]);
            upk2(s2[r][2], sv[4], sv[5]); upk2(s2[r][3], sv[6], sv[7]);
            float mx = sv[0];
            #pragma unroll
            for (int c = 1; c < 8; c++) mx = fmaxf(mx, sv[c]);
            mx = fmaxf(mx, __shfl_xor_sync(0xffffffffu, mx, 1));
            mx = fmaxf(mx, __shfl_xor_sync(0xffffffffu, mx, 2));
            mx = fmaxf(mx, __shfl_xor_sync(0xffffffffu, mx, 4));
            float mnew = fmaxf(m_i[r], mx);
            float sum = 0.f;
            #pragma unroll
            for (int c = 0; c < 8; c++) {
                float p = __expf(sv[c] - mnew);
                sv[c] = p; sum += p;
            }
            sum += __shfl_xor_sync(0xffffffffu, sum, 1);
            sum += __shfl_xor_sync(0xffffffffu, sum, 2);
            sum += __shfl_xor_sync(0xffffffffu, sum, 4);
            float alpha = __expf(m_i[r] - mnew);
            l_i[r] = l_i[r] * alpha + sum;
            m_i[r] = mnew;
            unsigned long long aa = pk2(alpha, alpha);
            #pragma unroll
            for (int c = 0; c < 4; c++) o2[r][c] = fmul2(o2[r][c], aa);
            *(float4*)&PSM(i_base + r, jd_base) =
                make_float4(sv[0], sv[1], sv[2], sv[3]);
            *(float4*)&PSM(i_base + r, jd_base + 4) =
                make_float4(sv[4], sv[5], sv[6], sv[7]);
        }
        __syncthreads();                  /* (c) P visible */

        /* ---- O += P V^T : per-thread 4(i) x 8(d), d packed in pairs ---- */
        #pragma unroll 8
        for (int j = 0; j < 64; j++) {
            float p0 = PSM(i_base + 0, j);
            float p1 = PSM(i_base + 1, j);
            float p2 = PSM(i_base + 2, j);
            float p3 = PSM(i_base + 3, j);
            ulonglong2 v01 = *(ulonglong2*)&VT(j, jd_base);
            ulonglong2 v23 = *(ulonglong2*)&VT(j, jd_base + 4);
            unsigned long long vv[4] = {v01.x, v01.y, v23.x, v23.y};
            unsigned long long pp0 = pk2(p0, p0), pp1 = pk2(p1, p1);
            unsigned long long pp2 = pk2(p2, p2), pp3 = pk2(p3, p3);
            #pragma unroll
            for (int c = 0; c < 4; c++) {
                o2[0][c] = ffma2(pp0, vv[c], o2[0][c]);
                o2[1][c] = ffma2(pp1, vv[c], o2[1][c]);
                o2[2][c] = ffma2(pp2, vv[c], o2[2][c]);
                o2[3][c] = ffma2(pp3, vv[c], o2[3][c]);
            }
        }
        __syncthreads();                  /* (d) before overwriting tiles */
    }

    /* ---- epilogue: ao[b, h*64+d, i0+i] = O[i][d] / l[i] ---- */
    float ov[4][8];
    #pragma unroll
    for (int r = 0; r < 4; r++) {
        float invl = 1.f / l_i[r];
        #pragma unroll
        for (int c = 0; c < 4; c++) {
            float lo, hi;
            upk2(o2[r][c], lo, hi);
            ov[r][2 * c] = lo * invl; ov[r][2 * c + 1] = hi * invl;
        }
    }
    float* aop = ao + (long)b * HIDDEN * NPOS + (long)h * DIM_HEAD * NPOS
               + i0 + i_base;
    #pragma unroll
    for (int dd = 0; dd < 8; dd++) {
        float4 v = make_float4(ov[0][dd], ov[1][dd], ov[2][dd], ov[3][dd]);
        *(float4*)(aop + (long)(jd_base + dd) * NPOS) = v;
    }
}

/* ===================================================================== */
extern "C" void kernel_launch(void* const* d_in, const int* in_sizes, int n_in,
                              void* d_out, int out_size) {
    const float* x    = (const float*)d_in[0];
    const float* g    = (const float*)d_in[1];
    const float* Wqkv = (const float*)d_in[2];
    const float* Wout = (const float*)d_in[3];
    const float* bout = (const float*)d_in[4];
    float* out = (float*)d_out;

    float *xn, *qkv, *ao;
    cudaGetSymbolAddress((void**)&xn,  g_xn);
    cudaGetSymbolAddress((void**)&qkv, g_qkv);
    cudaGetSymbolAddress((void**)&ao,  g_ao);

    /* 1. LayerNorm */
    ln_kernel<<<(BATCH * NPOS) / 64, 256>>>(x, g, xn);

    /* 2. QKV projection */
    gemm_wx<<<dim3(QKV_ROWS / 128, NPOS / 64, BATCH), 256>>>(
        Wqkv, xn, qkv, nullptr, QKV_ROWS, CDIM);

    /* 3. attention */
    size_t smem = 25344 * sizeof(float);   /* 101376 B */
    cudaFuncSetAttribute(attn_kernel,
                         cudaFuncAttributeMaxDynamicSharedMemorySize,
                         (int)smem);
    attn_kernel<<<dim3(NPOS / 128, BATCH * HEADS), 256, smem>>>(qkv, ao);

    /* 4. output projection + bias */
    gemm_wx<<<dim3(HIDDEN / 128, NPOS / 64, BATCH), 256>>>(
        Wout, ao, out, bout, HIDDEN, CDIM);
}

// round 3
// speedup vs baseline: 3.1442x; 3.1442x over previous
#include <cuda_runtime.h>
#include <cstdint>

#define BATCH    8
#define CDIM     512
#define NPOS     2048
#define HEADS    8
#define DIM_HEAD 64
#define HIDDEN   512
#define QKV_ROWS 1536
#define EPS_LN   1e-5f

/* ---------------- scratch (static device globals) ---------------- */
__device__ float g_xn [BATCH * CDIM * NPOS];
__device__ float g_qkv[BATCH * QKV_ROWS * NPOS];
__device__ float g_ao [BATCH * HIDDEN * NPOS];

/* ---------------- tf32 mma helpers ---------------- */
__device__ __forceinline__ uint32_t f2tf(float f) {
    uint32_t u;
    asm("cvt.rna.tf32.f32 %0, %1;" : "=r"(u) : "f"(f));
    return u;
}
__device__ __forceinline__ void mma_tf32(float& c0, float& c1, float& c2, float& c3,
                                         uint32_t a0, uint32_t a1, uint32_t a2, uint32_t a3,
                                         uint32_t b0, uint32_t b1) {
    asm("mma.sync.aligned.m16n8k8.row.col.f32.tf32.tf32.f32 "
        "{%0,%1,%2,%3},{%4,%5,%6,%7},{%8,%9},{%0,%1,%2,%3};"
        : "+f"(c0), "+f"(c1), "+f"(c2), "+f"(c3)
        : "r"(a0), "r"(a1), "r"(a2), "r"(a3), "r"(b0), "r"(b1));
}

/* =====================================================================
 * Kernel 1: channel LayerNorm (unchanged — memory-bound, fine)
 * ===================================================================== */
__global__ void ln_kernel(const float* __restrict__ x,
                          const float* __restrict__ g,
                          float* __restrict__ xn) {
    __shared__ float gs[CDIM];
    __shared__ float red[2][4][64];
    int t = threadIdx.x;
    for (int c = t; c < CDIM; c += 256) gs[c] = g[c];

    int nl = t & 63;
    int cs = t >> 6;
    int pos0 = blockIdx.x * 64;
    int b  = pos0 / NPOS;
    int n0 = pos0 % NPOS;

    const float* xp = x + (long)b * CDIM * NPOS + n0 + nl;
    float s = 0.f, ss = 0.f;
    #pragma unroll 8
    for (int c = cs * 128; c < cs * 128 + 128; c++) {
        float v = xp[(long)c * NPOS];
        s += v; ss += v * v;
    }
    red[0][cs][nl] = s;  red[1][cs][nl] = ss;
    __syncthreads();
    float st  = red[0][0][nl] + red[0][1][nl] + red[0][2][nl] + red[0][3][nl];
    float sst = red[1][0][nl] + red[1][1][nl] + red[1][2][nl] + red[1][3][nl];
    float mean = st * (1.f / CDIM);
    float inv  = rsqrtf(sst * (1.f / CDIM) - mean * mean + EPS_LN);

    float* op = xn + (long)b * CDIM * NPOS + n0 + nl;
    #pragma unroll 8
    for (int c = cs * 128; c < cs * 128 + 128; c++) {
        float v = xp[(long)c * NPOS];
        op[(long)c * NPOS] = (v - mean) * inv * gs[c];
    }
}

/* =====================================================================
 * Kernel 2/4: TF32 tensor-core GEMM.  C[b,m,n] = A[m,k] * B[b,k,n] (+bias)
 * Block tile 128m x 128n x 32k. 8 warps (2m x 4n), warp tile 64m x 32n.
 * A staged [m][k] pad 36, B staged [k][n] pad 132 (conflict-free frags).
 * ===================================================================== */
__global__ void __launch_bounds__(256, 2)
gemm_tc(const float* __restrict__ A, const float* __restrict__ Bm,
        float* __restrict__ C, const float* __restrict__ bias,
        int M, int K) {
    __shared__ uint32_t As[128 * 36];
    __shared__ uint32_t Bs[32 * 132];
    int t = threadIdx.x, lane = t & 31, w = t >> 5;
    int m0 = blockIdx.x * 128, n0 = blockIdx.y * 128, b = blockIdx.z;
    const float* Ab = A  + (long)m0 * K;
    const float* Bb = Bm + (long)b * K * NPOS + n0;
    float*       Cb = C  + (long)b * M * NPOS;

    int wm = (w >> 2) * 64;   /* 0 / 64        */
    int wn = (w & 3) * 32;    /* 0/32/64/96    */
    int g  = lane >> 2, tg = lane & 3;

    float acc[4][4][4];
    #pragma unroll
    for (int i = 0; i < 4; i++)
        #pragma unroll
        for (int j = 0; j < 4; j++)
            #pragma unroll
            for (int r = 0; r < 4; r++) acc[i][j][r] = 0.f;

    for (int k0 = 0; k0 < K; k0 += 32) {
        #pragma unroll
        for (int s = 0; s < 4; s++) {              /* A tile 128x32 */
            int lin = s * 256 + t;
            int row = lin >> 3, col = (lin & 7) << 2;
            float4 v = *(const float4*)(Ab + (long)row * K + k0 + col);
            uint32_t* p = &As[row * 36 + col];
            p[0] = f2tf(v.x); p[1] = f2tf(v.y); p[2] = f2tf(v.z); p[3] = f2tf(v.w);
        }
        #pragma unroll
        for (int s = 0; s < 4; s++) {              /* B tile 32x128 */
            int lin = s * 256 + t;
            int row = lin >> 5, col = (lin & 31) << 2;
            float4 v = *(const float4*)(Bb + (long)(k0 + row) * NPOS + col);
            uint32_t* p = &Bs[row * 132 + col];
            p[0] = f2tf(v.x); p[1] = f2tf(v.y); p[2] = f2tf(v.z); p[3] = f2tf(v.w);
        }
        __syncthreads();

        #pragma unroll
        for (int kk = 0; kk < 32; kk += 8) {
            uint32_t af[4][4];
            #pragma unroll
            for (int mt = 0; mt < 4; mt++) {
                int r = wm + mt * 16 + g;
                af[mt][0] = As[r * 36 + kk + tg];
                af[mt][1] = As[(r + 8) * 36 + kk + tg];
                af[mt][2] = As[r * 36 + kk + tg + 4];
                af[mt][3] = As[(r + 8) * 36 + kk + tg + 4];
            }
            uint32_t bf[4][2];
            #pragma unroll
            for (int nt = 0; nt < 4; nt++) {
                int c = wn + nt * 8 + g;
                bf[nt][0] = Bs[(kk + tg) * 132 + c];
                bf[nt][1] = Bs[(kk + tg + 4) * 132 + c];
            }
            #pragma unroll
            for (int mt = 0; mt < 4; mt++)
                #pragma unroll
                for (int nt = 0; nt < 4; nt++)
                    mma_tf32(acc[mt][nt][0], acc[mt][nt][1], acc[mt][nt][2], acc[mt][nt][3],
                             af[mt][0], af[mt][1], af[mt][2], af[mt][3],
                             bf[nt][0], bf[nt][1]);
        }
        __syncthreads();
    }

    #pragma unroll
    for (int mt = 0; mt < 4; mt++) {
        int r0 = m0 + wm + mt * 16 + g;
        float b0 = bias ? bias[r0]     : 0.f;
        float b1 = bias ? bias[r0 + 8] : 0.f;
        #pragma unroll
        for (int nt = 0; nt < 4; nt++) {
            int c0 = n0 + wn + nt * 8 + 2 * tg;
            float2 vlo = make_float2(acc[mt][nt][0] + b0, acc[mt][nt][1] + b0);
            float2 vhi = make_float2(acc[mt][nt][2] + b1, acc[mt][nt][3] + b1);
            *(float2*)(Cb + (long)r0 * NPOS + c0)       = vlo;
            *(float2*)(Cb + (long)(r0 + 8) * NPOS + c0) = vhi;
        }
    }
}

/* =====================================================================
 * Kernel 3: fused TF32 flash attention per (b,h).
 * Block: 128 queries, 8 warps x 16 rows. KV tile 64. d = 64.
 * smem (tf32 words): Qs[64][132], Ks[64][68], Vs[64][68], Ps[128][68]
 *                    = 103424 B dynamic.
 * ===================================================================== */
__global__ void __launch_bounds__(256, 2)
attn_tc(const float* __restrict__ qkv, float* __restrict__ ao) {
    extern __shared__ uint32_t sm4[];
    uint32_t* Qs = sm4;                     /* [d][i] 64 x 132 */
    uint32_t* Ks = sm4 + 64 * 132;          /* [d][j] 64 x 68  */
    uint32_t* Vs = Ks + 64 * 68;            /* [d][j] 64 x 68  */
    uint32_t* Ps = Vs + 64 * 68;            /* [i][j] 128 x 68 */

    int t = threadIdx.x, lane = t & 31, w = t >> 5;
    int g = lane >> 2, tg = lane & 3;
    int iw = w * 16;                        /* warp's 16 query rows */

    int qt = blockIdx.x;                    /* 0..15 */
    int bh = blockIdx.y;                    /* 0..63 */
    int b  = bh >> 3, h = bh & 7;
    int i0 = qt * 128;
    const float scale = 0.125f;

    long base = (long)b * QKV_ROWS * NPOS + (long)h * DIM_HEAD * NPOS;
    const float* qp = qkv + base;
    const float* kp = qkv + base + (long)HIDDEN * NPOS;
    const float* vp = qkv + base + 2L * HIDDEN * NPOS;

    /* load Q tile (scaled, tf32) */
    #pragma unroll
    for (int s = 0; s < 8; s++) {
        int lin = s * 256 + t;
        int d = lin >> 5, i = (lin & 31) << 2;
        float4 v = *(const float4*)(qp + (long)d * NPOS + i0 + i);
        uint32_t* p = &Qs[d * 132 + i];
        p[0] = f2tf(v.x * scale); p[1] = f2tf(v.y * scale);
        p[2] = f2tf(v.z * scale); p[3] = f2tf(v.w * scale);
    }

    float m0s = -1e30f, m1s = -1e30f, l0 = 0.f, l1 = 0.f;
    float o[8][4];
    #pragma unroll
    for (int nt = 0; nt < 8; nt++)
        #pragma unroll
        for (int r = 0; r < 4; r++) o[nt][r] = 0.f;

    for (int j0 = 0; j0 < NPOS; j0 += 64) {
        __syncthreads();                    /* prev iter done with Ks/Vs */
        #pragma unroll
        for (int s = 0; s < 4; s++) {       /* K tile 64x64 */
            int lin = s * 256 + t;
            int d = lin >> 4, j = (lin & 15) << 2;
            float4 v = *(const float4*)(kp + (long)d * NPOS + j0 + j);
            uint32_t* p = &Ks[d * 68 + j];
            p[0] = f2tf(v.x); p[1] = f2tf(v.y); p[2] = f2tf(v.z); p[3] = f2tf(v.w);
        }
        #pragma unroll
        for (int s = 0; s < 4; s++) {       /* V tile 64x64 */
            int lin = s * 256 + t;
            int d = lin >> 4, j = (lin & 15) << 2;
            float4 v = *(const float4*)(vp + (long)d * NPOS + j0 + j);
            uint32_t* p = &Vs[d * 68 + j];
            p[0] = f2tf(v.x); p[1] = f2tf(v.y); p[2] = f2tf(v.z); p[3] = f2tf(v.w);
        }
        __syncthreads();

        /* ---- S = Q^T K : warp tile 16i x 64j ---- */
        float sa[8][4];
        #pragma unroll
        for (int nt = 0; nt < 8; nt++)
            #pragma unroll
            for (int r = 0; r < 4; r++) sa[nt][r] = 0.f;

        #pragma unroll
        for (int kk = 0; kk < 64; kk += 8) {
            uint32_t a0 = Qs[(kk + tg) * 132 + iw + g];
            uint32_t a1 = Qs[(kk + tg) * 132 + iw + g + 8];
            uint32_t a2 = Qs[(kk + tg + 4) * 132 + iw + g];
            uint32_t a3 = Qs[(kk + tg + 4) * 132 + iw + g + 8];
            #pragma unroll
            for (int nt = 0; nt < 8; nt++) {
                uint32_t b0 = Ks[(kk + tg) * 68 + nt * 8 + g];
                uint32_t b1 = Ks[(kk + tg + 4) * 68 + nt * 8 + g];
                mma_tf32(sa[nt][0], sa[nt][1], sa[nt][2], sa[nt][3],
                         a0, a1, a2, a3, b0, b1);
            }
        }

        /* ---- online softmax (rows iw+g and iw+g+8) ---- */
        float mx0 = -1e30f, mx1 = -1e30f;
        #pragma unroll
        for (int nt = 0; nt < 8; nt++) {
            mx0 = fmaxf(mx0, fmaxf(sa[nt][0], sa[nt][1]));
            mx1 = fmaxf(mx1, fmaxf(sa[nt][2], sa[nt][3]));
        }
        mx0 = fmaxf(mx0, __shfl_xor_sync(0xffffffffu, mx0, 1));
        mx0 = fmaxf(mx0, __shfl_xor_sync(0xffffffffu, mx0, 2));
        mx1 = fmaxf(mx1, __shfl_xor_sync(0xffffffffu, mx1, 1));
        mx1 = fmaxf(mx1, __shfl_xor_sync(0xffffffffu, mx1, 2));
        float mn0 = fmaxf(m0s, mx0), mn1 = fmaxf(m1s, mx1);
        float sum0 = 0.f, sum1 = 0.f;
        #pragma unroll
        for (int nt = 0; nt < 8; nt++) {
            sa[nt][0] = __expf(sa[nt][0] - mn0);
            sa[nt][1] = __expf(sa[nt][1] - mn0);
            sa[nt][2] = __expf(sa[nt][2] - mn1);
            sa[nt][3] = __expf(sa[nt][3] - mn1);
            sum0 += sa[nt][0] + sa[nt][1];
            sum1 += sa[nt][2] + sa[nt][3];
        }
        sum0 += __shfl_xor_sync(0xffffffffu, sum0, 1);
        sum0 += __shfl_xor_sync(0xffffffffu, sum0, 2);
        sum1 += __shfl_xor_sync(0xffffffffu, sum1, 1);
        sum1 += __shfl_xor_sync(0xffffffffu, sum1, 2);
        float a0f = __expf(m0s - mn0), a1f = __expf(m1s - mn1);
        l0 = l0 * a0f + sum0;  m0s = mn0;
        l1 = l1 * a1f + sum1;  m1s = mn1;
        #pragma unroll
        for (int nt = 0; nt < 8; nt++) {
            o[nt][0] *= a0f; o[nt][1] *= a0f;
            o[nt][2] *= a1f; o[nt][3] *= a1f;
        }
        /* write P (tf32) — warp-local rows, no block sync needed */
        #pragma unroll
        for (int nt = 0; nt < 8; nt++) {
            int jc = nt * 8 + 2 * tg;
            uint2 v0 = make_uint2(f2tf(sa[nt][0]), f2tf(sa[nt][1]));
            uint2 v1 = make_uint2(f2tf(sa[nt][2]), f2tf(sa[nt][3]));
            *(uint2*)&Ps[(iw + g) * 68 + jc]     = v0;
            *(uint2*)&Ps[(iw + g + 8) * 68 + jc] = v1;
        }
        __syncwarp();

        /* ---- O += P V^T : warp tile 16i x 64d ---- */
        #pragma unroll
        for (int kk = 0; kk < 64; kk += 8) {
            uint32_t a0 = Ps[(iw + g) * 68 + kk + tg];
            uint32_t a1 = Ps[(iw + g + 8) * 68 + kk + tg];
            uint32_t a2 = Ps[(iw + g) * 68 + kk + tg + 4];
            uint32_t a3 = Ps[(iw + g + 8) * 68 + kk + tg + 4];
            #pragma unroll
            for (int nt = 0; nt < 8; nt++) {
                uint32_t b0 = Vs[(nt * 8 + g) * 68 + kk + tg];
                uint32_t b1 = Vs[(nt * 8 + g) * 68 + kk + tg + 4];
                mma_tf32(o[nt][0], o[nt][1], o[nt][2], o[nt][3],
                         a0, a1, a2, a3, b0, b1);
            }
        }
    }

    /* ---- epilogue: normalize, transpose through Qs, coalesced store ---- */
    float inv0 = 1.f / l0, inv1 = 1.f / l1;
    __syncthreads();                        /* done reading Qs everywhere */
    #pragma unroll
    for (int nt = 0; nt < 8; nt++) {
        int d0 = nt * 8 + 2 * tg;
        Qs[d0 * 132 + iw + g]           = __float_as_uint(o[nt][0] * inv0);
        Qs[(d0 + 1) * 132 + iw + g]     = __float_as_uint(o[nt][1] * inv0);
        Qs[d0 * 132 + iw + g + 8]       = __float_as_uint(o[nt][2] * inv1);
        Qs[(d0 + 1) * 132 + iw + g + 8] = __float_as_uint(o[nt][3] * inv1);
    }
    __syncthreads();
    float* aop = ao + (long)b * HIDDEN * NPOS + (long)h * DIM_HEAD * NPOS + i0;
    #pragma unroll
    for (int s = 0; s < 8; s++) {
        int lin = s * 256 + t;
        int d = lin >> 5, i = (lin & 31) << 2;
        float4 v;
        v.x = __uint_as_float(Qs[d * 132 + i]);
        v.y = __uint_as_float(Qs[d * 132 + i + 1]);
        v.z = __uint_as_float(Qs[d * 132 + i + 2]);
        v.w = __uint_as_float(Qs[d * 132 + i + 3]);
        *(float4*)(aop + (long)d * NPOS + i) = v;
    }
}

/* ===================================================================== */
extern "C" void kernel_launch(void* const* d_in, const int* in_sizes, int n_in,
                              void* d_out, int out_size) {
    const float* x    = (const float*)d_in[0];
    const float* g    = (const float*)d_in[1];
    const float* Wqkv = (const float*)d_in[2];
    const float* Wout = (const float*)d_in[3];
    const float* bout = (const float*)d_in[4];
    float* out = (float*)d_out;

    float *xn, *qkv, *ao;
    cudaGetSymbolAddress((void**)&xn,  g_xn);
    cudaGetSymbolAddress((void**)&qkv, g_qkv);
    cudaGetSymbolAddress((void**)&ao,  g_ao);

    /* 1. LayerNorm */
    ln_kernel<<<(BATCH * NPOS) / 64, 256>>>(x, g, xn);

    /* 2. QKV projection (TF32 TC) */
    gemm_tc<<<dim3(QKV_ROWS / 128, NPOS / 128, BATCH), 256>>>(
        Wqkv, xn, qkv, nullptr, QKV_ROWS, CDIM);

    /* 3. fused attention (TF32 TC) */
    size_t smem = (64 * 132 + 2 * 64 * 68 + 128 * 68) * sizeof(uint32_t); /* 103424 */
    cudaFuncSetAttribute(attn_tc,
                         cudaFuncAttributeMaxDynamicSharedMemorySize, (int)smem);
    attn_tc<<<dim3(NPOS / 128, BATCH * HEADS), 256, smem>>>(qkv, ao);

    /* 4. output projection + bias (TF32 TC) */
    gemm_tc<<<dim3(HIDDEN / 128, NPOS / 128, BATCH), 256>>>(
        Wout, ao, out, bout, HIDDEN, CDIM);
}

// round 5
// speedup vs baseline: 3.8568x; 1.2267x over previous
#include <cuda_runtime.h>
#include <cstdint>

#define BATCH    8
#define CDIM     512
#define NPOS     2048
#define HEADS    8
#define DIM_HEAD 64
#define HIDDEN   512
#define QKV_ROWS 1536
#define EPS_LN   1e-5f

/* ---------------- scratch (static device globals) ---------------- */
__device__ float g_xn [BATCH * CDIM * NPOS];      /* tf32-rounded LN output   */
__device__ float g_qkv[BATCH * QKV_ROWS * NPOS];  /* tf32-rounded q,k,v       */
__device__ float g_ao [BATCH * HIDDEN * NPOS];    /* tf32-rounded attn output */
__device__ float g_wq [QKV_ROWS * CDIM];          /* tf32-rounded W_qkv       */
__device__ float g_wo [CDIM * HIDDEN];            /* tf32-rounded W_out       */

/* ---------------- helpers ---------------- */
__device__ __forceinline__ uint32_t f2tf(float f) {
    uint32_t u;
    asm("cvt.rna.tf32.f32 %0, %1;" : "=r"(u) : "f"(f));
    return u;
}
__device__ __forceinline__ void mma_tf32(float& c0, float& c1, float& c2, float& c3,
                                         uint32_t a0, uint32_t a1, uint32_t a2, uint32_t a3,
                                         uint32_t b0, uint32_t b1) {
    asm("mma.sync.aligned.m16n8k8.row.col.f32.tf32.tf32.f32 "
        "{%0,%1,%2,%3},{%4,%5,%6,%7},{%8,%9},{%0,%1,%2,%3};"
        : "+f"(c0), "+f"(c1), "+f"(c2), "+f"(c3)
        : "r"(a0), "r"(a1), "r"(a2), "r"(a3), "r"(b0), "r"(b1));
}
__device__ __forceinline__ void cpasync16(uint32_t dst, const void* src) {
    asm volatile("cp.async.cg.shared.global [%0], [%1], 16;" :: "r"(dst), "l"(src));
}
#define CP_COMMIT() asm volatile("cp.async.commit_group;")
#define CP_WAIT(n)  asm volatile("cp.async.wait_group %0;" :: "n"(n))

/* =====================================================================
 * Kernel 0: one-time tf32 rounding of weights
 * ===================================================================== */
__global__ void round_copy(const float* __restrict__ src, float* __restrict__ dst) {
    int i = (blockIdx.x * 256 + threadIdx.x) * 4;
    float4 v = *(const float4*)(src + i);
    v.x = __uint_as_float(f2tf(v.x));
    v.y = __uint_as_float(f2tf(v.y));
    v.z = __uint_as_float(f2tf(v.z));
    v.w = __uint_as_float(f2tf(v.w));
    *(float4*)(dst + i) = v;
}

/* =====================================================================
 * Kernel 1: channel LayerNorm, output tf32-rounded
 * ===================================================================== */
__global__ void ln_kernel(const float* __restrict__ x,
                          const float* __restrict__ g,
                          float* __restrict__ xn) {
    __shared__ float gs[CDIM];
    __shared__ float red[2][4][64];
    int t = threadIdx.x;
    for (int c = t; c < CDIM; c += 256) gs[c] = g[c];

    int nl = t & 63;
    int cs = t >> 6;
    int pos0 = blockIdx.x * 64;
    int b  = pos0 / NPOS;
    int n0 = pos0 % NPOS;

    const float* xp = x + (long)b * CDIM * NPOS + n0 + nl;
    float s = 0.f, ss = 0.f;
    #pragma unroll 8
    for (int c = cs * 128; c < cs * 128 + 128; c++) {
        float v = xp[(long)c * NPOS];
        s += v; ss += v * v;
    }
    red[0][cs][nl] = s;  red[1][cs][nl] = ss;
    __syncthreads();
    float st  = red[0][0][nl] + red[0][1][nl] + red[0][2][nl] + red[0][3][nl];
    float sst = red[1][0][nl] + red[1][1][nl] + red[1][2][nl] + red[1][3][nl];
    float mean = st * (1.f / CDIM);
    float inv  = rsqrtf(sst * (1.f / CDIM) - mean * mean + EPS_LN);

    float* op = xn + (long)b * CDIM * NPOS + n0 + nl;
    #pragma unroll 8
    for (int c = cs * 128; c < cs * 128 + 128; c++) {
        float v = xp[(long)c * NPOS];
        op[(long)c * NPOS] = __uint_as_float(f2tf((v - mean) * inv * gs[c]));
    }
}

/* =====================================================================
 * Kernel 2/4: TF32 TC GEMM, cp.async double-buffered (round-4 structure)
 * ===================================================================== */
__global__ void __launch_bounds__(256, 2)
gemm_tc(const float* __restrict__ A, const float* __restrict__ Bm,
        float* __restrict__ C, const float* __restrict__ bias,
        int M, int K, int round_out) {
    __shared__ uint32_t As[2][128 * 36];
    __shared__ uint32_t Bs[2][32 * 136];
    int t = threadIdx.x, lane = t & 31, w = t >> 5;
    int m0 = blockIdx.x * 128, n0 = blockIdx.y * 128, b = blockIdx.z;
    const float* Ab = A  + (long)m0 * K;
    const float* Bb = Bm + (long)b * K * NPOS + n0;
    float*       Cb = C  + (long)b * M * NPOS;

    uint32_t sA = (uint32_t)__cvta_generic_to_shared(&As[0][0]);
    uint32_t sB = (uint32_t)__cvta_generic_to_shared(&Bs[0][0]);

    int wm = (w >> 2) * 64;
    int wn = (w & 3) * 32;
    int g  = lane >> 2, tg = lane & 3;

    float acc[4][4][4];
    #pragma unroll
    for (int i = 0; i < 4; i++)
        #pragma unroll
        for (int j = 0; j < 4; j++)
            #pragma unroll
            for (int r = 0; r < 4; r++) acc[i][j][r] = 0.f;

    const int NIT = K / 32;

    auto load_stage = [&](int buf, int k0) {
        #pragma unroll
        for (int ss = 0; ss < 4; ss++) {          /* A: 128x32 */
            int c = ss * 256 + t;
            int row = c >> 3, cq = (c & 7) << 2;
            cpasync16(sA + (buf * 128 * 36 + row * 36 + cq) * 4,
                      Ab + (long)row * K + k0 + cq);
        }
        #pragma unroll
        for (int ss = 0; ss < 4; ss++) {          /* B: 32x128 */
            int c = ss * 256 + t;
            int row = c >> 5, cq = (c & 31) << 2;
            cpasync16(sB + (buf * 32 * 136 + row * 136 + cq) * 4,
                      Bb + (long)(k0 + row) * NPOS + cq);
        }
        CP_COMMIT();
    };

    load_stage(0, 0);

    for (int it = 0; it < NIT; it++) {
        if (it + 1 < NIT) load_stage((it + 1) & 1, (it + 1) * 32);
        CP_WAIT(1);
        __syncthreads();
        const uint32_t* Ab_s = &As[it & 1][0];
        const uint32_t* Bb_s = &Bs[it & 1][0];

        #pragma unroll
        for (int kk = 0; kk < 32; kk += 8) {
            uint32_t af[4][4];
            #pragma unroll
            for (int mt = 0; mt < 4; mt++) {
                int r = wm + mt * 16 + g;
                af[mt][0] = Ab_s[r * 36 + kk + tg];
                af[mt][1] = Ab_s[(r + 8) * 36 + kk + tg];
                af[mt][2] = Ab_s[r * 36 + kk + tg + 4];
                af[mt][3] = Ab_s[(r + 8) * 36 + kk + tg + 4];
            }
            uint32_t bf[4][2];
            #pragma unroll
            for (int nt = 0; nt < 4; nt++) {
                int c = wn + nt * 8 + g;
                bf[nt][0] = Bb_s[(kk + tg) * 136 + c];
                bf[nt][1] = Bb_s[(kk + tg + 4) * 136 + c];
            }
            #pragma unroll
            for (int mt = 0; mt < 4; mt++)
                #pragma unroll
                for (int nt = 0; nt < 4; nt++)
                    mma_tf32(acc[mt][nt][0], acc[mt][nt][1], acc[mt][nt][2], acc[mt][nt][3],
                             af[mt][0], af[mt][1], af[mt][2], af[mt][3],
                             bf[nt][0], bf[nt][1]);
        }
        __syncthreads();
    }

    #pragma unroll
    for (int mt = 0; mt < 4; mt++) {
        int r0 = m0 + wm + mt * 16 + g;
        float b0 = bias ? bias[r0]     : 0.f;
        float b1 = bias ? bias[r0 + 8] : 0.f;
        #pragma unroll
        for (int nt = 0; nt < 4; nt++) {
            int c0 = n0 + wn + nt * 8 + 2 * tg;
            float v0 = acc[mt][nt][0] + b0, v1 = acc[mt][nt][1] + b0;
            float v2 = acc[mt][nt][2] + b1, v3 = acc[mt][nt][3] + b1;
            if (round_out) {
                v0 = __uint_as_float(f2tf(v0)); v1 = __uint_as_float(f2tf(v1));
                v2 = __uint_as_float(f2tf(v2)); v3 = __uint_as_float(f2tf(v3));
            }
            *(float2*)(Cb + (long)r0 * NPOS + c0)       = make_float2(v0, v1);
            *(float2*)(Cb + (long)(r0 + 8) * NPOS + c0) = make_float2(v2, v3);
        }
    }
}

/* =====================================================================
 * Kernel 3: fused TF32 flash attention (round-4 structure,
 *           round-3 softmax numerics restored EXACTLY).
 * Q scaled by 0.125 at staging (exact for tf32 values);
 * softmax in natural domain with __expf.
 * ===================================================================== */
#define QS_STRIDE 136
#define KS_STRIDE 72
#define VS_STRIDE 68
#define PS_STRIDE 68
#define QS_OFF 0
#define KS_OFF (64 * QS_STRIDE)
#define VS_OFF (KS_OFF + 64 * KS_STRIDE)
#define PS_OFF (VS_OFF + 64 * VS_STRIDE)
#define ATTN_SMEM_WORDS (PS_OFF + 128 * PS_STRIDE)   /* 26368 words */

__global__ void __launch_bounds__(128)
attn_tc(const float* __restrict__ qkv, float* __restrict__ ao) {
    extern __shared__ uint32_t sm4[];
    uint32_t* Qs = sm4 + QS_OFF;
    uint32_t* Ks = sm4 + KS_OFF;
    uint32_t* Vs = sm4 + VS_OFF;
    uint32_t* Ps = sm4 + PS_OFF;
    uint32_t sbase = (uint32_t)__cvta_generic_to_shared(sm4);

    int t = threadIdx.x, lane = t & 31, w = t >> 5;
    int g = lane >> 2, tg = lane & 3;
    int iw = w * 32;

    int qt = blockIdx.x;
    int bh = blockIdx.y;
    int b  = bh >> 3, h = bh & 7;
    int i0 = qt * 128;
    const float scale = 0.125f;          /* exact power of 2 */

    long base = (long)b * QKV_ROWS * NPOS + (long)h * DIM_HEAD * NPOS;
    const float* qp = qkv + base;
    const float* kp = qkv + base + (long)HIDDEN * NPOS;
    const float* vp = qkv + base + 2L * HIDDEN * NPOS;

    auto load_k = [&](int j0) {
        #pragma unroll
        for (int ss = 0; ss < 8; ss++) {
            int c = ss * 128 + t;
            int d = c >> 4, j = (c & 15) << 2;
            cpasync16(sbase + (KS_OFF + d * KS_STRIDE + j) * 4,
                      kp + (long)d * NPOS + j0 + j);
        }
        CP_COMMIT();
    };
    auto load_v = [&](int j0) {
        #pragma unroll
        for (int ss = 0; ss < 8; ss++) {
            int c = ss * 128 + t;
            int d = c >> 4, j = (c & 15) << 2;
            cpasync16(sbase + (VS_OFF + d * VS_STRIDE + j) * 4,
                      vp + (long)d * NPOS + j0 + j);
        }
        CP_COMMIT();
    };

    load_k(0);
    load_v(0);

    /* Q tile: pre-rounded tf32; scale by 0.125 (exact) at staging */
    #pragma unroll
    for (int ss = 0; ss < 16; ss++) {
        int lin = ss * 128 + t;
        int d = lin >> 5, i = (lin & 31) << 2;
        float4 v = *(const float4*)(qp + (long)d * NPOS + i0 + i);
        uint32_t* p = &Qs[d * QS_STRIDE + i];
        p[0] = __float_as_uint(v.x * scale); p[1] = __float_as_uint(v.y * scale);
        p[2] = __float_as_uint(v.z * scale); p[3] = __float_as_uint(v.w * scale);
    }

    float m_s[2][2], l_s[2][2];
    float o[2][8][4];
    #pragma unroll
    for (int mi = 0; mi < 2; mi++) {
        m_s[mi][0] = m_s[mi][1] = -1e30f;
        l_s[mi][0] = l_s[mi][1] = 0.f;
        #pragma unroll
        for (int nt = 0; nt < 8; nt++)
            #pragma unroll
            for (int r = 0; r < 4; r++) o[mi][nt][r] = 0.f;
    }

    const int T = NPOS / 64;
    for (int ti = 0; ti < T; ti++) {
        CP_WAIT(1);
        __syncthreads();

        /* ---- S = Q^T K : warp tile 32i x 64j (S already scaled) ---- */
        float sa[2][8][4];
        #pragma unroll
        for (int mi = 0; mi < 2; mi++)
            #pragma unroll
            for (int nt = 0; nt < 8; nt++)
                #pragma unroll
                for (int r = 0; r < 4; r++) sa[mi][nt][r] = 0.f;

        #pragma unroll
        for (int kk = 0; kk < 64; kk += 8) {
            uint32_t a[2][4];
            #pragma unroll
            for (int mi = 0; mi < 2; mi++) {
                int r0 = iw + mi * 16 + g;
                a[mi][0] = Qs[(kk + tg) * QS_STRIDE + r0];
                a[mi][1] = Qs[(kk + tg) * QS_STRIDE + r0 + 8];
                a[mi][2] = Qs[(kk + tg + 4) * QS_STRIDE + r0];
                a[mi][3] = Qs[(kk + tg + 4) * QS_STRIDE + r0 + 8];
            }
            #pragma unroll
            for (int nt = 0; nt < 8; nt++) {
                uint32_t b0 = Ks[(kk + tg) * KS_STRIDE + nt * 8 + g];
                uint32_t b1 = Ks[(kk + tg + 4) * KS_STRIDE + nt * 8 + g];
                mma_tf32(sa[0][nt][0], sa[0][nt][1], sa[0][nt][2], sa[0][nt][3],
                         a[0][0], a[0][1], a[0][2], a[0][3], b0, b1);
                mma_tf32(sa[1][nt][0], sa[1][nt][1], sa[1][nt][2], sa[1][nt][3],
                         a[1][0], a[1][1], a[1][2], a[1][3], b0, b1);
            }
        }
        __syncthreads();
        if (ti + 1 < T) load_k((ti + 1) * 64);

        /* ---- online softmax: EXACT round-3 numerics ---- */
        #pragma unroll
        for (int mi = 0; mi < 2; mi++) {
            float mx0 = -1e30f, mx1 = -1e30f;
            #pragma unroll
            for (int nt = 0; nt < 8; nt++) {
                mx0 = fmaxf(mx0, fmaxf(sa[mi][nt][0], sa[mi][nt][1]));
                mx1 = fmaxf(mx1, fmaxf(sa[mi][nt][2], sa[mi][nt][3]));
            }
            mx0 = fmaxf(mx0, __shfl_xor_sync(0xffffffffu, mx0, 1));
            mx0 = fmaxf(mx0, __shfl_xor_sync(0xffffffffu, mx0, 2));
            mx1 = fmaxf(mx1, __shfl_xor_sync(0xffffffffu, mx1, 1));
            mx1 = fmaxf(mx1, __shfl_xor_sync(0xffffffffu, mx1, 2));
            float mn0 = fmaxf(m_s[mi][0], mx0);
            float mn1 = fmaxf(m_s[mi][1], mx1);
            float s0 = 0.f, s1 = 0.f;
            int r0 = iw + mi * 16 + g;
            #pragma unroll
            for (int nt = 0; nt < 8; nt++) {
                float p0 = __expf(sa[mi][nt][0] - mn0);
                float p1 = __expf(sa[mi][nt][1] - mn0);
                float p2 = __expf(sa[mi][nt][2] - mn1);
                float p3 = __expf(sa[mi][nt][3] - mn1);
                s0 += p0 + p1;  s1 += p2 + p3;
                int jc = nt * 8 + 2 * tg;
                *(uint2*)&Ps[r0 * PS_STRIDE + jc]       = make_uint2(f2tf(p0), f2tf(p1));
                *(uint2*)&Ps[(r0 + 8) * PS_STRIDE + jc] = make_uint2(f2tf(p2), f2tf(p3));
            }
            s0 += __shfl_xor_sync(0xffffffffu, s0, 1);
            s0 += __shfl_xor_sync(0xffffffffu, s0, 2);
            s1 += __shfl_xor_sync(0xffffffffu, s1, 1);
            s1 += __shfl_xor_sync(0xffffffffu, s1, 2);
            float al0 = __expf(m_s[mi][0] - mn0);
            float al1 = __expf(m_s[mi][1] - mn1);
            l_s[mi][0] = l_s[mi][0] * al0 + s0;  m_s[mi][0] = mn0;
            l_s[mi][1] = l_s[mi][1] * al1 + s1;  m_s[mi][1] = mn1;
            #pragma unroll
            for (int nt = 0; nt < 8; nt++) {
                o[mi][nt][0] *= al0; o[mi][nt][1] *= al0;
                o[mi][nt][2] *= al1; o[mi][nt][3] *= al1;
            }
        }
        __syncwarp();

        if (ti + 1 < T) { CP_WAIT(1); } else { CP_WAIT(0); }
        __syncthreads();

        /* ---- O += P V^T : warp tile 32i x 64d ---- */
        #pragma unroll
        for (int kk = 0; kk < 64; kk += 8) {
            uint32_t a[2][4];
            #pragma unroll
            for (int mi = 0; mi < 2; mi++) {
                int r0 = iw + mi * 16 + g;
                a[mi][0] = Ps[r0 * PS_STRIDE + kk + tg];
                a[mi][1] = Ps[(r0 + 8) * PS_STRIDE + kk + tg];
                a[mi][2] = Ps[r0 * PS_STRIDE + kk + tg + 4];
                a[mi][3] = Ps[(r0 + 8) * PS_STRIDE + kk + tg + 4];
            }
            #pragma unroll
            for (int nt = 0; nt < 8; nt++) {
                uint32_t b0 = Vs[(nt * 8 + g) * VS_STRIDE + kk + tg];
                uint32_t b1 = Vs[(nt * 8 + g) * VS_STRIDE + kk + tg + 4];
                mma_tf32(o[0][nt][0], o[0][nt][1], o[0][nt][2], o[0][nt][3],
                         a[0][0], a[0][1], a[0][2], a[0][3], b0, b1);
                mma_tf32(o[1][nt][0], o[1][nt][1], o[1][nt][2], o[1][nt][3],
                         a[1][0], a[1][1], a[1][2], a[1][3], b0, b1);
            }
        }
        __syncthreads();
        if (ti + 1 < T) load_v((ti + 1) * 64);
    }

    /* ---- epilogue: normalize, round to tf32, transpose via Qs ---- */
    __syncthreads();
    #pragma unroll
    for (int mi = 0; mi < 2; mi++) {
        float inv0 = 1.f / l_s[mi][0], inv1 = 1.f / l_s[mi][1];
        int r0 = iw + mi * 16 + g;
        #pragma unroll
        for (int nt = 0; nt < 8; nt++) {
            int d0 = nt * 8 + 2 * tg;
            Qs[d0 * QS_STRIDE + r0]           = f2tf(o[mi][nt][0] * inv0);
            Qs[(d0 + 1) * QS_STRIDE + r0]     = f2tf(o[mi][nt][1] * inv0);
            Qs[d0 * QS_STRIDE + r0 + 8]       = f2tf(o[mi][nt][2] * inv1);
            Qs[(d0 + 1) * QS_STRIDE + r0 + 8] = f2tf(o[mi][nt][3] * inv1);
        }
    }
    __syncthreads();
    float* aop = ao + (long)b * HIDDEN * NPOS + (long)h * DIM_HEAD * NPOS + i0;
    #pragma unroll
    for (int ss = 0; ss < 16; ss++) {
        int lin = ss * 128 + t;
        int d = lin >> 5, i = (lin & 31) << 2;
        float4 v;
        v.x = __uint_as_float(Qs[d * QS_STRIDE + i]);
        v.y = __uint_as_float(Qs[d * QS_STRIDE + i + 1]);
        v.z = __uint_as_float(Qs[d * QS_STRIDE + i + 2]);
        v.w = __uint_as_float(Qs[d * QS_STRIDE + i + 3]);
        *(float4*)(aop + (long)d * NPOS + i) = v;
    }
}

/* ===================================================================== */
extern "C" void kernel_launch(void* const* d_in, const int* in_sizes, int n_in,
                              void* d_out, int out_size) {
    const float* x    = (const float*)d_in[0];
    const float* g    = (const float*)d_in[1];
    const float* Wqkv = (const float*)d_in[2];
    const float* Wout = (const float*)d_in[3];
    const float* bout = (const float*)d_in[4];
    float* out = (float*)d_out;

    float *xn, *qkv, *ao, *wq, *wo;
    cudaGetSymbolAddress((void**)&xn,  g_xn);
    cudaGetSymbolAddress((void**)&qkv, g_qkv);
    cudaGetSymbolAddress((void**)&ao,  g_ao);
    cudaGetSymbolAddress((void**)&wq,  g_wq);
    cudaGetSymbolAddress((void**)&wo,  g_wo);

    /* 0. one-time weight rounding */
    round_copy<<<(QKV_ROWS * CDIM) / 1024, 256>>>(Wqkv, wq);
    round_copy<<<(CDIM * HIDDEN) / 1024, 256>>>(Wout, wo);

    /* 1. LayerNorm (tf32-rounded out) */
    ln_kernel<<<(BATCH * NPOS) / 64, 256>>>(x, g, xn);

    /* 2. QKV projection (round output to tf32) */
    gemm_tc<<<dim3(QKV_ROWS / 128, NPOS / 128, BATCH), 256>>>(
        wq, xn, qkv, nullptr, QKV_ROWS, CDIM, 1);

    /* 3. fused attention */
    size_t smem = ATTN_SMEM_WORDS * sizeof(uint32_t);
    cudaFuncSetAttribute(attn_tc,
                         cudaFuncAttributeMaxDynamicSharedMemorySize, (int)smem);
    attn_tc<<<dim3(NPOS / 128, BATCH * HEADS), 128, smem>>>(qkv, ao);

    /* 4. output projection + bias (full fp32 out) */
    gemm_tc<<<dim3(HIDDEN / 128, NPOS / 128, BATCH), 256>>>(
        wo, ao, out, bout, HIDDEN, CDIM, 0);
}

// round 9
// speedup vs baseline: 3.9359x; 1.0205x over previous
#include <cuda_runtime.h>
#include <cstdint>

#define BATCH    8
#define CDIM     512
#define NPOS     2048
#define HEADS    8
#define DIM_HEAD 64
#define HIDDEN   512
#define QKV_ROWS 1536
#define EPS_LN   1e-5f

/* ---------------- scratch (static device globals) ---------------- */
__device__ float g_xn [BATCH * CDIM * NPOS];      /* tf32-rounded LN output   */
__device__ float g_qkv[BATCH * QKV_ROWS * NPOS];  /* tf32-rounded q,k,v       */
__device__ float g_ao [BATCH * HIDDEN * NPOS];    /* tf32-rounded attn output */
__device__ float g_wq [QKV_ROWS * CDIM];          /* tf32-rounded W_qkv       */
__device__ float g_wo [CDIM * HIDDEN];            /* tf32-rounded W_out       */

/* ---------------- helpers ---------------- */
__device__ __forceinline__ uint32_t f2tf(float f) {
    uint32_t u;
    asm("cvt.rna.tf32.f32 %0, %1;" : "=r"(u) : "f"(f));
    return u;
}
__device__ __forceinline__ void mma_tf32(float& c0, float& c1, float& c2, float& c3,
                                         uint32_t a0, uint32_t a1, uint32_t a2, uint32_t a3,
                                         uint32_t b0, uint32_t b1) {
    asm("mma.sync.aligned.m16n8k8.row.col.f32.tf32.tf32.f32 "
        "{%0,%1,%2,%3},{%4,%5,%6,%7},{%8,%9},{%0,%1,%2,%3};"
        : "+f"(c0), "+f"(c1), "+f"(c2), "+f"(c3)
        : "r"(a0), "r"(a1), "r"(a2), "r"(a3), "r"(b0), "r"(b1));
}
__device__ __forceinline__ void cpasync16(uint32_t dst, const void* src) {
    asm volatile("cp.async.cg.shared.global [%0], [%1], 16;" :: "r"(dst), "l"(src));
}
#define CP_COMMIT() asm volatile("cp.async.commit_group;")
#define CP_WAIT(n)  asm volatile("cp.async.wait_group %0;" :: "n"(n))

/* =====================================================================
 * Kernel 0: one-time tf32 rounding of weights
 * ===================================================================== */
__global__ void round_copy(const float* __restrict__ src, float* __restrict__ dst) {
    int i = (blockIdx.x * 256 + threadIdx.x) * 4;
    float4 v = *(const float4*)(src + i);
    v.x = __uint_as_float(f2tf(v.x));
    v.y = __uint_as_float(f2tf(v.y));
    v.z = __uint_as_float(f2tf(v.z));
    v.w = __uint_as_float(f2tf(v.w));
    *(float4*)(dst + i) = v;
}

/* =====================================================================
 * Kernel 1: channel LayerNorm, output tf32-rounded (round-5 verbatim)
 * ===================================================================== */
__global__ void ln_kernel(const float* __restrict__ x,
                          const float* __restrict__ g,
                          float* __restrict__ xn) {
    __shared__ float gs[CDIM];
    __shared__ float red[2][4][64];
    int t = threadIdx.x;
    for (int c = t; c < CDIM; c += 256) gs[c] = g[c];

    int nl = t & 63;
    int cs = t >> 6;
    int pos0 = blockIdx.x * 64;
    int b  = pos0 / NPOS;
    int n0 = pos0 % NPOS;

    const float* xp = x + (long)b * CDIM * NPOS + n0 + nl;
    float s = 0.f, ss = 0.f;
    #pragma unroll 8
    for (int c = cs * 128; c < cs * 128 + 128; c++) {
        float v = xp[(long)c * NPOS];
        s += v; ss += v * v;
    }
    red[0][cs][nl] = s;  red[1][cs][nl] = ss;
    __syncthreads();
    float st  = red[0][0][nl] + red[0][1][nl] + red[0][2][nl] + red[0][3][nl];
    float sst = red[1][0][nl] + red[1][1][nl] + red[1][2][nl] + red[1][3][nl];
    float mean = st * (1.f / CDIM);
    float inv  = rsqrtf(sst * (1.f / CDIM) - mean * mean + EPS_LN);

    float* op = xn + (long)b * CDIM * NPOS + n0 + nl;
    #pragma unroll 8
    for (int c = cs * 128; c < cs * 128 + 128; c++) {
        float v = xp[(long)c * NPOS];
        op[(long)c * NPOS] = __uint_as_float(f2tf((v - mean) * inv * gs[c]));
    }
}

/* =====================================================================
 * Kernel 2/4: TF32 TC GEMM, cp.async double-buffered.
 * RACE FIX: final iteration must CP_WAIT(0) — the newest group IS the
 * buffer being read.  (CP_WAIT(1) there let stage(NIT-1) stay in
 * flight: the per-run corruption behind rounds 4/6/7/8.)
 * ===================================================================== */
__global__ void __launch_bounds__(256, 2)
gemm_tc(const float* __restrict__ A, const float* __restrict__ Bm,
        float* __restrict__ C, const float* __restrict__ bias,
        int M, int K, int round_out) {
    __shared__ uint32_t As[2][128 * 36];
    __shared__ uint32_t Bs[2][32 * 136];
    int t = threadIdx.x, lane = t & 31, w = t >> 5;
    int m0 = blockIdx.x * 128, n0 = blockIdx.y * 128, b = blockIdx.z;
    const float* Ab = A  + (long)m0 * K;
    const float* Bb = Bm + (long)b * K * NPOS + n0;
    float*       Cb = C  + (long)b * M * NPOS;

    uint32_t sA = (uint32_t)__cvta_generic_to_shared(&As[0][0]);
    uint32_t sB = (uint32_t)__cvta_generic_to_shared(&Bs[0][0]);

    int wm = (w >> 2) * 64;
    int wn = (w & 3) * 32;
    int g  = lane >> 2, tg = lane & 3;

    float acc[4][4][4];
    #pragma unroll
    for (int i = 0; i < 4; i++)
        #pragma unroll
        for (int j = 0; j < 4; j++)
            #pragma unroll
            for (int r = 0; r < 4; r++) acc[i][j][r] = 0.f;

    const int NIT = K / 32;

    auto load_stage = [&](int buf, int k0) {
        #pragma unroll
        for (int ss = 0; ss < 4; ss++) {
            int c = ss * 256 + t;
            int row = c >> 3, cq = (c & 7) << 2;
            cpasync16(sA + (buf * 128 * 36 + row * 36 + cq) * 4,
                      Ab + (long)row * K + k0 + cq);
        }
        #pragma unroll
        for (int ss = 0; ss < 4; ss++) {
            int c = ss * 256 + t;
            int row = c >> 5, cq = (c & 31) << 2;
            cpasync16(sB + (buf * 32 * 136 + row * 136 + cq) * 4,
                      Bb + (long)(k0 + row) * NPOS + cq);
        }
        CP_COMMIT();
    };

    load_stage(0, 0);

    for (int it = 0; it < NIT; it++) {
        if (it + 1 < NIT) {
            load_stage((it + 1) & 1, (it + 1) * 32);
            CP_WAIT(1);               /* newest = stage(it+1); stage(it) landed */
        } else {
            CP_WAIT(0);               /* tail: stage(it) IS the newest — drain all */
        }
        __syncthreads();
        const uint32_t* Ab_s = &As[it & 1][0];
        const uint32_t* Bb_s = &Bs[it & 1][0];

        #pragma unroll
        for (int kk = 0; kk < 32; kk += 8) {
            uint32_t af[4][4];
            #pragma unroll
            for (int mt = 0; mt < 4; mt++) {
                int r = wm + mt * 16 + g;
                af[mt][0] = Ab_s[r * 36 + kk + tg];
                af[mt][1] = Ab_s[(r + 8) * 36 + kk + tg];
                af[mt][2] = Ab_s[r * 36 + kk + tg + 4];
                af[mt][3] = Ab_s[(r + 8) * 36 + kk + tg + 4];
            }
            uint32_t bf[4][2];
            #pragma unroll
            for (int nt = 0; nt < 4; nt++) {
                int c = wn + nt * 8 + g;
                bf[nt][0] = Bb_s[(kk + tg) * 136 + c];
                bf[nt][1] = Bb_s[(kk + tg + 4) * 136 + c];
            }
            #pragma unroll
            for (int mt = 0; mt < 4; mt++)
                #pragma unroll
                for (int nt = 0; nt < 4; nt++)
                    mma_tf32(acc[mt][nt][0], acc[mt][nt][1], acc[mt][nt][2], acc[mt][nt][3],
                             af[mt][0], af[mt][1], af[mt][2], af[mt][3],
                             bf[nt][0], bf[nt][1]);
        }
        __syncthreads();
    }

    #pragma unroll
    for (int mt = 0; mt < 4; mt++) {
        int r0 = m0 + wm + mt * 16 + g;
        float b0 = bias ? bias[r0]     : 0.f;
        float b1 = bias ? bias[r0 + 8] : 0.f;
        #pragma unroll
        for (int nt = 0; nt < 4; nt++) {
            int c0 = n0 + wn + nt * 8 + 2 * tg;
            float v0 = acc[mt][nt][0] + b0, v1 = acc[mt][nt][1] + b0;
            float v2 = acc[mt][nt][2] + b1, v3 = acc[mt][nt][3] + b1;
            if (round_out) {
                v0 = __uint_as_float(f2tf(v0)); v1 = __uint_as_float(f2tf(v1));
                v2 = __uint_as_float(f2tf(v2)); v3 = __uint_as_float(f2tf(v3));
            }
            *(float2*)(Cb + (long)r0 * NPOS + c0)       = make_float2(v0, v1);
            *(float2*)(Cb + (long)(r0 + 8) * NPOS + c0) = make_float2(v2, v3);
        }
    }
}

/* =====================================================================
 * Kernel 3: fused TF32 flash attention.
 * Round-5 inner loop and numerics verbatim; 64-query CTAs (4 warps x
 * 16 rows), smem 71680 B -> 3 CTAs/SM. Tail waits were always correct
 * here (CP_WAIT(0) on last iteration).
 * ===================================================================== */
#define QS_STRIDE 72
#define KS_STRIDE 72
#define VS_STRIDE 68
#define PS_STRIDE 68
#define QS_OFF 0
#define KS_OFF (64 * QS_STRIDE)                 /* 4608  */
#define VS_OFF (KS_OFF + 64 * KS_STRIDE)        /* 9216  */
#define PS_OFF (VS_OFF + 64 * VS_STRIDE)        /* 13568 */
#define ATTN_SMEM_WORDS (PS_OFF + 64 * PS_STRIDE)  /* 17920 words = 71680 B */

__global__ void __launch_bounds__(128, 3)
attn_tc(const float* __restrict__ qkv, float* __restrict__ ao) {
    extern __shared__ uint32_t sm4[];
    uint32_t* Qs = sm4 + QS_OFF;
    uint32_t* Ks = sm4 + KS_OFF;
    uint32_t* Vs = sm4 + VS_OFF;
    uint32_t* Ps = sm4 + PS_OFF;
    uint32_t sbase = (uint32_t)__cvta_generic_to_shared(sm4);

    int t = threadIdx.x, lane = t & 31, w = t >> 5;
    int g = lane >> 2, tg = lane & 3;
    int iw = w * 16;                      /* warp's 16 query rows */

    int qt = blockIdx.x;                  /* 0..31 */
    int bh = blockIdx.y;                  /* 0..63 */
    int b  = bh >> 3, h = bh & 7;
    int i0 = qt * 64;
    const float scale = 0.125f;           /* exact power of 2 */

    long base = (long)b * QKV_ROWS * NPOS + (long)h * DIM_HEAD * NPOS;
    const float* qp = qkv + base;
    const float* kp = qkv + base + (long)HIDDEN * NPOS;
    const float* vp = qkv + base + 2L * HIDDEN * NPOS;

    auto load_k = [&](int j0) {
        #pragma unroll
        for (int ss = 0; ss < 8; ss++) {
            int c = ss * 128 + t;
            int d = c >> 4, j = (c & 15) << 2;
            cpasync16(sbase + (KS_OFF + d * KS_STRIDE + j) * 4,
                      kp + (long)d * NPOS + j0 + j);
        }
        CP_COMMIT();
    };
    auto load_v = [&](int j0) {
        #pragma unroll
        for (int ss = 0; ss < 8; ss++) {
            int c = ss * 128 + t;
            int d = c >> 4, j = (c & 15) << 2;
            cpasync16(sbase + (VS_OFF + d * VS_STRIDE + j) * 4,
                      vp + (long)d * NPOS + j0 + j);
        }
        CP_COMMIT();
    };

    load_k(0);
    load_v(0);

    /* Q tile 64d x 64i: pre-rounded tf32; scale by 0.125 (exact) */
    #pragma unroll
    for (int ss = 0; ss < 8; ss++) {
        int lin = ss * 128 + t;
        int d = lin >> 4, i = (lin & 15) << 2;
        float4 v = *(const float4*)(qp + (long)d * NPOS + i0 + i);
        uint32_t* p = &Qs[d * QS_STRIDE + i];
        p[0] = __float_as_uint(v.x * scale); p[1] = __float_as_uint(v.y * scale);
        p[2] = __float_as_uint(v.z * scale); p[3] = __float_as_uint(v.w * scale);
    }

    float m_s[2], l_s[2];
    float o[8][4];
    m_s[0] = m_s[1] = -1e30f;
    l_s[0] = l_s[1] = 0.f;
    #pragma unroll
    for (int nt = 0; nt < 8; nt++)
        #pragma unroll
        for (int r = 0; r < 4; r++) o[nt][r] = 0.f;

    const int T = NPOS / 64;
    for (int ti = 0; ti < T; ti++) {
        CP_WAIT(1);                       /* newest = V(ti); K(ti) landed */
        __syncthreads();

        /* ---- S = Q^T K : warp tile 16i x 64j ---- */
        float sa[8][4];
        #pragma unroll
        for (int nt = 0; nt < 8; nt++)
            #pragma unroll
            for (int r = 0; r < 4; r++) sa[nt][r] = 0.f;

        #pragma unroll
        for (int kk = 0; kk < 64; kk += 8) {
            int r0 = iw + g;
            uint32_t a0 = Qs[(kk + tg) * QS_STRIDE + r0];
            uint32_t a1 = Qs[(kk + tg) * QS_STRIDE + r0 + 8];
            uint32_t a2 = Qs[(kk + tg + 4) * QS_STRIDE + r0];
            uint32_t a3 = Qs[(kk + tg + 4) * QS_STRIDE + r0 + 8];
            int kr0 = (kk + tg) * KS_STRIDE;
            int kr1 = (kk + tg + 4) * KS_STRIDE;
            #pragma unroll
            for (int nt = 0; nt < 8; nt++) {
                uint32_t b0 = Ks[kr0 + nt * 8 + g];
                uint32_t b1 = Ks[kr1 + nt * 8 + g];
                mma_tf32(sa[nt][0], sa[nt][1], sa[nt][2], sa[nt][3],
                         a0, a1, a2, a3, b0, b1);
            }
        }
        __syncthreads();
        if (ti + 1 < T) load_k((ti + 1) * 64);

        /* ---- online softmax: EXACT round-3/5 numerics ---- */
        {
            float mx0 = -1e30f, mx1 = -1e30f;
            #pragma unroll
            for (int nt = 0; nt < 8; nt++) {
                mx0 = fmaxf(mx0, fmaxf(sa[nt][0], sa[nt][1]));
                mx1 = fmaxf(mx1, fmaxf(sa[nt][2], sa[nt][3]));
            }
            mx0 = fmaxf(mx0, __shfl_xor_sync(0xffffffffu, mx0, 1));
            mx0 = fmaxf(mx0, __shfl_xor_sync(0xffffffffu, mx0, 2));
            mx1 = fmaxf(mx1, __shfl_xor_sync(0xffffffffu, mx1, 1));
            mx1 = fmaxf(mx1, __shfl_xor_sync(0xffffffffu, mx1, 2));
            float mn0 = fmaxf(m_s[0], mx0);
            float mn1 = fmaxf(m_s[1], mx1);
            float s0 = 0.f, s1 = 0.f;
            int r0 = iw + g;
            #pragma unroll
            for (int nt = 0; nt < 8; nt++) {
                float p0 = __expf(sa[nt][0] - mn0);
                float p1 = __expf(sa[nt][1] - mn0);
                float p2 = __expf(sa[nt][2] - mn1);
                float p3 = __expf(sa[nt][3] - mn1);
                s0 += p0 + p1;  s1 += p2 + p3;
                int jc = nt * 8 + 2 * tg;
                *(uint2*)&Ps[r0 * PS_STRIDE + jc]       = make_uint2(f2tf(p0), f2tf(p1));
                *(uint2*)&Ps[(r0 + 8) * PS_STRIDE + jc] = make_uint2(f2tf(p2), f2tf(p3));
            }
            s0 += __shfl_xor_sync(0xffffffffu, s0, 1);
            s0 += __shfl_xor_sync(0xffffffffu, s0, 2);
            s1 += __shfl_xor_sync(0xffffffffu, s1, 1);
            s1 += __shfl_xor_sync(0xffffffffu, s1, 2);
            float al0 = __expf(m_s[0] - mn0);
            float al1 = __expf(m_s[1] - mn1);
            l_s[0] = l_s[0] * al0 + s0;  m_s[0] = mn0;
            l_s[1] = l_s[1] * al1 + s1;  m_s[1] = mn1;
            #pragma unroll
            for (int nt = 0; nt < 8; nt++) {
                o[nt][0] *= al0; o[nt][1] *= al0;
                o[nt][2] *= al1; o[nt][3] *= al1;
            }
        }
        __syncwarp();                     /* P rows are warp-local */

        if (ti + 1 < T) { CP_WAIT(1); } else { CP_WAIT(0); }
        __syncthreads();

        /* ---- O += P V^T : warp tile 16i x 64d ---- */
        #pragma unroll
        for (int kk = 0; kk < 64; kk += 8) {
            int r0 = iw + g;
            uint32_t a0 = Ps[r0 * PS_STRIDE + kk + tg];
            uint32_t a1 = Ps[(r0 + 8) * PS_STRIDE + kk + tg];
            uint32_t a2 = Ps[r0 * PS_STRIDE + kk + tg + 4];
            uint32_t a3 = Ps[(r0 + 8) * PS_STRIDE + kk + tg + 4];
            #pragma unroll
            for (int nt = 0; nt < 8; nt++) {
                uint32_t b0 = Vs[(nt * 8 + g) * VS_STRIDE + kk + tg];
                uint32_t b1 = Vs[(nt * 8 + g) * VS_STRIDE + kk + tg + 4];
                mma_tf32(o[nt][0], o[nt][1], o[nt][2], o[nt][3],
                         a0, a1, a2, a3, b0, b1);
            }
        }
        __syncthreads();
        if (ti + 1 < T) load_v((ti + 1) * 64);
    }

    /* ---- epilogue: normalize, round to tf32, transpose via Qs ---- */
    __syncthreads();
    {
        float inv0 = 1.f / l_s[0], inv1 = 1.f / l_s[1];
        int r0 = iw + g;
        #pragma unroll
        for (int nt = 0; nt < 8; nt++) {
            int d0 = nt * 8 + 2 * tg;
            Qs[d0 * QS_STRIDE + r0]           = f2tf(o[nt][0] * inv0);
            Qs[(d0 + 1) * QS_STRIDE + r0]     = f2tf(o[nt][1] * inv0);
            Qs[d0 * QS_STRIDE + r0 + 8]       = f2tf(o[nt][2] * inv1);
            Qs[(d0 + 1) * QS_STRIDE + r0 + 8] = f2tf(o[nt][3] * inv1);
        }
    }
    __syncthreads();
    float* aop = ao + (long)b * HIDDEN * NPOS + (long)h * DIM_HEAD * NPOS + i0;
    #pragma unroll
    for (int ss = 0; ss < 8; ss++) {
        int lin = ss * 128 + t;
        int d = lin >> 4, i = (lin & 15) << 2;
        float4 v;
        v.x = __uint_as_float(Qs[d * QS_STRIDE + i]);
        v.y = __uint_as_float(Qs[d * QS_STRIDE + i + 1]);
        v.z = __uint_as_float(Qs[d * QS_STRIDE + i + 2]);
        v.w = __uint_as_float(Qs[d * QS_STRIDE + i + 3]);
        *(float4*)(aop + (long)d * NPOS + i) = v;
    }
}

/* ===================================================================== */
extern "C" void kernel_launch(void* const* d_in, const int* in_sizes, int n_in,
                              void* d_out, int out_size) {
    const float* x    = (const float*)d_in[0];
    const float* g    = (const float*)d_in[1];
    const float* Wqkv = (const float*)d_in[2];
    const float* Wout = (const float*)d_in[3];
    const float* bout = (const float*)d_in[4];
    float* out = (float*)d_out;

    float *xn, *qkv, *ao, *wq, *wo;
    cudaGetSymbolAddress((void**)&xn,  g_xn);
    cudaGetSymbolAddress((void**)&qkv, g_qkv);
    cudaGetSymbolAddress((void**)&ao,  g_ao);
    cudaGetSymbolAddress((void**)&wq,  g_wq);
    cudaGetSymbolAddress((void**)&wo,  g_wo);

    /* 0. one-time weight rounding */
    round_copy<<<(QKV_ROWS * CDIM) / 1024, 256>>>(Wqkv, wq);
    round_copy<<<(CDIM * HIDDEN) / 1024, 256>>>(Wout, wo);

    /* 1. LayerNorm (tf32-rounded out) */
    ln_kernel<<<(BATCH * NPOS) / 64, 256>>>(x, g, xn);

    /* 2. QKV projection (round output to tf32) */
    gemm_tc<<<dim3(QKV_ROWS / 128, NPOS / 128, BATCH), 256>>>(
        wq, xn, qkv, nullptr, QKV_ROWS, CDIM, 1);

    /* 3. fused attention (64-query CTAs, 3/SM) */
    size_t smem = ATTN_SMEM_WORDS * sizeof(uint32_t);   /* 71680 B */
    cudaFuncSetAttribute(attn_tc,
                         cudaFuncAttributeMaxDynamicSharedMemorySize, (int)smem);
    attn_tc<<<dim3(NPOS / 64, BATCH * HEADS), 128, smem>>>(qkv, ao);

    /* 4. output projection + bias (full fp32 out) */
    gemm_tc<<<dim3(HIDDEN / 128, NPOS / 128, BATCH), 256>>>(
        wo, ao, out, bout, HIDDEN, CDIM, 0);
}

// round 10
// speedup vs baseline: 4.0046x; 1.0175x over previous
#include <cuda_runtime.h>
#include <cstdint>

#define BATCH    8
#define CDIM     512
#define NPOS     2048
#define HEADS    8
#define DIM_HEAD 64
#define HIDDEN   512
#define QKV_ROWS 1536
#define EPS_LN   1e-5f

/* ---------------- scratch (static device globals) ---------------- */
__device__ float g_xn [BATCH * CDIM * NPOS];      /* tf32-rounded LN output   */
__device__ float g_qkv[BATCH * QKV_ROWS * NPOS];  /* tf32-rounded q,k,v       */
__device__ float g_ao [BATCH * HIDDEN * NPOS];    /* tf32-rounded attn output */
__device__ float g_wq [QKV_ROWS * CDIM];          /* tf32-rounded W_qkv       */
__device__ float g_wo [CDIM * HIDDEN];            /* tf32-rounded W_out       */

/* ---------------- helpers ---------------- */
__device__ __forceinline__ uint32_t f2tf(float f) {
    uint32_t u;
    asm("cvt.rna.tf32.f32 %0, %1;" : "=r"(u) : "f"(f));
    return u;
}
__device__ __forceinline__ void mma_tf32(float& c0, float& c1, float& c2, float& c3,
                                         uint32_t a0, uint32_t a1, uint32_t a2, uint32_t a3,
                                         uint32_t b0, uint32_t b1) {
    asm("mma.sync.aligned.m16n8k8.row.col.f32.tf32.tf32.f32 "
        "{%0,%1,%2,%3},{%4,%5,%6,%7},{%8,%9},{%0,%1,%2,%3};"
        : "+f"(c0), "+f"(c1), "+f"(c2), "+f"(c3)
        : "r"(a0), "r"(a1), "r"(a2), "r"(a3), "r"(b0), "r"(b1));
}
__device__ __forceinline__ void cpasync16(uint32_t dst, const void* src) {
    asm volatile("cp.async.cg.shared.global [%0], [%1], 16;" :: "r"(dst), "l"(src));
}
#define CP_COMMIT() asm volatile("cp.async.commit_group;")
#define CP_WAIT(n)  asm volatile("cp.async.wait_group %0;" :: "n"(n))

/* =====================================================================
 * Kernel 0: one-time tf32 rounding of weights
 * ===================================================================== */
__global__ void round_copy(const float* __restrict__ src, float* __restrict__ dst) {
    int i = (blockIdx.x * 256 + threadIdx.x) * 4;
    float4 v = *(const float4*)(src + i);
    v.x = __uint_as_float(f2tf(v.x));
    v.y = __uint_as_float(f2tf(v.y));
    v.z = __uint_as_float(f2tf(v.z));
    v.w = __uint_as_float(f2tf(v.w));
    *(float4*)(dst + i) = v;
}

/* =====================================================================
 * Kernel 1: channel LayerNorm, tf32-rounded out.
 * 512 threads = 64 n-positions x 8 c-slices (64 c each) for 2x resident
 * parallelism vs the 256-thread version (latency-bound strided reads).
 * ===================================================================== */
__global__ void __launch_bounds__(512)
ln_kernel(const float* __restrict__ x,
          const float* __restrict__ g,
          float* __restrict__ xn) {
    __shared__ float gs[CDIM];
    __shared__ float red[2][8][64];
    int t = threadIdx.x;
    if (t < CDIM) gs[t] = g[t];

    int nl = t & 63;          /* local n      */
    int cs = t >> 6;          /* c slice 0..7 */
    int pos0 = blockIdx.x * 64;
    int b  = pos0 / NPOS;
    int n0 = pos0 % NPOS;

    const float* xp = x + (long)b * CDIM * NPOS + n0 + nl;
    float s = 0.f, ss = 0.f;
    #pragma unroll 8
    for (int c = cs * 64; c < cs * 64 + 64; c++) {
        float v = xp[(long)c * NPOS];
        s += v; ss += v * v;
    }
    red[0][cs][nl] = s;  red[1][cs][nl] = ss;
    __syncthreads();
    float st = 0.f, sst = 0.f;
    #pragma unroll
    for (int k = 0; k < 8; k++) { st += red[0][k][nl]; sst += red[1][k][nl]; }
    float mean = st * (1.f / CDIM);
    float inv  = rsqrtf(sst * (1.f / CDIM) - mean * mean + EPS_LN);

    float* op = xn + (long)b * CDIM * NPOS + n0 + nl;
    #pragma unroll 8
    for (int c = cs * 64; c < cs * 64 + 64; c++) {
        float v = xp[(long)c * NPOS];
        op[(long)c * NPOS] = __uint_as_float(f2tf((v - mean) * inv * gs[c]));
    }
}

/* =====================================================================
 * Kernel 2/4: TF32 TC GEMM — 3-stage cp.async pipeline, ONE sync/iter.
 * Safety argument:
 *  - load(it+2) is issued AFTER the top-of-iter barrier, so every warp
 *    has finished compute(it-1), whose buffer ((it+2)%3 == (it-1)%3)
 *    is being overwritten.
 *  - CP_WAIT(1) before the barrier: newest outstanding group is
 *    stage(it+1) (issued last iter), so stage(it) has landed.
 *  - Tail iterations CP_WAIT(0)  (the round-9 race-fix rule).
 * Dynamic smem: 3*(128*36 + 32*136)*4 = 107520 B -> 2 CTAs/SM.
 * ===================================================================== */
#define ASTG (128 * 36)
#define BSTG (32 * 136)
#define GEMM_SMEM_BYTES (3 * (ASTG + BSTG) * 4)

__global__ void __launch_bounds__(256, 2)
gemm_tc(const float* __restrict__ A, const float* __restrict__ Bm,
        float* __restrict__ C, const float* __restrict__ bias,
        int M, int K, int round_out) {
    extern __shared__ uint32_t gsm[];
    uint32_t* Asb = gsm;                 /* 3 x ASTG */
    uint32_t* Bsb = gsm + 3 * ASTG;      /* 3 x BSTG */

    int t = threadIdx.x, lane = t & 31, w = t >> 5;
    int m0 = blockIdx.x * 128, n0 = blockIdx.y * 128, b = blockIdx.z;
    const float* Ab = A  + (long)m0 * K;
    const float* Bb = Bm + (long)b * K * NPOS + n0;
    float*       Cb = C  + (long)b * M * NPOS;

    uint32_t sbase = (uint32_t)__cvta_generic_to_shared(gsm);

    int wm = (w >> 2) * 64;
    int wn = (w & 3) * 32;
    int g  = lane >> 2, tg = lane & 3;

    float acc[4][4][4];
    #pragma unroll
    for (int i = 0; i < 4; i++)
        #pragma unroll
        for (int j = 0; j < 4; j++)
            #pragma unroll
            for (int r = 0; r < 4; r++) acc[i][j][r] = 0.f;

    const int NIT = K / 32;

    auto load_stage = [&](int buf, int k0) {
        #pragma unroll
        for (int ss = 0; ss < 4; ss++) {          /* A: 128x32 */
            int c = ss * 256 + t;
            int row = c >> 3, cq = (c & 7) << 2;
            cpasync16(sbase + (buf * ASTG + row * 36 + cq) * 4,
                      Ab + (long)row * K + k0 + cq);
        }
        #pragma unroll
        for (int ss = 0; ss < 4; ss++) {          /* B: 32x128 */
            int c = ss * 256 + t;
            int row = c >> 5, cq = (c & 31) << 2;
            cpasync16(sbase + (3 * ASTG + buf * BSTG + row * 136 + cq) * 4,
                      Bb + (long)(k0 + row) * NPOS + cq);
        }
        CP_COMMIT();
    };

    load_stage(0, 0);
    if (NIT > 1) load_stage(1, 32);

    for (int it = 0; it < NIT; it++) {
        if (it + 1 < NIT) { CP_WAIT(1); } else { CP_WAIT(0); }
        __syncthreads();
        if (it + 2 < NIT) load_stage((it + 2) % 3, (it + 2) * 32);

        const uint32_t* Ab_s = Asb + (it % 3) * ASTG;
        const uint32_t* Bb_s = Bsb + (it % 3) * BSTG;

        #pragma unroll
        for (int kk = 0; kk < 32; kk += 8) {
            uint32_t af[4][4];
            #pragma unroll
            for (int mt = 0; mt < 4; mt++) {
                int r = wm + mt * 16 + g;
                af[mt][0] = Ab_s[r * 36 + kk + tg];
                af[mt][1] = Ab_s[(r + 8) * 36 + kk + tg];
                af[mt][2] = Ab_s[r * 36 + kk + tg + 4];
                af[mt][3] = Ab_s[(r + 8) * 36 + kk + tg + 4];
            }
            uint32_t bf[4][2];
            #pragma unroll
            for (int nt = 0; nt < 4; nt++) {
                int c = wn + nt * 8 + g;
                bf[nt][0] = Bb_s[(kk + tg) * 136 + c];
                bf[nt][1] = Bb_s[(kk + tg + 4) * 136 + c];
            }
            #pragma unroll
            for (int mt = 0; mt < 4; mt++)
                #pragma unroll
                for (int nt = 0; nt < 4; nt++)
                    mma_tf32(acc[mt][nt][0], acc[mt][nt][1], acc[mt][nt][2], acc[mt][nt][3],
                             af[mt][0], af[mt][1], af[mt][2], af[mt][3],
                             bf[nt][0], bf[nt][1]);
        }
    }

    #pragma unroll
    for (int mt = 0; mt < 4; mt++) {
        int r0 = m0 + wm + mt * 16 + g;
        float b0 = bias ? bias[r0]     : 0.f;
        float b1 = bias ? bias[r0 + 8] : 0.f;
        #pragma unroll
        for (int nt = 0; nt < 4; nt++) {
            int c0 = n0 + wn + nt * 8 + 2 * tg;
            float v0 = acc[mt][nt][0] + b0, v1 = acc[mt][nt][1] + b0;
            float v2 = acc[mt][nt][2] + b1, v3 = acc[mt][nt][3] + b1;
            if (round_out) {
                v0 = __uint_as_float(f2tf(v0)); v1 = __uint_as_float(f2tf(v1));
                v2 = __uint_as_float(f2tf(v2)); v3 = __uint_as_float(f2tf(v3));
            }
            *(float2*)(Cb + (long)r0 * NPOS + c0)       = make_float2(v0, v1);
            *(float2*)(Cb + (long)(r0 + 8) * NPOS + c0) = make_float2(v2, v3);
        }
    }
}

/* =====================================================================
 * Kernel 3: fused TF32 flash attention — round-9 VERBATIM (passing).
 * ===================================================================== */
#define QS_STRIDE 72
#define KS_STRIDE 72
#define VS_STRIDE 68
#define PS_STRIDE 68
#define QS_OFF 0
#define KS_OFF (64 * QS_STRIDE)                 /* 4608  */
#define VS_OFF (KS_OFF + 64 * KS_STRIDE)        /* 9216  */
#define PS_OFF (VS_OFF + 64 * VS_STRIDE)        /* 13568 */
#define ATTN_SMEM_WORDS (PS_OFF + 64 * PS_STRIDE)  /* 17920 words = 71680 B */

__global__ void __launch_bounds__(128, 3)
attn_tc(const float* __restrict__ qkv, float* __restrict__ ao) {
    extern __shared__ uint32_t sm4[];
    uint32_t* Qs = sm4 + QS_OFF;
    uint32_t* Ks = sm4 + KS_OFF;
    uint32_t* Vs = sm4 + VS_OFF;
    uint32_t* Ps = sm4 + PS_OFF;
    uint32_t sbase = (uint32_t)__cvta_generic_to_shared(sm4);

    int t = threadIdx.x, lane = t & 31, w = t >> 5;
    int g = lane >> 2, tg = lane & 3;
    int iw = w * 16;

    int qt = blockIdx.x;
    int bh = blockIdx.y;
    int b  = bh >> 3, h = bh & 7;
    int i0 = qt * 64;
    const float scale = 0.125f;

    long base = (long)b * QKV_ROWS * NPOS + (long)h * DIM_HEAD * NPOS;
    const float* qp = qkv + base;
    const float* kp = qkv + base + (long)HIDDEN * NPOS;
    const float* vp = qkv + base + 2L * HIDDEN * NPOS;

    auto load_k = [&](int j0) {
        #pragma unroll
        for (int ss = 0; ss < 8; ss++) {
            int c = ss * 128 + t;
            int d = c >> 4, j = (c & 15) << 2;
            cpasync16(sbase + (KS_OFF + d * KS_STRIDE + j) * 4,
                      kp + (long)d * NPOS + j0 + j);
        }
        CP_COMMIT();
    };
    auto load_v = [&](int j0) {
        #pragma unroll
        for (int ss = 0; ss < 8; ss++) {
            int c = ss * 128 + t;
            int d = c >> 4, j = (c & 15) << 2;
            cpasync16(sbase + (VS_OFF + d * VS_STRIDE + j) * 4,
                      vp + (long)d * NPOS + j0 + j);
        }
        CP_COMMIT();
    };

    load_k(0);
    load_v(0);

    #pragma unroll
    for (int ss = 0; ss < 8; ss++) {
        int lin = ss * 128 + t;
        int d = lin >> 4, i = (lin & 15) << 2;
        float4 v = *(const float4*)(qp + (long)d * NPOS + i0 + i);
        uint32_t* p = &Qs[d * QS_STRIDE + i];
        p[0] = __float_as_uint(v.x * scale); p[1] = __float_as_uint(v.y * scale);
        p[2] = __float_as_uint(v.z * scale); p[3] = __float_as_uint(v.w * scale);
    }

    float m_s[2], l_s[2];
    float o[8][4];
    m_s[0] = m_s[1] = -1e30f;
    l_s[0] = l_s[1] = 0.f;
    #pragma unroll
    for (int nt = 0; nt < 8; nt++)
        #pragma unroll
        for (int r = 0; r < 4; r++) o[nt][r] = 0.f;

    const int T = NPOS / 64;
    for (int ti = 0; ti < T; ti++) {
        CP_WAIT(1);
        __syncthreads();

        float sa[8][4];
        #pragma unroll
        for (int nt = 0; nt < 8; nt++)
            #pragma unroll
            for (int r = 0; r < 4; r++) sa[nt][r] = 0.f;

        #pragma unroll
        for (int kk = 0; kk < 64; kk += 8) {
            int r0 = iw + g;
            uint32_t a0 = Qs[(kk + tg) * QS_STRIDE + r0];
            uint32_t a1 = Qs[(kk + tg) * QS_STRIDE + r0 + 8];
            uint32_t a2 = Qs[(kk + tg + 4) * QS_STRIDE + r0];
            uint32_t a3 = Qs[(kk + tg + 4) * QS_STRIDE + r0 + 8];
            int kr0 = (kk + tg) * KS_STRIDE;
            int kr1 = (kk + tg + 4) * KS_STRIDE;
            #pragma unroll
            for (int nt = 0; nt < 8; nt++) {
                uint32_t b0 = Ks[kr0 + nt * 8 + g];
                uint32_t b1 = Ks[kr1 + nt * 8 + g];
                mma_tf32(sa[nt][0], sa[nt][1], sa[nt][2], sa[nt][3],
                         a0, a1, a2, a3, b0, b1);
            }
        }
        __syncthreads();
        if (ti + 1 < T) load_k((ti + 1) * 64);

        {
            float mx0 = -1e30f, mx1 = -1e30f;
            #pragma unroll
            for (int nt = 0; nt < 8; nt++) {
                mx0 = fmaxf(mx0, fmaxf(sa[nt][0], sa[nt][1]));
                mx1 = fmaxf(mx1, fmaxf(sa[nt][2], sa[nt][3]));
            }
            mx0 = fmaxf(mx0, __shfl_xor_sync(0xffffffffu, mx0, 1));
            mx0 = fmaxf(mx0, __shfl_xor_sync(0xffffffffu, mx0, 2));
            mx1 = fmaxf(mx1, __shfl_xor_sync(0xffffffffu, mx1, 1));
            mx1 = fmaxf(mx1, __shfl_xor_sync(0xffffffffu, mx1, 2));
            float mn0 = fmaxf(m_s[0], mx0);
            float mn1 = fmaxf(m_s[1], mx1);
            float s0 = 0.f, s1 = 0.f;
            int r0 = iw + g;
            #pragma unroll
            for (int nt = 0; nt < 8; nt++) {
                float p0 = __expf(sa[nt][0] - mn0);
                float p1 = __expf(sa[nt][1] - mn0);
                float p2 = __expf(sa[nt][2] - mn1);
                float p3 = __expf(sa[nt][3] - mn1);
                s0 += p0 + p1;  s1 += p2 + p3;
                int jc = nt * 8 + 2 * tg;
                *(uint2*)&Ps[r0 * PS_STRIDE + jc]       = make_uint2(f2tf(p0), f2tf(p1));
                *(uint2*)&Ps[(r0 + 8) * PS_STRIDE + jc] = make_uint2(f2tf(p2), f2tf(p3));
            }
            s0 += __shfl_xor_sync(0xffffffffu, s0, 1);
            s0 += __shfl_xor_sync(0xffffffffu, s0, 2);
            s1 += __shfl_xor_sync(0xffffffffu, s1, 1);
            s1 += __shfl_xor_sync(0xffffffffu, s1, 2);
            float al0 = __expf(m_s[0] - mn0);
            float al1 = __expf(m_s[1] - mn1);
            l_s[0] = l_s[0] * al0 + s0;  m_s[0] = mn0;
            l_s[1] = l_s[1] * al1 + s1;  m_s[1] = mn1;
            #pragma unroll
            for (int nt = 0; nt < 8; nt++) {
                o[nt][0] *= al0; o[nt][1] *= al0;
                o[nt][2] *= al1; o[nt][3] *= al1;
            }
        }
        __syncwarp();

        if (ti + 1 < T) { CP_WAIT(1); } else { CP_WAIT(0); }
        __syncthreads();

        #pragma unroll
        for (int kk = 0; kk < 64; kk += 8) {
            int r0 = iw + g;
            uint32_t a0 = Ps[r0 * PS_STRIDE + kk + tg];
            uint32_t a1 = Ps[(r0 + 8) * PS_STRIDE + kk + tg];
            uint32_t a2 = Ps[r0 * PS_STRIDE + kk + tg + 4];
            uint32_t a3 = Ps[(r0 + 8) * PS_STRIDE + kk + tg + 4];
            #pragma unroll
            for (int nt = 0; nt < 8; nt++) {
                uint32_t b0 = Vs[(nt * 8 + g) * VS_STRIDE + kk + tg];
                uint32_t b1 = Vs[(nt * 8 + g) * VS_STRIDE + kk + tg + 4];
                mma_tf32(o[nt][0], o[nt][1], o[nt][2], o[nt][3],
                         a0, a1, a2, a3, b0, b1);
            }
        }
        __syncthreads();
        if (ti + 1 < T) load_v((ti + 1) * 64);
    }

    __syncthreads();
    {
        float inv0 = 1.f / l_s[0], inv1 = 1.f / l_s[1];
        int r0 = iw + g;
        #pragma unroll
        for (int nt = 0; nt < 8; nt++) {
            int d0 = nt * 8 + 2 * tg;
            Qs[d0 * QS_STRIDE + r0]           = f2tf(o[nt][0] * inv0);
            Qs[(d0 + 1) * QS_STRIDE + r0]     = f2tf(o[nt][1] * inv0);
            Qs[d0 * QS_STRIDE + r0 + 8]       = f2tf(o[nt][2] * inv1);
            Qs[(d0 + 1) * QS_STRIDE + r0 + 8] = f2tf(o[nt][3] * inv1);
        }
    }
    __syncthreads();
    float* aop = ao + (long)b * HIDDEN * NPOS + (long)h * DIM_HEAD * NPOS + i0;
    #pragma unroll
    for (int ss = 0; ss < 8; ss++) {
        int lin = ss * 128 + t;
        int d = lin >> 4, i = (lin & 15) << 2;
        float4 v;
        v.x = __uint_as_float(Qs[d * QS_STRIDE + i]);
        v.y = __uint_as_float(Qs[d * QS_STRIDE + i + 1]);
        v.z = __uint_as_float(Qs[d * QS_STRIDE + i + 2]);
        v.w = __uint_as_float(Qs[d * QS_STRIDE + i + 3]);
        *(float4*)(aop + (long)d * NPOS + i) = v;
    }
}

/* ===================================================================== */
extern "C" void kernel_launch(void* const* d_in, const int* in_sizes, int n_in,
                              void* d_out, int out_size) {
    const float* x    = (const float*)d_in[0];
    const float* g    = (const float*)d_in[1];
    const float* Wqkv = (const float*)d_in[2];
    const float* Wout = (const float*)d_in[3];
    const float* bout = (const float*)d_in[4];
    float* out = (float*)d_out;

    float *xn, *qkv, *ao, *wq, *wo;
    cudaGetSymbolAddress((void**)&xn,  g_xn);
    cudaGetSymbolAddress((void**)&qkv, g_qkv);
    cudaGetSymbolAddress((void**)&ao,  g_ao);
    cudaGetSymbolAddress((void**)&wq,  g_wq);
    cudaGetSymbolAddress((void**)&wo,  g_wo);

    /* 0. one-time weight rounding */
    round_copy<<<(QKV_ROWS * CDIM) / 1024, 256>>>(Wqkv, wq);
    round_copy<<<(CDIM * HIDDEN) / 1024, 256>>>(Wout, wo);

    /* 1. LayerNorm (512-thread blocks) */
    ln_kernel<<<(BATCH * NPOS) / 64, 512>>>(x, g, xn);

    /* 2. QKV projection (3-stage pipeline, round output to tf32) */
    cudaFuncSetAttribute(gemm_tc,
                         cudaFuncAttributeMaxDynamicSharedMemorySize,
                         GEMM_SMEM_BYTES);
    gemm_tc<<<dim3(QKV_ROWS / 128, NPOS / 128, BATCH), 256, GEMM_SMEM_BYTES>>>(
        wq, xn, qkv, nullptr, QKV_ROWS, CDIM, 1);

    /* 3. fused attention (round-9 verbatim) */
    size_t smem = ATTN_SMEM_WORDS * sizeof(uint32_t);   /* 71680 B */
    cudaFuncSetAttribute(attn_tc,
                         cudaFuncAttributeMaxDynamicSharedMemorySize, (int)smem);
    attn_tc<<<dim3(NPOS / 64, BATCH * HEADS), 128, smem>>>(qkv, ao);

    /* 4. output projection + bias (full fp32 out) */
    gemm_tc<<<dim3(HIDDEN / 128, NPOS / 128, BATCH), 256, GEMM_SMEM_BYTES>>>(
        wo, ao, out, bout, HIDDEN, CDIM, 0);
}

// round 12
// speedup vs baseline: 5.6842x; 1.4194x over previous
#include <cuda_runtime.h>
#include <cuda_fp16.h>
#include <cstdint>

#define BATCH    8
#define CDIM     512
#define NPOS     2048
#define HEADS    8
#define DIM_HEAD 64
#define HIDDEN   512
#define QKV_ROWS 1536
#define EPS_LN   1e-5f

/* ---------------- scratch (static device globals) ---------------- */
__device__ float    g_xn [BATCH * CDIM * NPOS];      /* tf32 LN output [b][c][n] */
__device__ float    g_qkv[BATCH * QKV_ROWS * NPOS];  /* tf32 q,k,v [b][row][n]   */
__device__ float    g_ao [BATCH * HIDDEN * NPOS];    /* tf32 attn out [b][hd][n] */
__device__ float    g_wq [QKV_ROWS * CDIM];
__device__ float    g_wo [CDIM * HIDDEN];
__device__ uint32_t g_qpk[64 * 32 * 2048];           /* Q half2 d-pairs [bh][dp][n] */
__device__ uint32_t g_kpk[64 * 32 * 2048];           /* K half2 d-pairs [bh][dp][n] */
__device__ uint32_t g_vpk[64 * 1024 * 64];           /* V half2 j-pairs [bh][jp][d] */

/* ---------------- helpers ---------------- */
__device__ __forceinline__ uint32_t f2tf(float f) {
    uint32_t u;
    asm("cvt.rna.tf32.f32 %0, %1;" : "=r"(u) : "f"(f));
    return u;
}
__device__ __forceinline__ uint32_t pk_h2(float lo, float hi) {
    __half2 h = __floats2half2_rn(lo, hi);
    return *(uint32_t*)&h;
}
__device__ __forceinline__ void mma_tf32(float& c0, float& c1, float& c2, float& c3,
                                         uint32_t a0, uint32_t a1, uint32_t a2, uint32_t a3,
                                         uint32_t b0, uint32_t b1) {
    asm("mma.sync.aligned.m16n8k8.row.col.f32.tf32.tf32.f32 "
        "{%0,%1,%2,%3},{%4,%5,%6,%7},{%8,%9},{%0,%1,%2,%3};"
        : "+f"(c0), "+f"(c1), "+f"(c2), "+f"(c3)
        : "r"(a0), "r"(a1), "r"(a2), "r"(a3), "r"(b0), "r"(b1));
}
__device__ __forceinline__ void mma_f16(float& c0, float& c1, float& c2, float& c3,
                                        uint32_t a0, uint32_t a1, uint32_t a2, uint32_t a3,
                                        uint32_t b0, uint32_t b1) {
    asm("mma.sync.aligned.m16n8k16.row.col.f32.f16.f16.f32 "
        "{%0,%1,%2,%3},{%4,%5,%6,%7},{%8,%9},{%0,%1,%2,%3};"
        : "+f"(c0), "+f"(c1), "+f"(c2), "+f"(c3)
        : "r"(a0), "r"(a1), "r"(a2), "r"(a3), "r"(b0), "r"(b1));
}
__device__ __forceinline__ void cpasync16(uint32_t dst, const void* src) {
    asm volatile("cp.async.cg.shared.global [%0], [%1], 16;" :: "r"(dst), "l"(src));
}
#define CP_COMMIT() asm volatile("cp.async.commit_group;")
#define CP_WAIT(n)  asm volatile("cp.async.wait_group %0;" :: "n"(n))

/* =====================================================================
 * Kernel 0: one-time tf32 rounding of weights
 * ===================================================================== */
__global__ void round_copy(const float* __restrict__ src, float* __restrict__ dst) {
    int i = (blockIdx.x * 256 + threadIdx.x) * 4;
    float4 v = *(const float4*)(src + i);
    v.x = __uint_as_float(f2tf(v.x));
    v.y = __uint_as_float(f2tf(v.y));
    v.z = __uint_as_float(f2tf(v.z));
    v.w = __uint_as_float(f2tf(v.w));
    *(float4*)(dst + i) = v;
}

/* =====================================================================
 * Kernel 1: channel LayerNorm (round-10 verbatim)
 * ===================================================================== */
__global__ void __launch_bounds__(512)
ln_kernel(const float* __restrict__ x,
          const float* __restrict__ g,
          float* __restrict__ xn) {
    __shared__ float gs[CDIM];
    __shared__ float red[2][8][64];
    int t = threadIdx.x;
    if (t < CDIM) gs[t] = g[t];

    int nl = t & 63;
    int cs = t >> 6;
    int pos0 = blockIdx.x * 64;
    int b  = pos0 / NPOS;
    int n0 = pos0 % NPOS;

    const float* xp = x + (long)b * CDIM * NPOS + n0 + nl;
    float s = 0.f, ss = 0.f;
    #pragma unroll 8
    for (int c = cs * 64; c < cs * 64 + 64; c++) {
        float v = xp[(long)c * NPOS];
        s += v; ss += v * v;
    }
    red[0][cs][nl] = s;  red[1][cs][nl] = ss;
    __syncthreads();
    float st = 0.f, sst = 0.f;
    #pragma unroll
    for (int k = 0; k < 8; k++) { st += red[0][k][nl]; sst += red[1][k][nl]; }
    float mean = st * (1.f / CDIM);
    float inv  = rsqrtf(sst * (1.f / CDIM) - mean * mean + EPS_LN);

    float* op = xn + (long)b * CDIM * NPOS + n0 + nl;
    #pragma unroll 8
    for (int c = cs * 64; c < cs * 64 + 64; c++) {
        float v = xp[(long)c * NPOS];
        op[(long)c * NPOS] = __uint_as_float(f2tf((v - mean) * inv * gs[c]));
    }
}

/* =====================================================================
 * Kernel 2/4: TF32 TC GEMM (round-10 verbatim: 3-stage, tail CP_WAIT(0))
 * ===================================================================== */
#define ASTG (128 * 36)
#define BSTG (32 * 136)
#define GEMM_SMEM_BYTES (3 * (ASTG + BSTG) * 4)

__global__ void __launch_bounds__(256, 2)
gemm_tc(const float* __restrict__ A, const float* __restrict__ Bm,
        float* __restrict__ C, const float* __restrict__ bias,
        int M, int K, int round_out) {
    extern __shared__ uint32_t gsm[];
    uint32_t* Asb = gsm;
    uint32_t* Bsb = gsm + 3 * ASTG;

    int t = threadIdx.x, lane = t & 31, w = t >> 5;
    int m0 = blockIdx.x * 128, n0 = blockIdx.y * 128, b = blockIdx.z;
    const float* Ab = A  + (long)m0 * K;
    const float* Bb = Bm + (long)b * K * NPOS + n0;
    float*       Cb = C  + (long)b * M * NPOS;

    uint32_t sbase = (uint32_t)__cvta_generic_to_shared(gsm);

    int wm = (w >> 2) * 64;
    int wn = (w & 3) * 32;
    int g  = lane >> 2, tg = lane & 3;

    float acc[4][4][4];
    #pragma unroll
    for (int i = 0; i < 4; i++)
        #pragma unroll
        for (int j = 0; j < 4; j++)
            #pragma unroll
            for (int r = 0; r < 4; r++) acc[i][j][r] = 0.f;

    const int NIT = K / 32;

    auto load_stage = [&](int buf, int k0) {
        #pragma unroll
        for (int ss = 0; ss < 4; ss++) {
            int c = ss * 256 + t;
            int row = c >> 3, cq = (c & 7) << 2;
            cpasync16(sbase + (buf * ASTG + row * 36 + cq) * 4,
                      Ab + (long)row * K + k0 + cq);
        }
        #pragma unroll
        for (int ss = 0; ss < 4; ss++) {
            int c = ss * 256 + t;
            int row = c >> 5, cq = (c & 31) << 2;
            cpasync16(sbase + (3 * ASTG + buf * BSTG + row * 136 + cq) * 4,
                      Bb + (long)(k0 + row) * NPOS + cq);
        }
        CP_COMMIT();
    };

    load_stage(0, 0);
    if (NIT > 1) load_stage(1, 32);

    for (int it = 0; it < NIT; it++) {
        if (it + 1 < NIT) { CP_WAIT(1); } else { CP_WAIT(0); }
        __syncthreads();
        if (it + 2 < NIT) load_stage((it + 2) % 3, (it + 2) * 32);

        const uint32_t* Ab_s = Asb + (it % 3) * ASTG;
        const uint32_t* Bb_s = Bsb + (it % 3) * BSTG;

        #pragma unroll
        for (int kk = 0; kk < 32; kk += 8) {
            uint32_t af[4][4];
            #pragma unroll
            for (int mt = 0; mt < 4; mt++) {
                int r = wm + mt * 16 + g;
                af[mt][0] = Ab_s[r * 36 + kk + tg];
                af[mt][1] = Ab_s[(r + 8) * 36 + kk + tg];
                af[mt][2] = Ab_s[r * 36 + kk + tg + 4];
                af[mt][3] = Ab_s[(r + 8) * 36 + kk + tg + 4];
            }
            uint32_t bf[4][2];
            #pragma unroll
            for (int nt = 0; nt < 4; nt++) {
                int c = wn + nt * 8 + g;
                bf[nt][0] = Bb_s[(kk + tg) * 136 + c];
                bf[nt][1] = Bb_s[(kk + tg + 4) * 136 + c];
            }
            #pragma unroll
            for (int mt = 0; mt < 4; mt++)
                #pragma unroll
                for (int nt = 0; nt < 4; nt++)
                    mma_tf32(acc[mt][nt][0], acc[mt][nt][1], acc[mt][nt][2], acc[mt][nt][3],
                             af[mt][0], af[mt][1], af[mt][2], af[mt][3],
                             bf[nt][0], bf[nt][1]);
        }
    }

    #pragma unroll
    for (int mt = 0; mt < 4; mt++) {
        int r0 = m0 + wm + mt * 16 + g;
        float b0 = bias ? bias[r0]     : 0.f;
        float b1 = bias ? bias[r0 + 8] : 0.f;
        #pragma unroll
        for (int nt = 0; nt < 4; nt++) {
            int c0 = n0 + wn + nt * 8 + 2 * tg;
            float v0 = acc[mt][nt][0] + b0, v1 = acc[mt][nt][1] + b0;
            float v2 = acc[mt][nt][2] + b1, v3 = acc[mt][nt][3] + b1;
            if (round_out) {
                v0 = __uint_as_float(f2tf(v0)); v1 = __uint_as_float(f2tf(v1));
                v2 = __uint_as_float(f2tf(v2)); v3 = __uint_as_float(f2tf(v3));
            }
            *(float2*)(Cb + (long)r0 * NPOS + c0)       = make_float2(v0, v1);
            *(float2*)(Cb + (long)(r0 + 8) * NPOS + c0) = make_float2(v2, v3);
        }
    }
}

/* =====================================================================
 * Kernel R1: repack Q/K -> half2 d-pair words.
 * Qpk/Kpk[bh][dp][n] : word = half2( v(2dp, n), v(2dp+1, n) ).
 * Q scaled by 0.125 (exact). grid (64, bh=64, part=2), 256 thr.
 * ===================================================================== */
__global__ void __launch_bounds__(256)
repack_qk(const float* __restrict__ qkv,
          uint32_t* __restrict__ qpk, uint32_t* __restrict__ kpk) {
    int part = blockIdx.z;                       /* 0=q, 1=k */
    int bh   = blockIdx.y;
    int b = bh >> 3, h = bh & 7;
    int lin = blockIdx.x * 256 + threadIdx.x;    /* 16384 per (bh,part) */
    int dp = lin >> 9;                           /* 0..31 */
    int n4 = (lin & 511) * 4;                    /* 0..2044 */

    const float* r0 = qkv + ((long)b * QKV_ROWS + part * HIDDEN + h * DIM_HEAD
                              + 2 * dp) * NPOS + n4;
    const float* r1 = r0 + NPOS;
    float s = part == 0 ? 0.125f : 1.0f;
    float4 v0 = *(const float4*)r0;
    float4 v1 = *(const float4*)r1;
    uint4 wv;
    wv.x = pk_h2(v0.x * s, v1.x * s);
    wv.y = pk_h2(v0.y * s, v1.y * s);
    wv.z = pk_h2(v0.z * s, v1.z * s);
    wv.w = pk_h2(v0.w * s, v1.w * s);
    uint32_t* dst = (part == 0 ? qpk : kpk) + ((long)bh * 32 + dp) * 2048 + n4;
    *(uint4*)dst = wv;
}

/* =====================================================================
 * Kernel R2: repack V -> half2 j-pair words (smem-tiled transpose).
 * Vpk[bh][jp][d] : word = half2( v(d, 2jp), v(d, 2jp+1) ).
 * grid (jt=32, bh=64), 256 thr. Tile 64d x 64j.
 * ===================================================================== */
__global__ void __launch_bounds__(256)
repack_v(const float* __restrict__ qkv, uint32_t* __restrict__ vpk) {
    __shared__ float sm[64 * 68];
    int bh = blockIdx.y;
    int b = bh >> 3, h = bh & 7;
    int j0 = blockIdx.x * 64;
    int t = threadIdx.x;

    const float* vb = qkv + ((long)b * QKV_ROWS + 2 * HIDDEN + h * DIM_HEAD) * NPOS;
    #pragma unroll
    for (int it = 0; it < 4; it++) {
        int lin = it * 256 + t;                  /* 1024 float4s */
        int d = lin >> 4, j4 = (lin & 15) * 4;
        *(float4*)&sm[d * 68 + j4] = *(const float4*)(vb + (long)d * NPOS + j0 + j4);
    }
    __syncthreads();
    int d  = t & 63;
    int jg = t >> 6;                             /* 0..3 */
    #pragma unroll
    for (int jt = 0; jt < 8; jt++) {
        int jp = jg * 8 + jt;                    /* 0..31 */
        uint32_t wv = pk_h2(sm[d * 68 + 2 * jp], sm[d * 68 + 2 * jp + 1]);
        vpk[((long)bh * 1024 + (j0 >> 1) + jp) * 64 + d] = wv;
    }
}

/* =====================================================================
 * Kernel 3: fused FP16 flash attention.
 * Round-10 structure/sync verbatim; fp16 m16n8k16 MMAs (half the
 * instructions and fragment LDS). smem 36864 B -> 4 CTAs/SM.
 * Regions (uint32 words, stride 72, 32 rows each):
 *  QH@0, KH@2304, VH@4608, PH@6912; total 9216 words.
 * Epilogue fp32 scratch overlays words 0..4351 (stride 68).
 * ===================================================================== */
#define HST 72
#define QH_OFF 0
#define KH_OFF 2304
#define VH_OFF 4608
#define PH_OFF 6912
#define ATTN_SMEM_WORDS 9216

__global__ void __launch_bounds__(128, 4)
attn_f16(const uint32_t* __restrict__ qpk, const uint32_t* __restrict__ kpk,
         const uint32_t* __restrict__ vpk, float* __restrict__ ao) {
    extern __shared__ uint32_t sm4[];
    uint32_t* QH = sm4 + QH_OFF;
    uint32_t* KH = sm4 + KH_OFF;
    uint32_t* VH = sm4 + VH_OFF;
    uint32_t* PH = sm4 + PH_OFF;
    uint32_t sbase = (uint32_t)__cvta_generic_to_shared(sm4);

    int t = threadIdx.x, lane = t & 31, w = t >> 5;
    int g = lane >> 2, tg = lane & 3;
    int iw = w * 16;

    int qt = blockIdx.x;                 /* 0..31 */
    int bh = blockIdx.y;                 /* 0..63 */
    int b  = bh >> 3, h = bh & 7;
    int i0 = qt * 64;

    const uint32_t* qb = qpk + (long)bh * 32 * 2048;
    const uint32_t* kb = kpk + (long)bh * 32 * 2048;
    const uint32_t* vb = vpk + (long)bh * 1024 * 64;

    auto load_k = [&](int j0) {
        #pragma unroll
        for (int ss = 0; ss < 4; ss++) {
            int c = ss * 128 + t;                /* 512 chunks */
            int dp = c >> 4, cw = (c & 15) << 2;
            cpasync16(sbase + (KH_OFF + dp * HST + cw) * 4,
                      kb + (long)dp * 2048 + j0 + cw);
        }
        CP_COMMIT();
    };
    auto load_v = [&](int j0) {
        #pragma unroll
        for (int ss = 0; ss < 4; ss++) {
            int c = ss * 128 + t;
            int jp = c >> 4, cw = (c & 15) << 2;
            cpasync16(sbase + (VH_OFF + jp * HST + cw) * 4,
                      vb + ((long)(j0 >> 1) + jp) * 64 + cw);
        }
        CP_COMMIT();
    };

    load_k(0);
    load_v(0);

    /* Q tile: plain loads (once) into QH[dp][i] */
    #pragma unroll
    for (int ss = 0; ss < 4; ss++) {
        int c = ss * 128 + t;
        int dp = c >> 4, cw = (c & 15) << 2;
        uint4 v = *(const uint4*)(qb + (long)dp * 2048 + i0 + cw);
        *(uint4*)&QH[dp * HST + cw] = v;
    }

    float m_s[2], l_s[2];
    float o[8][4];
    m_s[0] = m_s[1] = -1e30f;
    l_s[0] = l_s[1] = 0.f;
    #pragma unroll
    for (int nt = 0; nt < 8; nt++)
        #pragma unroll
        for (int r = 0; r < 4; r++) o[nt][r] = 0.f;

    const int T = NPOS / 64;
    for (int ti = 0; ti < T; ti++) {
        CP_WAIT(1);                      /* K(ti) landed, V(ti) may pend */
        __syncthreads();

        /* ---- S = Q^T K : warp 16i x 64j, fp16 k16 ---- */
        float sa[8][4];
        #pragma unroll
        for (int nt = 0; nt < 8; nt++)
            #pragma unroll
            for (int r = 0; r < 4; r++) sa[nt][r] = 0.f;

        #pragma unroll
        for (int kbk = 0; kbk < 4; kbk++) {
            int r0 = iw + g;
            int q0 = (kbk * 8 + tg) * HST;
            int q1 = (kbk * 8 + 4 + tg) * HST;
            uint32_t a0 = QH[q0 + r0];
            uint32_t a1 = QH[q0 + r0 + 8];
            uint32_t a2 = QH[q1 + r0];
            uint32_t a3 = QH[q1 + r0 + 8];
            #pragma unroll
            for (int nt = 0; nt < 8; nt++) {
                uint32_t b0 = KH[q0 + nt * 8 + g];
                uint32_t b1 = KH[q1 + nt * 8 + g];
                mma_f16(sa[nt][0], sa[nt][1], sa[nt][2], sa[nt][3],
                        a0, a1, a2, a3, b0, b1);
            }
        }
        __syncthreads();
        if (ti + 1 < T) load_k((ti + 1) * 64);

        /* ---- online softmax: round-10 numerics; P packed fp16 ---- */
        {
            float mx0 = -1e30f, mx1 = -1e30f;
            #pragma unroll
            for (int nt = 0; nt < 8; nt++) {
                mx0 = fmaxf(mx0, fmaxf(sa[nt][0], sa[nt][1]));
                mx1 = fmaxf(mx1, fmaxf(sa[nt][2], sa[nt][3]));
            }
            mx0 = fmaxf(mx0, __shfl_xor_sync(0xffffffffu, mx0, 1));
            mx0 = fmaxf(mx0, __shfl_xor_sync(0xffffffffu, mx0, 2));
            mx1 = fmaxf(mx1, __shfl_xor_sync(0xffffffffu, mx1, 1));
            mx1 = fmaxf(mx1, __shfl_xor_sync(0xffffffffu, mx1, 2));
            float mn0 = fmaxf(m_s[0], mx0);
            float mn1 = fmaxf(m_s[1], mx1);
            float s0 = 0.f, s1 = 0.f;
            int r0 = iw + g;
            #pragma unroll
            for (int nt = 0; nt < 8; nt++) {
                float p0 = __expf(sa[nt][0] - mn0);
                float p1 = __expf(sa[nt][1] - mn0);
                float p2 = __expf(sa[nt][2] - mn1);
                float p3 = __expf(sa[nt][3] - mn1);
                s0 += p0 + p1;  s1 += p2 + p3;
                int jp = nt * 4 + tg;
                PH[jp * HST + r0]     = pk_h2(p0, p1);
                PH[jp * HST + r0 + 8] = pk_h2(p2, p3);
            }
            s0 += __shfl_xor_sync(0xffffffffu, s0, 1);
            s0 += __shfl_xor_sync(0xffffffffu, s0, 2);
            s1 += __shfl_xor_sync(0xffffffffu, s1, 1);
            s1 += __shfl_xor_sync(0xffffffffu, s1, 2);
            float al0 = __expf(m_s[0] - mn0);
            float al1 = __expf(m_s[1] - mn1);
            l_s[0] = l_s[0] * al0 + s0;  m_s[0] = mn0;
            l_s[1] = l_s[1] * al1 + s1;  m_s[1] = mn1;
            #pragma unroll
            for (int nt = 0; nt < 8; nt++) {
                o[nt][0] *= al0; o[nt][1] *= al0;
                o[nt][2] *= al1; o[nt][3] *= al1;
            }
        }
        __syncwarp();                    /* P rows warp-local */

        if (ti + 1 < T) { CP_WAIT(1); } else { CP_WAIT(0); }
        __syncthreads();

        /* ---- O += P V^T : warp 16i x 64d, fp16 k16 ---- */
        #pragma unroll
        for (int jb = 0; jb < 4; jb++) {
            int r0 = iw + g;
            int p0r = (jb * 8 + tg) * HST;
            int p1r = (jb * 8 + 4 + tg) * HST;
            uint32_t a0 = PH[p0r + r0];
            uint32_t a1 = PH[p0r + r0 + 8];
            uint32_t a2 = PH[p1r + r0];
            uint32_t a3 = PH[p1r + r0 + 8];
            #pragma unroll
            for (int nt = 0; nt < 8; nt++) {
                uint32_t b0 = VH[p0r + nt * 8 + g];
                uint32_t b1 = VH[p1r + nt * 8 + g];
                mma_f16(o[nt][0], o[nt][1], o[nt][2], o[nt][3],
                        a0, a1, a2, a3, b0, b1);
            }
        }
        __syncthreads();
        if (ti + 1 < T) load_v((ti + 1) * 64);
    }

    /* ---- epilogue: normalize, tf32-round, transpose via fp32 scratch ---- */
    __syncthreads();
    {
        float inv0 = 1.f / l_s[0], inv1 = 1.f / l_s[1];
        int r0 = iw + g;
        #pragma unroll
        for (int nt = 0; nt < 8; nt++) {
            int d0 = nt * 8 + 2 * tg;
            sm4[d0 * 68 + r0]           = f2tf(o[nt][0] * inv0);
            sm4[(d0 + 1) * 68 + r0]     = f2tf(o[nt][1] * inv0);
            sm4[d0 * 68 + r0 + 8]       = f2tf(o[nt][2] * inv1);
            sm4[(d0 + 1) * 68 + r0 + 8] = f2tf(o[nt][3] * inv1);
        }
    }
    __syncthreads();
    float* aop = ao + (long)b * HIDDEN * NPOS + (long)h * DIM_HEAD * NPOS + i0;
    #pragma unroll
    for (int ss = 0; ss < 8; ss++) {
        int lin = ss * 128 + t;
        int d = lin >> 4, i = (lin & 15) << 2;
        float4 v;
        v.x = __uint_as_float(sm4[d * 68 + i]);
        v.y = __uint_as_float(sm4[d * 68 + i + 1]);
        v.z = __uint_as_float(sm4[d * 68 + i + 2]);
        v.w = __uint_as_float(sm4[d * 68 + i + 3]);
        *(float4*)(aop + (long)d * NPOS + i) = v;
    }
}

/* ===================================================================== */
extern "C" void kernel_launch(void* const* d_in, const int* in_sizes, int n_in,
                              void* d_out, int out_size) {
    const float* x    = (const float*)d_in[0];
    const float* g    = (const float*)d_in[1];
    const float* Wqkv = (const float*)d_in[2];
    const float* Wout = (const float*)d_in[3];
    const float* bout = (const float*)d_in[4];
    float* out = (float*)d_out;

    float *xn, *qkv, *ao, *wq, *wo;
    uint32_t *qpk, *kpk, *vpk;
    cudaGetSymbolAddress((void**)&xn,  g_xn);
    cudaGetSymbolAddress((void**)&qkv, g_qkv);
    cudaGetSymbolAddress((void**)&ao,  g_ao);
    cudaGetSymbolAddress((void**)&wq,  g_wq);
    cudaGetSymbolAddress((void**)&wo,  g_wo);
    cudaGetSymbolAddress((void**)&qpk, g_qpk);
    cudaGetSymbolAddress((void**)&kpk, g_kpk);
    cudaGetSymbolAddress((void**)&vpk, g_vpk);

    /* 0. one-time weight rounding */
    round_copy<<<(QKV_ROWS * CDIM) / 1024, 256>>>(Wqkv, wq);
    round_copy<<<(CDIM * HIDDEN) / 1024, 256>>>(Wout, wo);

    /* 1. LayerNorm */
    ln_kernel<<<(BATCH * NPOS) / 64, 512>>>(x, g, xn);

    /* 2. QKV projection (tf32, rounded output) */
    cudaFuncSetAttribute(gemm_tc,
                         cudaFuncAttributeMaxDynamicSharedMemorySize,
                         GEMM_SMEM_BYTES);
    gemm_tc<<<dim3(QKV_ROWS / 128, NPOS / 128, BATCH), 256, GEMM_SMEM_BYTES>>>(
        wq, xn, qkv, nullptr, QKV_ROWS, CDIM, 1);

    /* 2b. repack q/k/v into fp16 MMA layouts */
    repack_qk<<<dim3(64, 64, 2), 256>>>(qkv, qpk, kpk);
    repack_v<<<dim3(32, 64), 256>>>(qkv, vpk);

    /* 3. fused fp16 attention */
    size_t smem = ATTN_SMEM_WORDS * sizeof(uint32_t);   /* 36864 B */
    cudaFuncSetAttribute(attn_f16,
                         cudaFuncAttributeMaxDynamicSharedMemorySize, (int)smem);
    attn_f16<<<dim3(NPOS / 64, BATCH * HEADS), 128, smem>>>(qpk, kpk, vpk, ao);

    /* 4. output projection + bias (tf32, full fp32 out) */
    gemm_tc<<<dim3(HIDDEN / 128, NPOS / 128, BATCH), 256, GEMM_SMEM_BYTES>>>(
        wo, ao, out, bout, HIDDEN, CDIM, 0);
}

// round 13
// speedup vs baseline: 6.9354x; 1.2201x over previous
#include <cuda_runtime.h>
#include <cuda_fp16.h>
#include <cstdint>

#define BATCH    8
#define CDIM     512
#define NPOS     2048
#define HEADS    8
#define DIM_HEAD 64
#define HIDDEN   512
#define QKV_ROWS 1536
#define EPS_LN   1e-5f

/* ---------------- scratch (static device globals) ---------------- */
__device__ float    g_qkv[BATCH * QKV_ROWS * NPOS];  /* tf32 q,k,v [b][row][n]      */
__device__ uint32_t g_xnh[BATCH * 256 * NPOS];       /* LN out half2 [b][cp][n]     */
__device__ uint32_t g_aoh[BATCH * 256 * NPOS];       /* attn out half2 [b][kp][n]   */
__device__ uint32_t g_wqh[256 * QKV_ROWS];           /* W_qkv half2 [kp][M]         */
__device__ uint32_t g_woh[256 * CDIM];               /* W_out half2 [kp][M]         */
__device__ uint32_t g_qpk[64 * 32 * 2048];           /* Q half2 d-pairs [bh][dp][n] */
__device__ uint32_t g_kpk[64 * 32 * 2048];           /* K half2 d-pairs [bh][dp][n] */
__device__ uint32_t g_vpk[64 * 1024 * 64];           /* V half2 j-pairs [bh][jp][d] */

/* ---------------- helpers ---------------- */
__device__ __forceinline__ uint32_t f2tf(float f) {
    uint32_t u;
    asm("cvt.rna.tf32.f32 %0, %1;" : "=r"(u) : "f"(f));
    return u;
}
__device__ __forceinline__ float tfr(float f) { return __uint_as_float(f2tf(f)); }
__device__ __forceinline__ uint32_t pk_h2(float lo, float hi) {
    __half2 h = __floats2half2_rn(lo, hi);
    return *(uint32_t*)&h;
}
__device__ __forceinline__ void mma_f16(float& c0, float& c1, float& c2, float& c3,
                                        uint32_t a0, uint32_t a1, uint32_t a2, uint32_t a3,
                                        uint32_t b0, uint32_t b1) {
    asm("mma.sync.aligned.m16n8k16.row.col.f32.f16.f16.f32 "
        "{%0,%1,%2,%3},{%4,%5,%6,%7},{%8,%9},{%0,%1,%2,%3};"
        : "+f"(c0), "+f"(c1), "+f"(c2), "+f"(c3)
        : "r"(a0), "r"(a1), "r"(a2), "r"(a3), "r"(b0), "r"(b1));
}
__device__ __forceinline__ void cpasync16(uint32_t dst, const void* src) {
    asm volatile("cp.async.cg.shared.global [%0], [%1], 16;" :: "r"(dst), "l"(src));
}
#define CP_COMMIT() asm volatile("cp.async.commit_group;")
#define CP_WAIT(n)  asm volatile("cp.async.wait_group %0;" :: "n"(n))

/* =====================================================================
 * Kernel 0: one-time weight prepack: tf32-round -> half2 k-pair words,
 * layout [kp][M]  (word(kp,m) = half2(W[m][2kp], W[m][2kp+1])).
 * ===================================================================== */
__global__ void pack_w(const float* __restrict__ src, uint32_t* __restrict__ dst,
                       int M, int K) {
    int lin = blockIdx.x * 256 + threadIdx.x;    /* M*K/2 items */
    int kp = lin % (K >> 1);
    int m  = lin / (K >> 1);
    float a = tfr(src[(long)m * K + 2 * kp]);
    float b = tfr(src[(long)m * K + 2 * kp + 1]);
    dst[(long)kp * M + m] = pk_h2(a, b);
}

/* =====================================================================
 * Kernel 1: channel LayerNorm -> packed half2 [b][cp][n].
 * Same per-element math as round-12 (f2tf then exact half convert).
 * ===================================================================== */
__global__ void __launch_bounds__(512)
ln_kernel(const float* __restrict__ x,
          const float* __restrict__ g,
          uint32_t* __restrict__ xnh) {
    __shared__ float gs[CDIM];
    __shared__ float red[2][8][64];
    int t = threadIdx.x;
    if (t < CDIM) gs[t] = g[t];

    int nl = t & 63;
    int cs = t >> 6;
    int pos0 = blockIdx.x * 64;
    int b  = pos0 / NPOS;
    int n0 = pos0 % NPOS;

    const float* xp = x + (long)b * CDIM * NPOS + n0 + nl;
    float s = 0.f, ss = 0.f;
    #pragma unroll 8
    for (int c = cs * 64; c < cs * 64 + 64; c++) {
        float v = xp[(long)c * NPOS];
        s += v; ss += v * v;
    }
    red[0][cs][nl] = s;  red[1][cs][nl] = ss;
    __syncthreads();
    float st = 0.f, sst = 0.f;
    #pragma unroll
    for (int k = 0; k < 8; k++) { st += red[0][k][nl]; sst += red[1][k][nl]; }
    float mean = st * (1.f / CDIM);
    float inv  = rsqrtf(sst * (1.f / CDIM) - mean * mean + EPS_LN);

    uint32_t* op = xnh + (long)b * 256 * NPOS + n0 + nl;
    #pragma unroll 8
    for (int c = cs * 64; c < cs * 64 + 64; c += 2) {
        float v0 = tfr((xp[(long)(c + 0) * NPOS] - mean) * inv * gs[c + 0]);
        float v1 = tfr((xp[(long)(c + 1) * NPOS] - mean) * inv * gs[c + 1]);
        op[(long)(c >> 1) * NPOS] = pk_h2(v0, v1);
    }
}

/* =====================================================================
 * Kernel 2/4: FP16 TC GEMM (fp32 accumulate), 3-stage cp.async.
 *   C[b][m][n] = A[m][k] * B[b][k][n]  (+bias, optional tf32 round)
 * A prepacked [kp][M] half2; B packed [b][kp][NPOS] half2.
 * Tile 128m x 128n x 32k (16 kp rows). Stage = A[16][136] + B[16][136]
 * words; 3 stages = 52224 B. Fragment layout mirrors the validated
 * attention fp16 S-phase term-for-term.
 * ===================================================================== */
#define FASTG (16 * 136)
#define GEMM16_SMEM (3 * 2 * FASTG * 4)

__global__ void __launch_bounds__(256, 2)
gemm_f16(const uint32_t* __restrict__ Ah, const uint32_t* __restrict__ Bh,
         float* __restrict__ C, const float* __restrict__ bias,
         int M, int K, int round_out) {
    extern __shared__ uint32_t gsm[];
    uint32_t* Asb = gsm;                 /* 3 x FASTG */
    uint32_t* Bsb = gsm + 3 * FASTG;     /* 3 x FASTG */

    int t = threadIdx.x, lane = t & 31, w = t >> 5;
    int m0 = blockIdx.x * 128, n0 = blockIdx.y * 128, b = blockIdx.z;
    const uint32_t* Ab = Ah + m0;                        /* [kp][M] */
    const uint32_t* Bb = Bh + (long)b * (K >> 1) * NPOS + n0;
    float*           Cb = C  + (long)b * M * NPOS;

    uint32_t sbase = (uint32_t)__cvta_generic_to_shared(gsm);

    int wm = (w >> 2) * 64;
    int wn = (w & 3) * 32;
    int g  = lane >> 2, tg = lane & 3;

    float acc[4][4][4];
    #pragma unroll
    for (int i = 0; i < 4; i++)
        #pragma unroll
        for (int j = 0; j < 4; j++)
            #pragma unroll
            for (int r = 0; r < 4; r++) acc[i][j][r] = 0.f;

    const int NIT = K / 32;              /* 16 */

    auto load_stage = [&](int buf, int kp0) {
        #pragma unroll
        for (int ss = 0; ss < 2; ss++) {          /* A: 16x128 words = 512 chunks */
            int c = ss * 256 + t;
            int row = c >> 5, cw = (c & 31) << 2;
            cpasync16(sbase + (buf * FASTG + row * 136 + cw) * 4,
                      Ab + (long)(kp0 + row) * M + cw);
        }
        #pragma unroll
        for (int ss = 0; ss < 2; ss++) {          /* B: 16x128 words */
            int c = ss * 256 + t;
            int row = c >> 5, cw = (c & 31) << 2;
            cpasync16(sbase + ((3 + buf) * FASTG + row * 136 + cw) * 4,
                      Bb + (long)(kp0 + row) * NPOS + cw);
        }
        CP_COMMIT();
    };

    load_stage(0, 0);
    if (NIT > 1) load_stage(1, 16);

    for (int it = 0; it < NIT; it++) {
        if (it + 1 < NIT) { CP_WAIT(1); } else { CP_WAIT(0); }
        __syncthreads();
        if (it + 2 < NIT) load_stage((it + 2) % 3, (it + 2) * 16);

        const uint32_t* Ab_s = Asb + (it % 3) * FASTG;
        const uint32_t* Bb_s = Bsb + (it % 3) * FASTG;

        #pragma unroll
        for (int kb = 0; kb < 2; kb++) {
            int kr0 = (kb * 8 + tg) * 136;
            int kr1 = (kb * 8 + 4 + tg) * 136;
            uint32_t af[4][4];
            #pragma unroll
            for (int mt = 0; mt < 4; mt++) {
                int r = wm + mt * 16 + g;
                af[mt][0] = Ab_s[kr0 + r];
                af[mt][1] = Ab_s[kr0 + r + 8];
                af[mt][2] = Ab_s[kr1 + r];
                af[mt][3] = Ab_s[kr1 + r + 8];
            }
            uint32_t bf[4][2];
            #pragma unroll
            for (int nt = 0; nt < 4; nt++) {
                int c = wn + nt * 8 + g;
                bf[nt][0] = Bb_s[kr0 + c];
                bf[nt][1] = Bb_s[kr1 + c];
            }
            #pragma unroll
            for (int mt = 0; mt < 4; mt++)
                #pragma unroll
                for (int nt = 0; nt < 4; nt++)
                    mma_f16(acc[mt][nt][0], acc[mt][nt][1], acc[mt][nt][2], acc[mt][nt][3],
                            af[mt][0], af[mt][1], af[mt][2], af[mt][3],
                            bf[nt][0], bf[nt][1]);
        }
    }

    #pragma unroll
    for (int mt = 0; mt < 4; mt++) {
        int r0 = m0 + wm + mt * 16 + g;
        float b0 = bias ? bias[r0]     : 0.f;
        float b1 = bias ? bias[r0 + 8] : 0.f;
        #pragma unroll
        for (int nt = 0; nt < 4; nt++) {
            int c0 = n0 + wn + nt * 8 + 2 * tg;
            float v0 = acc[mt][nt][0] + b0, v1 = acc[mt][nt][1] + b0;
            float v2 = acc[mt][nt][2] + b1, v3 = acc[mt][nt][3] + b1;
            if (round_out) { v0 = tfr(v0); v1 = tfr(v1); v2 = tfr(v2); v3 = tfr(v3); }
            *(float2*)(Cb + (long)r0 * NPOS + c0)       = make_float2(v0, v1);
            *(float2*)(Cb + (long)(r0 + 8) * NPOS + c0) = make_float2(v2, v3);
        }
    }
}

/* =====================================================================
 * Kernel R1/R2: repack q/k/v into attention fp16 layouts (R12 verbatim)
 * ===================================================================== */
__global__ void __launch_bounds__(256)
repack_qk(const float* __restrict__ qkv,
          uint32_t* __restrict__ qpk, uint32_t* __restrict__ kpk) {
    int part = blockIdx.z;
    int bh   = blockIdx.y;
    int b = bh >> 3, h = bh & 7;
    int lin = blockIdx.x * 256 + threadIdx.x;
    int dp = lin >> 9;
    int n4 = (lin & 511) * 4;

    const float* r0 = qkv + ((long)b * QKV_ROWS + part * HIDDEN + h * DIM_HEAD
                              + 2 * dp) * NPOS + n4;
    const float* r1 = r0 + NPOS;
    float s = part == 0 ? 0.125f : 1.0f;
    float4 v0 = *(const float4*)r0;
    float4 v1 = *(const float4*)r1;
    uint4 wv;
    wv.x = pk_h2(v0.x * s, v1.x * s);
    wv.y = pk_h2(v0.y * s, v1.y * s);
    wv.z = pk_h2(v0.z * s, v1.z * s);
    wv.w = pk_h2(v0.w * s, v1.w * s);
    uint32_t* dst = (part == 0 ? qpk : kpk) + ((long)bh * 32 + dp) * 2048 + n4;
    *(uint4*)dst = wv;
}

__global__ void __launch_bounds__(256)
repack_v(const float* __restrict__ qkv, uint32_t* __restrict__ vpk) {
    __shared__ float sm[64 * 68];
    int bh = blockIdx.y;
    int b = bh >> 3, h = bh & 7;
    int j0 = blockIdx.x * 64;
    int t = threadIdx.x;

    const float* vb = qkv + ((long)b * QKV_ROWS + 2 * HIDDEN + h * DIM_HEAD) * NPOS;
    #pragma unroll
    for (int it = 0; it < 4; it++) {
        int lin = it * 256 + t;
        int d = lin >> 4, j4 = (lin & 15) * 4;
        *(float4*)&sm[d * 68 + j4] = *(const float4*)(vb + (long)d * NPOS + j0 + j4);
    }
    __syncthreads();
    int d  = t & 63;
    int jg = t >> 6;
    #pragma unroll
    for (int jt = 0; jt < 8; jt++) {
        int jp = jg * 8 + jt;
        uint32_t wv = pk_h2(sm[d * 68 + 2 * jp], sm[d * 68 + 2 * jp + 1]);
        vpk[((long)bh * 1024 + (j0 >> 1) + jp) * 64 + d] = wv;
    }
}

/* =====================================================================
 * Kernel 3: fused FP16 flash attention (R12 verbatim inner loop).
 * Epilogue now emits packed half2 ao_h[b][kp][n] for the out-proj.
 * ===================================================================== */
#define HST 72
#define QH_OFF 0
#define KH_OFF 2304
#define VH_OFF 4608
#define PH_OFF 6912
#define ATTN_SMEM_WORDS 9216

__global__ void __launch_bounds__(128, 4)
attn_f16(const uint32_t* __restrict__ qpk, const uint32_t* __restrict__ kpk,
         const uint32_t* __restrict__ vpk, uint32_t* __restrict__ aoh) {
    extern __shared__ uint32_t sm4[];
    uint32_t* QH = sm4 + QH_OFF;
    uint32_t* KH = sm4 + KH_OFF;
    uint32_t* VH = sm4 + VH_OFF;
    uint32_t* PH = sm4 + PH_OFF;
    uint32_t sbase = (uint32_t)__cvta_generic_to_shared(sm4);

    int t = threadIdx.x, lane = t & 31, w = t >> 5;
    int g = lane >> 2, tg = lane & 3;
    int iw = w * 16;

    int qt = blockIdx.x;
    int bh = blockIdx.y;
    int b  = bh >> 3, h = bh & 7;
    int i0 = qt * 64;

    const uint32_t* qb = qpk + (long)bh * 32 * 2048;
    const uint32_t* kb = kpk + (long)bh * 32 * 2048;
    const uint32_t* vb = vpk + (long)bh * 1024 * 64;

    auto load_k = [&](int j0) {
        #pragma unroll
        for (int ss = 0; ss < 4; ss++) {
            int c = ss * 128 + t;
            int dp = c >> 4, cw = (c & 15) << 2;
            cpasync16(sbase + (KH_OFF + dp * HST + cw) * 4,
                      kb + (long)dp * 2048 + j0 + cw);
        }
        CP_COMMIT();
    };
    auto load_v = [&](int j0) {
        #pragma unroll
        for (int ss = 0; ss < 4; ss++) {
            int c = ss * 128 + t;
            int jp = c >> 4, cw = (c & 15) << 2;
            cpasync16(sbase + (VH_OFF + jp * HST + cw) * 4,
                      vb + ((long)(j0 >> 1) + jp) * 64 + cw);
        }
        CP_COMMIT();
    };

    load_k(0);
    load_v(0);

    #pragma unroll
    for (int ss = 0; ss < 4; ss++) {
        int c = ss * 128 + t;
        int dp = c >> 4, cw = (c & 15) << 2;
        uint4 v = *(const uint4*)(qb + (long)dp * 2048 + i0 + cw);
        *(uint4*)&QH[dp * HST + cw] = v;
    }

    float m_s[2], l_s[2];
    float o[8][4];
    m_s[0] = m_s[1] = -1e30f;
    l_s[0] = l_s[1] = 0.f;
    #pragma unroll
    for (int nt = 0; nt < 8; nt++)
        #pragma unroll
        for (int r = 0; r < 4; r++) o[nt][r] = 0.f;

    const int T = NPOS / 64;
    for (int ti = 0; ti < T; ti++) {
        CP_WAIT(1);
        __syncthreads();

        float sa[8][4];
        #pragma unroll
        for (int nt = 0; nt < 8; nt++)
            #pragma unroll
            for (int r = 0; r < 4; r++) sa[nt][r] = 0.f;

        #pragma unroll
        for (int kbk = 0; kbk < 4; kbk++) {
            int r0 = iw + g;
            int q0 = (kbk * 8 + tg) * HST;
            int q1 = (kbk * 8 + 4 + tg) * HST;
            uint32_t a0 = QH[q0 + r0];
            uint32_t a1 = QH[q0 + r0 + 8];
            uint32_t a2 = QH[q1 + r0];
            uint32_t a3 = QH[q1 + r0 + 8];
            #pragma unroll
            for (int nt = 0; nt < 8; nt++) {
                uint32_t b0 = KH[q0 + nt * 8 + g];
                uint32_t b1 = KH[q1 + nt * 8 + g];
                mma_f16(sa[nt][0], sa[nt][1], sa[nt][2], sa[nt][3],
                        a0, a1, a2, a3, b0, b1);
            }
        }
        __syncthreads();
        if (ti + 1 < T) load_k((ti + 1) * 64);

        {
            float mx0 = -1e30f, mx1 = -1e30f;
            #pragma unroll
            for (int nt = 0; nt < 8; nt++) {
                mx0 = fmaxf(mx0, fmaxf(sa[nt][0], sa[nt][1]));
                mx1 = fmaxf(mx1, fmaxf(sa[nt][2], sa[nt][3]));
            }
            mx0 = fmaxf(mx0, __shfl_xor_sync(0xffffffffu, mx0, 1));
            mx0 = fmaxf(mx0, __shfl_xor_sync(0xffffffffu, mx0, 2));
            mx1 = fmaxf(mx1, __shfl_xor_sync(0xffffffffu, mx1, 1));
            mx1 = fmaxf(mx1, __shfl_xor_sync(0xffffffffu, mx1, 2));
            float mn0 = fmaxf(m_s[0], mx0);
            float mn1 = fmaxf(m_s[1], mx1);
            float s0 = 0.f, s1 = 0.f;
            int r0 = iw + g;
            #pragma unroll
            for (int nt = 0; nt < 8; nt++) {
                float p0 = __expf(sa[nt][0] - mn0);
                float p1 = __expf(sa[nt][1] - mn0);
                float p2 = __expf(sa[nt][2] - mn1);
                float p3 = __expf(sa[nt][3] - mn1);
                s0 += p0 + p1;  s1 += p2 + p3;
                int jp = nt * 4 + tg;
                PH[jp * HST + r0]     = pk_h2(p0, p1);
                PH[jp * HST + r0 + 8] = pk_h2(p2, p3);
            }
            s0 += __shfl_xor_sync(0xffffffffu, s0, 1);
            s0 += __shfl_xor_sync(0xffffffffu, s0, 2);
            s1 += __shfl_xor_sync(0xffffffffu, s1, 1);
            s1 += __shfl_xor_sync(0xffffffffu, s1, 2);
            float al0 = __expf(m_s[0] - mn0);
            float al1 = __expf(m_s[1] - mn1);
            l_s[0] = l_s[0] * al0 + s0;  m_s[0] = mn0;
            l_s[1] = l_s[1] * al1 + s1;  m_s[1] = mn1;
            #pragma unroll
            for (int nt = 0; nt < 8; nt++) {
                o[nt][0] *= al0; o[nt][1] *= al0;
                o[nt][2] *= al1; o[nt][3] *= al1;
            }
        }
        __syncwarp();

        if (ti + 1 < T) { CP_WAIT(1); } else { CP_WAIT(0); }
        __syncthreads();

        #pragma unroll
        for (int jb = 0; jb < 4; jb++) {
            int r0 = iw + g;
            int p0r = (jb * 8 + tg) * HST;
            int p1r = (jb * 8 + 4 + tg) * HST;
            uint32_t a0 = PH[p0r + r0];
            uint32_t a1 = PH[p0r + r0 + 8];
            uint32_t a2 = PH[p1r + r0];
            uint32_t a3 = PH[p1r + r0 + 8];
            #pragma unroll
            for (int nt = 0; nt < 8; nt++) {
                uint32_t b0 = VH[p0r + nt * 8 + g];
                uint32_t b1 = VH[p1r + nt * 8 + g];
                mma_f16(o[nt][0], o[nt][1], o[nt][2], o[nt][3],
                        a0, a1, a2, a3, b0, b1);
            }
        }
        __syncthreads();
        if (ti + 1 < T) load_v((ti + 1) * 64);
    }

    /* ---- epilogue: normalize, tf32-round, transpose, pack half2 ---- */
    __syncthreads();
    {
        float inv0 = 1.f / l_s[0], inv1 = 1.f / l_s[1];
        int r0 = iw + g;
        #pragma unroll
        for (int nt = 0; nt < 8; nt++) {
            int d0 = nt * 8 + 2 * tg;
            sm4[d0 * 68 + r0]           = f2tf(o[nt][0] * inv0);
            sm4[(d0 + 1) * 68 + r0]     = f2tf(o[nt][1] * inv0);
            sm4[d0 * 68 + r0 + 8]       = f2tf(o[nt][2] * inv1);
            sm4[(d0 + 1) * 68 + r0 + 8] = f2tf(o[nt][3] * inv1);
        }
    }
    __syncthreads();
    /* write ao_h[b][kp = h*32+dp][n] : word = half2(o[2dp][n], o[2dp+1][n]) */
    uint32_t* aop = aoh + ((long)b * 256 + (long)h * 32) * NPOS + i0;
    #pragma unroll
    for (int ss = 0; ss < 4; ss++) {
        int lin = ss * 128 + t;                    /* 512 items */
        int dp = lin >> 4, i4 = (lin & 15) << 2;
        uint4 wv;
        wv.x = pk_h2(__uint_as_float(sm4[(2 * dp) * 68 + i4 + 0]),
                     __uint_as_float(sm4[(2 * dp + 1) * 68 + i4 + 0]));
        wv.y = pk_h2(__uint_as_float(sm4[(2 * dp) * 68 + i4 + 1]),
                     __uint_as_float(sm4[(2 * dp + 1) * 68 + i4 + 1]));
        wv.z = pk_h2(__uint_as_float(sm4[(2 * dp) * 68 + i4 + 2]),
                     __uint_as_float(sm4[(2 * dp + 1) * 68 + i4 + 2]));
        wv.w = pk_h2(__uint_as_float(sm4[(2 * dp) * 68 + i4 + 3]),
                     __uint_as_float(sm4[(2 * dp + 1) * 68 + i4 + 3]));
        *(uint4*)(aop + (long)dp * NPOS + i4) = wv;
    }
}

/* ===================================================================== */
extern "C" void kernel_launch(void* const* d_in, const int* in_sizes, int n_in,
                              void* d_out, int out_size) {
    const float* x    = (const float*)d_in[0];
    const float* g    = (const float*)d_in[1];
    const float* Wqkv = (const float*)d_in[2];
    const float* Wout = (const float*)d_in[3];
    const float* bout = (const float*)d_in[4];
    float* out = (float*)d_out;

    float *qkv;
    uint32_t *xnh, *aoh, *wqh, *woh, *qpk, *kpk, *vpk;
    cudaGetSymbolAddress((void**)&qkv, g_qkv);
    cudaGetSymbolAddress((void**)&xnh, g_xnh);
    cudaGetSymbolAddress((void**)&aoh, g_aoh);
    cudaGetSymbolAddress((void**)&wqh, g_wqh);
    cudaGetSymbolAddress((void**)&woh, g_woh);
    cudaGetSymbolAddress((void**)&qpk, g_qpk);
    cudaGetSymbolAddress((void**)&kpk, g_kpk);
    cudaGetSymbolAddress((void**)&vpk, g_vpk);

    /* 0. one-time weight prepack (tf32-round -> half2 [kp][M]) */
    pack_w<<<(QKV_ROWS * 256) / 256, 256>>>(Wqkv, wqh, QKV_ROWS, CDIM);
    pack_w<<<(CDIM * 256) / 256, 256>>>(Wout, woh, CDIM, HIDDEN);

    /* 1. LayerNorm -> packed half2 */
    ln_kernel<<<(BATCH * NPOS) / 64, 512>>>(x, g, xnh);

    /* 2. QKV projection (fp16 MMA, fp32 accum, tf32-rounded out) */
    cudaFuncSetAttribute(gemm_f16,
                         cudaFuncAttributeMaxDynamicSharedMemorySize,
                         GEMM16_SMEM);
    gemm_f16<<<dim3(QKV_ROWS / 128, NPOS / 128, BATCH), 256, GEMM16_SMEM>>>(
        wqh, xnh, qkv, nullptr, QKV_ROWS, CDIM, 1);

    /* 2b. repack q/k/v into attention layouts */
    repack_qk<<<dim3(64, 64, 2), 256>>>(qkv, qpk, kpk);
    repack_v<<<dim3(32, 64), 256>>>(qkv, vpk);

    /* 3. fused fp16 attention -> packed half2 ao */
    size_t smem = ATTN_SMEM_WORDS * sizeof(uint32_t);   /* 36864 B */
    cudaFuncSetAttribute(attn_f16,
                         cudaFuncAttributeMaxDynamicSharedMemorySize, (int)smem);
    attn_f16<<<dim3(NPOS / 64, BATCH * HEADS), 128, smem>>>(qpk, kpk, vpk, aoh);

    /* 4. output projection + bias (fp16 MMA, fp32 out) */
    gemm_f16<<<dim3(HIDDEN / 128, NPOS / 128, BATCH), 256, GEMM16_SMEM>>>(
        woh, aoh, out, bout, HIDDEN, CDIM, 0);
}

// round 14
// speedup vs baseline: 7.3907x; 1.0656x over previous
#include <cuda_runtime.h>
#include <cuda_fp16.h>
#include <cstdint>

#define BATCH    8
#define CDIM     512
#define NPOS     2048
#define HEADS    8
#define DIM_HEAD 64
#define HIDDEN   512
#define QKV_ROWS 1536
#define EPS_LN   1e-5f

/* ---------------- scratch (static device globals) ---------------- */
__device__ uint32_t g_xnh[BATCH * 256 * NPOS];       /* LN out half2 [b][cp][n]     */
__device__ uint32_t g_aoh[BATCH * 256 * NPOS];       /* attn out half2 [b][kp][n]   */
__device__ uint32_t g_wqh[256 * QKV_ROWS];           /* W_qkv half2 [kp][M]         */
__device__ uint32_t g_woh[256 * CDIM];               /* W_out half2 [kp][M]         */
__device__ uint32_t g_qpk[64 * 32 * 2048];           /* Q half2 d-pairs [bh][dp][n] */
__device__ uint32_t g_kpk[64 * 32 * 2048];           /* K half2 d-pairs [bh][dp][n] */
__device__ uint32_t g_vpk[64 * 1024 * 64];           /* V half2 j-pairs [bh][jp][d] */

/* ---------------- helpers ---------------- */
__device__ __forceinline__ uint32_t f2tf(float f) {
    uint32_t u;
    asm("cvt.rna.tf32.f32 %0, %1;" : "=r"(u) : "f"(f));
    return u;
}
__device__ __forceinline__ float tfr(float f) { return __uint_as_float(f2tf(f)); }
__device__ __forceinline__ uint32_t pk_h2(float lo, float hi) {
    __half2 h = __floats2half2_rn(lo, hi);
    return *(uint32_t*)&h;
}
__device__ __forceinline__ void mma_f16(float& c0, float& c1, float& c2, float& c3,
                                        uint32_t a0, uint32_t a1, uint32_t a2, uint32_t a3,
                                        uint32_t b0, uint32_t b1) {
    asm("mma.sync.aligned.m16n8k16.row.col.f32.f16.f16.f32 "
        "{%0,%1,%2,%3},{%4,%5,%6,%7},{%8,%9},{%0,%1,%2,%3};"
        : "+f"(c0), "+f"(c1), "+f"(c2), "+f"(c3)
        : "r"(a0), "r"(a1), "r"(a2), "r"(a3), "r"(b0), "r"(b1));
}
__device__ __forceinline__ void cpasync16(uint32_t dst, const void* src) {
    asm volatile("cp.async.cg.shared.global [%0], [%1], 16;" :: "r"(dst), "l"(src));
}
#define CP_COMMIT() asm volatile("cp.async.commit_group;")
#define CP_WAIT(n)  asm volatile("cp.async.wait_group %0;" :: "n"(n))

/* =====================================================================
 * Kernel 0: one-time weight prepack (tf32-round -> half2 [kp][M])
 * ===================================================================== */
__global__ void pack_w(const float* __restrict__ src, uint32_t* __restrict__ dst,
                       int M, int K) {
    int lin = blockIdx.x * 256 + threadIdx.x;
    int kp = lin % (K >> 1);
    int m  = lin / (K >> 1);
    float a = tfr(src[(long)m * K + 2 * kp]);
    float b = tfr(src[(long)m * K + 2 * kp + 1]);
    dst[(long)kp * M + m] = pk_h2(a, b);
}

/* =====================================================================
 * Kernel 1: channel LayerNorm -> packed half2 [b][cp][n]  (R13 verbatim)
 * ===================================================================== */
__global__ void __launch_bounds__(512)
ln_kernel(const float* __restrict__ x,
          const float* __restrict__ g,
          uint32_t* __restrict__ xnh) {
    __shared__ float gs[CDIM];
    __shared__ float red[2][8][64];
    int t = threadIdx.x;
    if (t < CDIM) gs[t] = g[t];

    int nl = t & 63;
    int cs = t >> 6;
    int pos0 = blockIdx.x * 64;
    int b  = pos0 / NPOS;
    int n0 = pos0 % NPOS;

    const float* xp = x + (long)b * CDIM * NPOS + n0 + nl;
    float s = 0.f, ss = 0.f;
    #pragma unroll 8
    for (int c = cs * 64; c < cs * 64 + 64; c++) {
        float v = xp[(long)c * NPOS];
        s += v; ss += v * v;
    }
    red[0][cs][nl] = s;  red[1][cs][nl] = ss;
    __syncthreads();
    float st = 0.f, sst = 0.f;
    #pragma unroll
    for (int k = 0; k < 8; k++) { st += red[0][k][nl]; sst += red[1][k][nl]; }
    float mean = st * (1.f / CDIM);
    float inv  = rsqrtf(sst * (1.f / CDIM) - mean * mean + EPS_LN);

    uint32_t* op = xnh + (long)b * 256 * NPOS + n0 + nl;
    #pragma unroll 8
    for (int c = cs * 64; c < cs * 64 + 64; c += 2) {
        float v0 = tfr((xp[(long)(c + 0) * NPOS] - mean) * inv * gs[c + 0]);
        float v1 = tfr((xp[(long)(c + 1) * NPOS] - mean) * inv * gs[c + 1]);
        op[(long)(c >> 1) * NPOS] = pk_h2(v0, v1);
    }
}

/* =====================================================================
 * FP16 GEMM mainloop bits shared by both GEMM kernels (R13 proven):
 * tile 128m x 128n x 32k, 3-stage cp.async, tail CP_WAIT(0).
 * ===================================================================== */
#define FASTG (16 * 136)
#define GEMM16_SMEM (3 * 2 * FASTG * 4)

#define GEMM_MAINLOOP(ACC)                                                      \
    const int NIT = K / 32;                                                     \
    auto load_stage = [&](int buf, int kp0) {                                   \
        _Pragma("unroll")                                                       \
        for (int ss = 0; ss < 2; ss++) {                                        \
            int c = ss * 256 + t;                                               \
            int row = c >> 5, cw = (c & 31) << 2;                               \
            cpasync16(sbase + (buf * FASTG + row * 136 + cw) * 4,               \
                      Ab + (long)(kp0 + row) * M + cw);                         \
        }                                                                       \
        _Pragma("unroll")                                                       \
        for (int ss = 0; ss < 2; ss++) {                                        \
            int c = ss * 256 + t;                                               \
            int row = c >> 5, cw = (c & 31) << 2;                               \
            cpasync16(sbase + ((3 + buf) * FASTG + row * 136 + cw) * 4,         \
                      Bb + (long)(kp0 + row) * NPOS + cw);                      \
        }                                                                       \
        CP_COMMIT();                                                            \
    };                                                                          \
    load_stage(0, 0);                                                           \
    if (NIT > 1) load_stage(1, 16);                                             \
    for (int it = 0; it < NIT; it++) {                                          \
        if (it + 1 < NIT) { CP_WAIT(1); } else { CP_WAIT(0); }                  \
        __syncthreads();                                                        \
        if (it + 2 < NIT) load_stage((it + 2) % 3, (it + 2) * 16);              \
        const uint32_t* Ab_s = gsm + (it % 3) * FASTG;                          \
        const uint32_t* Bb_s = gsm + (3 + it % 3) * FASTG;                      \
        _Pragma("unroll")                                                       \
        for (int kb = 0; kb < 2; kb++) {                                        \
            int kr0 = (kb * 8 + tg) * 136;                                      \
            int kr1 = (kb * 8 + 4 + tg) * 136;                                  \
            uint32_t af[4][4];                                                  \
            _Pragma("unroll")                                                   \
            for (int mt = 0; mt < 4; mt++) {                                    \
                int r = wm + mt * 16 + g;                                       \
                af[mt][0] = Ab_s[kr0 + r];                                      \
                af[mt][1] = Ab_s[kr0 + r + 8];                                  \
                af[mt][2] = Ab_s[kr1 + r];                                      \
                af[mt][3] = Ab_s[kr1 + r + 8];                                  \
            }                                                                   \
            uint32_t bf[4][2];                                                  \
            _Pragma("unroll")                                                   \
            for (int nt = 0; nt < 4; nt++) {                                    \
                int c = wn + nt * 8 + g;                                        \
                bf[nt][0] = Bb_s[kr0 + c];                                      \
                bf[nt][1] = Bb_s[kr1 + c];                                      \
            }                                                                   \
            _Pragma("unroll")                                                   \
            for (int mt = 0; mt < 4; mt++)                                      \
                _Pragma("unroll")                                               \
                for (int nt = 0; nt < 4; nt++)                                  \
                    mma_f16(ACC[mt][nt][0], ACC[mt][nt][1],                     \
                            ACC[mt][nt][2], ACC[mt][nt][3],                     \
                            af[mt][0], af[mt][1], af[mt][2], af[mt][3],         \
                            bf[nt][0], bf[nt][1]);                              \
        }                                                                       \
    }

/* =====================================================================
 * Kernel 2: QKV projection with FUSED PACK EPILOGUE.
 * Writes qpk/kpk (d-pair half2 via lane^4 shfl) and vpk (n-pair half2,
 * transposed) directly. Value chain per element is bitwise R13:
 * tfr(acc) -> exact x0.125 (Q only) -> half convert.
 * ===================================================================== */
__global__ void __launch_bounds__(256, 2)
gemm_qkv(const uint32_t* __restrict__ Ah, const uint32_t* __restrict__ Bh,
         uint32_t* __restrict__ qpk, uint32_t* __restrict__ kpk,
         uint32_t* __restrict__ vpk, int M, int K) {
    extern __shared__ uint32_t gsm[];
    int t = threadIdx.x, lane = t & 31, w = t >> 5;
    int m0 = blockIdx.x * 128, n0 = blockIdx.y * 128, b = blockIdx.z;
    const uint32_t* Ab = Ah + m0;
    const uint32_t* Bb = Bh + (long)b * (K >> 1) * NPOS + n0;
    uint32_t sbase = (uint32_t)__cvta_generic_to_shared(gsm);

    int wm = (w >> 2) * 64;
    int wn = (w & 3) * 32;
    int g  = lane >> 2, tg = lane & 3;

    float acc[4][4][4];
    #pragma unroll
    for (int i = 0; i < 4; i++)
        #pragma unroll
        for (int j = 0; j < 4; j++)
            #pragma unroll
            for (int r = 0; r < 4; r++) acc[i][j][r] = 0.f;

    GEMM_MAINLOOP(acc)

    /* ---- fused pack epilogue ---- */
    int part = m0 >> 9;                      /* 0=Q 1=K 2=V (blocks never straddle) */
    float qs = (part == 0) ? 0.125f : 1.0f;
    bool evg = (g & 1) == 0;

    #pragma unroll
    for (int mt = 0; mt < 4; mt++) {
        int row0 = m0 + wm + mt * 16 + g;
        int h  = (row0 & 511) >> 6;
        int bh = b * 8 + h;
        #pragma unroll
        for (int nt = 0; nt < 4; nt++) {
            int c0 = n0 + wn + nt * 8 + 2 * tg;
            float v0 = tfr(acc[mt][nt][0]) * qs;
            float v1 = tfr(acc[mt][nt][1]) * qs;
            float v2 = tfr(acc[mt][nt][2]) * qs;
            float v3 = tfr(acc[mt][nt][3]) * qs;
            if (part < 2) {
                /* Q/K: pair adjacent m rows via lane^4 exchange */
                float p0 = __shfl_xor_sync(0xffffffffu, v0, 4);
                float p1 = __shfl_xor_sync(0xffffffffu, v1, 4);
                float p2 = __shfl_xor_sync(0xffffffffu, v2, 4);
                float p3 = __shfl_xor_sync(0xffffffffu, v3, 4);
                if (evg) {
                    int dp = (row0 & 63) >> 1;
                    uint32_t* dst = (part == 0 ? qpk : kpk)
                                  + ((long)bh * 32 + dp) * 2048 + c0;
                    *(uint2*)dst = make_uint2(pk_h2(v0, p0), pk_h2(v1, p1));
                    *(uint2*)(dst + 4 * 2048) = make_uint2(pk_h2(v2, p2), pk_h2(v3, p3));
                }
            } else {
                /* V: pair adjacent n cols in-thread, transposed store */
                int d0 = row0 & 63;
                int jp = c0 >> 1;
                uint32_t* dst = vpk + ((long)bh * 1024 + jp) * 64 + d0;
                dst[0] = pk_h2(v0, v1);
                dst[8] = pk_h2(v2, v3);
            }
        }
    }
}

/* =====================================================================
 * Kernel 4: output projection (R13 gemm_f16 verbatim, fp32 out + bias)
 * ===================================================================== */
__global__ void __launch_bounds__(256, 2)
gemm_f16(const uint32_t* __restrict__ Ah, const uint32_t* __restrict__ Bh,
         float* __restrict__ C, const float* __restrict__ bias,
         int M, int K) {
    extern __shared__ uint32_t gsm[];
    int t = threadIdx.x, lane = t & 31, w = t >> 5;
    int m0 = blockIdx.x * 128, n0 = blockIdx.y * 128, b = blockIdx.z;
    const uint32_t* Ab = Ah + m0;
    const uint32_t* Bb = Bh + (long)b * (K >> 1) * NPOS + n0;
    float*           Cb = C  + (long)b * M * NPOS;
    uint32_t sbase = (uint32_t)__cvta_generic_to_shared(gsm);

    int wm = (w >> 2) * 64;
    int wn = (w & 3) * 32;
    int g  = lane >> 2, tg = lane & 3;

    float acc[4][4][4];
    #pragma unroll
    for (int i = 0; i < 4; i++)
        #pragma unroll
        for (int j = 0; j < 4; j++)
            #pragma unroll
            for (int r = 0; r < 4; r++) acc[i][j][r] = 0.f;

    GEMM_MAINLOOP(acc)

    #pragma unroll
    for (int mt = 0; mt < 4; mt++) {
        int r0 = m0 + wm + mt * 16 + g;
        float b0 = bias ? bias[r0]     : 0.f;
        float b1 = bias ? bias[r0 + 8] : 0.f;
        #pragma unroll
        for (int nt = 0; nt < 4; nt++) {
            int c0 = n0 + wn + nt * 8 + 2 * tg;
            *(float2*)(Cb + (long)r0 * NPOS + c0) =
                make_float2(acc[mt][nt][0] + b0, acc[mt][nt][1] + b0);
            *(float2*)(Cb + (long)(r0 + 8) * NPOS + c0) =
                make_float2(acc[mt][nt][2] + b1, acc[mt][nt][3] + b1);
        }
    }
}

/* =====================================================================
 * Kernel 3: fused FP16 flash attention (R13 verbatim)
 * ===================================================================== */
#define HST 72
#define QH_OFF 0
#define KH_OFF 2304
#define VH_OFF 4608
#define PH_OFF 6912
#define ATTN_SMEM_WORDS 9216

__global__ void __launch_bounds__(128, 4)
attn_f16(const uint32_t* __restrict__ qpk, const uint32_t* __restrict__ kpk,
         const uint32_t* __restrict__ vpk, uint32_t* __restrict__ aoh) {
    extern __shared__ uint32_t sm4[];
    uint32_t* QH = sm4 + QH_OFF;
    uint32_t* KH = sm4 + KH_OFF;
    uint32_t* VH = sm4 + VH_OFF;
    uint32_t* PH = sm4 + PH_OFF;
    uint32_t sbase = (uint32_t)__cvta_generic_to_shared(sm4);

    int t = threadIdx.x, lane = t & 31, w = t >> 5;
    int g = lane >> 2, tg = lane & 3;
    int iw = w * 16;

    int qt = blockIdx.x;
    int bh = blockIdx.y;
    int b  = bh >> 3, h = bh & 7;
    int i0 = qt * 64;

    const uint32_t* qb = qpk + (long)bh * 32 * 2048;
    const uint32_t* kb = kpk + (long)bh * 32 * 2048;
    const uint32_t* vb = vpk + (long)bh * 1024 * 64;

    auto load_k = [&](int j0) {
        #pragma unroll
        for (int ss = 0; ss < 4; ss++) {
            int c = ss * 128 + t;
            int dp = c >> 4, cw = (c & 15) << 2;
            cpasync16(sbase + (KH_OFF + dp * HST + cw) * 4,
                      kb + (long)dp * 2048 + j0 + cw);
        }
        CP_COMMIT();
    };
    auto load_v = [&](int j0) {
        #pragma unroll
        for (int ss = 0; ss < 4; ss++) {
            int c = ss * 128 + t;
            int jp = c >> 4, cw = (c & 15) << 2;
            cpasync16(sbase + (VH_OFF + jp * HST + cw) * 4,
                      vb + ((long)(j0 >> 1) + jp) * 64 + cw);
        }
        CP_COMMIT();
    };

    load_k(0);
    load_v(0);

    #pragma unroll
    for (int ss = 0; ss < 4; ss++) {
        int c = ss * 128 + t;
        int dp = c >> 4, cw = (c & 15) << 2;
        uint4 v = *(const uint4*)(qb + (long)dp * 2048 + i0 + cw);
        *(uint4*)&QH[dp * HST + cw] = v;
    }

    float m_s[2], l_s[2];
    float o[8][4];
    m_s[0] = m_s[1] = -1e30f;
    l_s[0] = l_s[1] = 0.f;
    #pragma unroll
    for (int nt = 0; nt < 8; nt++)
        #pragma unroll
        for (int r = 0; r < 4; r++) o[nt][r] = 0.f;

    const int T = NPOS / 64;
    for (int ti = 0; ti < T; ti++) {
        CP_WAIT(1);
        __syncthreads();

        float sa[8][4];
        #pragma unroll
        for (int nt = 0; nt < 8; nt++)
            #pragma unroll
            for (int r = 0; r < 4; r++) sa[nt][r] = 0.f;

        #pragma unroll
        for (int kbk = 0; kbk < 4; kbk++) {
            int r0 = iw + g;
            int q0 = (kbk * 8 + tg) * HST;
            int q1 = (kbk * 8 + 4 + tg) * HST;
            uint32_t a0 = QH[q0 + r0];
            uint32_t a1 = QH[q0 + r0 + 8];
            uint32_t a2 = QH[q1 + r0];
            uint32_t a3 = QH[q1 + r0 + 8];
            #pragma unroll
            for (int nt = 0; nt < 8; nt++) {
                uint32_t b0 = KH[q0 + nt * 8 + g];
                uint32_t b1 = KH[q1 + nt * 8 + g];
                mma_f16(sa[nt][0], sa[nt][1], sa[nt][2], sa[nt][3],
                        a0, a1, a2, a3, b0, b1);
            }
        }
        __syncthreads();
        if (ti + 1 < T) load_k((ti + 1) * 64);

        {
            float mx0 = -1e30f, mx1 = -1e30f;
            #pragma unroll
            for (int nt = 0; nt < 8; nt++) {
                mx0 = fmaxf(mx0, fmaxf(sa[nt][0], sa[nt][1]));
                mx1 = fmaxf(mx1, fmaxf(sa[nt][2], sa[nt][3]));
            }
            mx0 = fmaxf(mx0, __shfl_xor_sync(0xffffffffu, mx0, 1));
            mx0 = fmaxf(mx0, __shfl_xor_sync(0xffffffffu, mx0, 2));
            mx1 = fmaxf(mx1, __shfl_xor_sync(0xffffffffu, mx1, 1));
            mx1 = fmaxf(mx1, __shfl_xor_sync(0xffffffffu, mx1, 2));
            float mn0 = fmaxf(m_s[0], mx0);
            float mn1 = fmaxf(m_s[1], mx1);
            float s0 = 0.f, s1 = 0.f;
            int r0 = iw + g;
            #pragma unroll
            for (int nt = 0; nt < 8; nt++) {
                float p0 = __expf(sa[nt][0] - mn0);
                float p1 = __expf(sa[nt][1] - mn0);
                float p2 = __expf(sa[nt][2] - mn1);
                float p3 = __expf(sa[nt][3] - mn1);
                s0 += p0 + p1;  s1 += p2 + p3;
                int jp = nt * 4 + tg;
                PH[jp * HST + r0]     = pk_h2(p0, p1);
                PH[jp * HST + r0 + 8] = pk_h2(p2, p3);
            }
            s0 += __shfl_xor_sync(0xffffffffu, s0, 1);
            s0 += __shfl_xor_sync(0xffffffffu, s0, 2);
            s1 += __shfl_xor_sync(0xffffffffu, s1, 1);
            s1 += __shfl_xor_sync(0xffffffffu, s1, 2);
            float al0 = __expf(m_s[0] - mn0);
            float al1 = __expf(m_s[1] - mn1);
            l_s[0] = l_s[0] * al0 + s0;  m_s[0] = mn0;
            l_s[1] = l_s[1] * al1 + s1;  m_s[1] = mn1;
            #pragma unroll
            for (int nt = 0; nt < 8; nt++) {
                o[nt][0] *= al0; o[nt][1] *= al0;
                o[nt][2] *= al1; o[nt][3] *= al1;
            }
        }
        __syncwarp();

        if (ti + 1 < T) { CP_WAIT(1); } else { CP_WAIT(0); }
        __syncthreads();

        #pragma unroll
        for (int jb = 0; jb < 4; jb++) {
            int r0 = iw + g;
            int p0r = (jb * 8 + tg) * HST;
            int p1r = (jb * 8 + 4 + tg) * HST;
            uint32_t a0 = PH[p0r + r0];
            uint32_t a1 = PH[p0r + r0 + 8];
            uint32_t a2 = PH[p1r + r0];
            uint32_t a3 = PH[p1r + r0 + 8];
            #pragma unroll
            for (int nt = 0; nt < 8; nt++) {
                uint32_t b0 = VH[p0r + nt * 8 + g];
                uint32_t b1 = VH[p1r + nt * 8 + g];
                mma_f16(o[nt][0], o[nt][1], o[nt][2], o[nt][3],
                        a0, a1, a2, a3, b0, b1);
            }
        }
        __syncthreads();
        if (ti + 1 < T) load_v((ti + 1) * 64);
    }

    /* ---- epilogue: normalize, tf32-round, transpose, pack half2 ---- */
    __syncthreads();
    {
        float inv0 = 1.f / l_s[0], inv1 = 1.f / l_s[1];
        int r0 = iw + g;
        #pragma unroll
        for (int nt = 0; nt < 8; nt++) {
            int d0 = nt * 8 + 2 * tg;
            sm4[d0 * 68 + r0]           = f2tf(o[nt][0] * inv0);
            sm4[(d0 + 1) * 68 + r0]     = f2tf(o[nt][1] * inv0);
            sm4[d0 * 68 + r0 + 8]       = f2tf(o[nt][2] * inv1);
            sm4[(d0 + 1) * 68 + r0 + 8] = f2tf(o[nt][3] * inv1);
        }
    }
    __syncthreads();
    uint32_t* aop = aoh + ((long)b * 256 + (long)h * 32) * NPOS + i0;
    #pragma unroll
    for (int ss = 0; ss < 4; ss++) {
        int lin = ss * 128 + t;
        int dp = lin >> 4, i4 = (lin & 15) << 2;
        uint4 wv;
        wv.x = pk_h2(__uint_as_float(sm4[(2 * dp) * 68 + i4 + 0]),
                     __uint_as_float(sm4[(2 * dp + 1) * 68 + i4 + 0]));
        wv.y = pk_h2(__uint_as_float(sm4[(2 * dp) * 68 + i4 + 1]),
                     __uint_as_float(sm4[(2 * dp + 1) * 68 + i4 + 1]));
        wv.z = pk_h2(__uint_as_float(sm4[(2 * dp) * 68 + i4 + 2]),
                     __uint_as_float(sm4[(2 * dp + 1) * 68 + i4 + 2]));
        wv.w = pk_h2(__uint_as_float(sm4[(2 * dp) * 68 + i4 + 3]),
                     __uint_as_float(sm4[(2 * dp + 1) * 68 + i4 + 3]));
        *(uint4*)(aop + (long)dp * NPOS + i4) = wv;
    }
}

/* ===================================================================== */
extern "C" void kernel_launch(void* const* d_in, const int* in_sizes, int n_in,
                              void* d_out, int out_size) {
    const float* x    = (const float*)d_in[0];
    const float* g    = (const float*)d_in[1];
    const float* Wqkv = (const float*)d_in[2];
    const float* Wout = (const float*)d_in[3];
    const float* bout = (const float*)d_in[4];
    float* out = (float*)d_out;

    uint32_t *xnh, *aoh, *wqh, *woh, *qpk, *kpk, *vpk;
    cudaGetSymbolAddress((void**)&xnh, g_xnh);
    cudaGetSymbolAddress((void**)&aoh, g_aoh);
    cudaGetSymbolAddress((void**)&wqh, g_wqh);
    cudaGetSymbolAddress((void**)&woh, g_woh);
    cudaGetSymbolAddress((void**)&qpk, g_qpk);
    cudaGetSymbolAddress((void**)&kpk, g_kpk);
    cudaGetSymbolAddress((void**)&vpk, g_vpk);

    /* 0. one-time weight prepack */
    pack_w<<<(QKV_ROWS * 256) / 256, 256>>>(Wqkv, wqh, QKV_ROWS, CDIM);
    pack_w<<<(CDIM * 256) / 256, 256>>>(Wout, woh, CDIM, HIDDEN);

    /* 1. LayerNorm -> packed half2 */
    ln_kernel<<<(BATCH * NPOS) / 64, 512>>>(x, g, xnh);

    /* 2. QKV projection with fused pack epilogue */
    cudaFuncSetAttribute(gemm_qkv,
                         cudaFuncAttributeMaxDynamicSharedMemorySize, GEMM16_SMEM);
    gemm_qkv<<<dim3(QKV_ROWS / 128, NPOS / 128, BATCH), 256, GEMM16_SMEM>>>(
        wqh, xnh, qpk, kpk, vpk, QKV_ROWS, CDIM);

    /* 3. fused fp16 attention -> packed half2 ao */
    size_t smem = ATTN_SMEM_WORDS * sizeof(uint32_t);   /* 36864 B */
    cudaFuncSetAttribute(attn_f16,
                         cudaFuncAttributeMaxDynamicSharedMemorySize, (int)smem);
    attn_f16<<<dim3(NPOS / 64, BATCH * HEADS), 128, smem>>>(qpk, kpk, vpk, aoh);

    /* 4. output projection + bias (fp32 out) */
    cudaFuncSetAttribute(gemm_f16,
                         cudaFuncAttributeMaxDynamicSharedMemorySize, GEMM16_SMEM);
    gemm_f16<<<dim3(HIDDEN / 128, NPOS / 128, BATCH), 256, GEMM16_SMEM>>>(
        woh, aoh, out, bout, HIDDEN, CDIM);
}

// round 15
// speedup vs baseline: 7.6055x; 1.0291x over previous
#include <cuda_runtime.h>
#include <cuda_fp16.h>
#include <cstdint>

#define BATCH    8
#define CDIM     512
#define NPOS     2048
#define HEADS    8
#define DIM_HEAD 64
#define HIDDEN   512
#define QKV_ROWS 1536
#define EPS_LN   1e-5f

/* ---------------- scratch (static device globals) ---------------- */
__device__ uint32_t g_xnh[BATCH * 256 * NPOS];       /* LN out half2 [b][cp][n]     */
__device__ uint32_t g_aoh[BATCH * 256 * NPOS];       /* attn out half2 [b][kp][n]   */
__device__ uint32_t g_wqh[256 * QKV_ROWS];           /* W_qkv half2 [kp][M]         */
__device__ uint32_t g_woh[256 * CDIM];               /* W_out half2 [kp][M]         */
__device__ uint32_t g_qpk[64 * 32 * 2048];           /* Q half2 d-pairs [bh][dp][n] */
__device__ uint32_t g_kpk[64 * 32 * 2048];           /* K half2 d-pairs [bh][dp][n] */
__device__ uint32_t g_vpk[64 * 1024 * 64];           /* V half2 j-pairs [bh][jp][d] */

/* ---------------- helpers ---------------- */
__device__ __forceinline__ uint32_t f2tf(float f) {
    uint32_t u;
    asm("cvt.rna.tf32.f32 %0, %1;" : "=r"(u) : "f"(f));
    return u;
}
__device__ __forceinline__ float tfr(float f) { return __uint_as_float(f2tf(f)); }
__device__ __forceinline__ uint32_t pk_h2(float lo, float hi) {
    __half2 h = __floats2half2_rn(lo, hi);
    return *(uint32_t*)&h;
}
__device__ __forceinline__ void mma_f16(float& c0, float& c1, float& c2, float& c3,
                                        uint32_t a0, uint32_t a1, uint32_t a2, uint32_t a3,
                                        uint32_t b0, uint32_t b1) {
    asm("mma.sync.aligned.m16n8k16.row.col.f32.f16.f16.f32 "
        "{%0,%1,%2,%3},{%4,%5,%6,%7},{%8,%9},{%0,%1,%2,%3};"
        : "+f"(c0), "+f"(c1), "+f"(c2), "+f"(c3)
        : "r"(a0), "r"(a1), "r"(a2), "r"(a3), "r"(b0), "r"(b1));
}
__device__ __forceinline__ void cpasync16(uint32_t dst, const void* src) {
    asm volatile("cp.async.cg.shared.global [%0], [%1], 16;" :: "r"(dst), "l"(src));
}
#define CP_COMMIT() asm volatile("cp.async.commit_group;")
#define CP_WAIT(n)  asm volatile("cp.async.wait_group %0;" :: "n"(n))

/* =====================================================================
 * Kernel 0: one-time weight prepack (tf32-round -> half2 [kp][M])
 * ===================================================================== */
__global__ void pack_w(const float* __restrict__ src, uint32_t* __restrict__ dst,
                       int M, int K) {
    int lin = blockIdx.x * 256 + threadIdx.x;
    int kp = lin % (K >> 1);
    int m  = lin / (K >> 1);
    float a = tfr(src[(long)m * K + 2 * kp]);
    float b = tfr(src[(long)m * K + 2 * kp + 1]);
    dst[(long)kp * M + m] = pk_h2(a, b);
}

/* =====================================================================
 * Kernel 1: channel LayerNorm -> packed half2 [b][cp][n]  (verbatim)
 * ===================================================================== */
__global__ void __launch_bounds__(512)
ln_kernel(const float* __restrict__ x,
          const float* __restrict__ g,
          uint32_t* __restrict__ xnh) {
    __shared__ float gs[CDIM];
    __shared__ float red[2][8][64];
    int t = threadIdx.x;
    if (t < CDIM) gs[t] = g[t];

    int nl = t & 63;
    int cs = t >> 6;
    int pos0 = blockIdx.x * 64;
    int b  = pos0 / NPOS;
    int n0 = pos0 % NPOS;

    const float* xp = x + (long)b * CDIM * NPOS + n0 + nl;
    float s = 0.f, ss = 0.f;
    #pragma unroll 8
    for (int c = cs * 64; c < cs * 64 + 64; c++) {
        float v = xp[(long)c * NPOS];
        s += v; ss += v * v;
    }
    red[0][cs][nl] = s;  red[1][cs][nl] = ss;
    __syncthreads();
    float st = 0.f, sst = 0.f;
    #pragma unroll
    for (int k = 0; k < 8; k++) { st += red[0][k][nl]; sst += red[1][k][nl]; }
    float mean = st * (1.f / CDIM);
    float inv  = rsqrtf(sst * (1.f / CDIM) - mean * mean + EPS_LN);

    uint32_t* op = xnh + (long)b * 256 * NPOS + n0 + nl;
    #pragma unroll 8
    for (int c = cs * 64; c < cs * 64 + 64; c += 2) {
        float v0 = tfr((xp[(long)(c + 0) * NPOS] - mean) * inv * gs[c + 0]);
        float v1 = tfr((xp[(long)(c + 1) * NPOS] - mean) * inv * gs[c + 1]);
        op[(long)(c >> 1) * NPOS] = pk_h2(v0, v1);
    }
}

/* =====================================================================
 * FP16 GEMM mainloop (R13/14 proven)
 * ===================================================================== */
#define FASTG (16 * 136)
#define GEMM16_SMEM (3 * 2 * FASTG * 4)

#define GEMM_MAINLOOP(ACC)                                                      \
    const int NIT = K / 32;                                                     \
    auto load_stage = [&](int buf, int kp0) {                                   \
        _Pragma("unroll")                                                       \
        for (int ss = 0; ss < 2; ss++) {                                        \
            int c = ss * 256 + t;                                               \
            int row = c >> 5, cw = (c & 31) << 2;                               \
            cpasync16(sbase + (buf * FASTG + row * 136 + cw) * 4,               \
                      Ab + (long)(kp0 + row) * M + cw);                         \
        }                                                                       \
        _Pragma("unroll")                                                       \
        for (int ss = 0; ss < 2; ss++) {                                        \
            int c = ss * 256 + t;                                               \
            int row = c >> 5, cw = (c & 31) << 2;                               \
            cpasync16(sbase + ((3 + buf) * FASTG + row * 136 + cw) * 4,         \
                      Bb + (long)(kp0 + row) * NPOS + cw);                      \
        }                                                                       \
        CP_COMMIT();                                                            \
    };                                                                          \
    load_stage(0, 0);                                                           \
    if (NIT > 1) load_stage(1, 16);                                             \
    for (int it = 0; it < NIT; it++) {                                          \
        if (it + 1 < NIT) { CP_WAIT(1); } else { CP_WAIT(0); }                  \
        __syncthreads();                                                        \
        if (it + 2 < NIT) load_stage((it + 2) % 3, (it + 2) * 16);              \
        const uint32_t* Ab_s = gsm + (it % 3) * FASTG;                          \
        const uint32_t* Bb_s = gsm + (3 + it % 3) * FASTG;                      \
        _Pragma("unroll")                                                       \
        for (int kb = 0; kb < 2; kb++) {                                        \
            int kr0 = (kb * 8 + tg) * 136;                                      \
            int kr1 = (kb * 8 + 4 + tg) * 136;                                  \
            uint32_t af[4][4];                                                  \
            _Pragma("unroll")                                                   \
            for (int mt = 0; mt < 4; mt++) {                                    \
                int r = wm + mt * 16 + g;                                       \
                af[mt][0] = Ab_s[kr0 + r];                                      \
                af[mt][1] = Ab_s[kr0 + r + 8];                                  \
                af[mt][2] = Ab_s[kr1 + r];                                      \
                af[mt][3] = Ab_s[kr1 + r + 8];                                  \
            }                                                                   \
            uint32_t bf[4][2];                                                  \
            _Pragma("unroll")                                                   \
            for (int nt = 0; nt < 4; nt++) {                                    \
                int c = wn + nt * 8 + g;                                        \
                bf[nt][0] = Bb_s[kr0 + c];                                      \
                bf[nt][1] = Bb_s[kr1 + c];                                      \
            }                                                                   \
            _Pragma("unroll")                                                   \
            for (int mt = 0; mt < 4; mt++)                                      \
                _Pragma("unroll")                                               \
                for (int nt = 0; nt < 4; nt++)                                  \
                    mma_f16(ACC[mt][nt][0], ACC[mt][nt][1],                     \
                            ACC[mt][nt][2], ACC[mt][nt][3],                     \
                            af[mt][0], af[mt][1], af[mt][2], af[mt][3],         \
                            bf[nt][0], bf[nt][1]);                              \
        }                                                                       \
    }

/* =====================================================================
 * Kernel 2: QKV projection with fused pack epilogue (R14 verbatim)
 * ===================================================================== */
__global__ void __launch_bounds__(256, 2)
gemm_qkv(const uint32_t* __restrict__ Ah, const uint32_t* __restrict__ Bh,
         uint32_t* __restrict__ qpk, uint32_t* __restrict__ kpk,
         uint32_t* __restrict__ vpk, int M, int K) {
    extern __shared__ uint32_t gsm[];
    int t = threadIdx.x, lane = t & 31, w = t >> 5;
    int m0 = blockIdx.x * 128, n0 = blockIdx.y * 128, b = blockIdx.z;
    const uint32_t* Ab = Ah + m0;
    const uint32_t* Bb = Bh + (long)b * (K >> 1) * NPOS + n0;
    uint32_t sbase = (uint32_t)__cvta_generic_to_shared(gsm);

    int wm = (w >> 2) * 64;
    int wn = (w & 3) * 32;
    int g  = lane >> 2, tg = lane & 3;

    float acc[4][4][4];
    #pragma unroll
    for (int i = 0; i < 4; i++)
        #pragma unroll
        for (int j = 0; j < 4; j++)
            #pragma unroll
            for (int r = 0; r < 4; r++) acc[i][j][r] = 0.f;

    GEMM_MAINLOOP(acc)

    int part = m0 >> 9;
    float qs = (part == 0) ? 0.125f : 1.0f;
    bool evg = (g & 1) == 0;

    #pragma unroll
    for (int mt = 0; mt < 4; mt++) {
        int row0 = m0 + wm + mt * 16 + g;
        int h  = (row0 & 511) >> 6;
        int bh = b * 8 + h;
        #pragma unroll
        for (int nt = 0; nt < 4; nt++) {
            int c0 = n0 + wn + nt * 8 + 2 * tg;
            float v0 = tfr(acc[mt][nt][0]) * qs;
            float v1 = tfr(acc[mt][nt][1]) * qs;
            float v2 = tfr(acc[mt][nt][2]) * qs;
            float v3 = tfr(acc[mt][nt][3]) * qs;
            if (part < 2) {
                float p0 = __shfl_xor_sync(0xffffffffu, v0, 4);
                float p1 = __shfl_xor_sync(0xffffffffu, v1, 4);
                float p2 = __shfl_xor_sync(0xffffffffu, v2, 4);
                float p3 = __shfl_xor_sync(0xffffffffu, v3, 4);
                if (evg) {
                    int dp = (row0 & 63) >> 1;
                    uint32_t* dst = (part == 0 ? qpk : kpk)
                                  + ((long)bh * 32 + dp) * 2048 + c0;
                    *(uint2*)dst = make_uint2(pk_h2(v0, p0), pk_h2(v1, p1));
                    *(uint2*)(dst + 4 * 2048) = make_uint2(pk_h2(v2, p2), pk_h2(v3, p3));
                }
            } else {
                int d0 = row0 & 63;
                int jp = c0 >> 1;
                uint32_t* dst = vpk + ((long)bh * 1024 + jp) * 64 + d0;
                dst[0] = pk_h2(v0, v1);
                dst[8] = pk_h2(v2, v3);
            }
        }
    }
}

/* =====================================================================
 * Kernel 4: output projection (R14 verbatim)
 * ===================================================================== */
__global__ void __launch_bounds__(256, 2)
gemm_f16(const uint32_t* __restrict__ Ah, const uint32_t* __restrict__ Bh,
         float* __restrict__ C, const float* __restrict__ bias,
         int M, int K) {
    extern __shared__ uint32_t gsm[];
    int t = threadIdx.x, lane = t & 31, w = t >> 5;
    int m0 = blockIdx.x * 128, n0 = blockIdx.y * 128, b = blockIdx.z;
    const uint32_t* Ab = Ah + m0;
    const uint32_t* Bb = Bh + (long)b * (K >> 1) * NPOS + n0;
    float*           Cb = C  + (long)b * M * NPOS;
    uint32_t sbase = (uint32_t)__cvta_generic_to_shared(gsm);

    int wm = (w >> 2) * 64;
    int wn = (w & 3) * 32;
    int g  = lane >> 2, tg = lane & 3;

    float acc[4][4][4];
    #pragma unroll
    for (int i = 0; i < 4; i++)
        #pragma unroll
        for (int j = 0; j < 4; j++)
            #pragma unroll
            for (int r = 0; r < 4; r++) acc[i][j][r] = 0.f;

    GEMM_MAINLOOP(acc)

    #pragma unroll
    for (int mt = 0; mt < 4; mt++) {
        int r0 = m0 + wm + mt * 16 + g;
        float b0 = bias ? bias[r0]     : 0.f;
        float b1 = bias ? bias[r0 + 8] : 0.f;
        #pragma unroll
        for (int nt = 0; nt < 4; nt++) {
            int c0 = n0 + wn + nt * 8 + 2 * tg;
            *(float2*)(Cb + (long)r0 * NPOS + c0) =
                make_float2(acc[mt][nt][0] + b0, acc[mt][nt][1] + b0);
            *(float2*)(Cb + (long)(r0 + 8) * NPOS + c0) =
                make_float2(acc[mt][nt][2] + b1, acc[mt][nt][3] + b1);
        }
    }
}

/* =====================================================================
 * Kernel 3: fused FP16 flash attention — restructured:
 *  - Q fragments in 16 registers, gathered directly from gmem (no QH)
 *  - double-buffered K/V, ONE combined cp.async group per tile
 *  - 2 __syncthreads per kv-tile (was 4)
 * smem: KH[2][2304] VH[2][2304] PH[2304] = 11520 words = 46080 B
 *       -> 4 CTAs/SM. Epilogue reuses retired K region as scratch.
 * All MMA operand values / op order identical to R14 -> bitwise output.
 * ===================================================================== */
#define HST 72
#define KH_OFF 0
#define VH_OFF (2 * 2304)
#define PH_OFF (4 * 2304)
#define ATTN_SMEM_WORDS (5 * 2304)      /* 11520 words = 46080 B */

__global__ void __launch_bounds__(128, 4)
attn_f16(const uint32_t* __restrict__ qpk, const uint32_t* __restrict__ kpk,
         const uint32_t* __restrict__ vpk, uint32_t* __restrict__ aoh) {
    extern __shared__ uint32_t sm4[];
    uint32_t* PH = sm4 + PH_OFF;
    uint32_t sbase = (uint32_t)__cvta_generic_to_shared(sm4);

    int t = threadIdx.x, lane = t & 31, w = t >> 5;
    int g = lane >> 2, tg = lane & 3;
    int iw = w * 16;

    int qt = blockIdx.x;
    int bh = blockIdx.y;
    int b  = bh >> 3, h = bh & 7;
    int i0 = qt * 64;

    const uint32_t* qb = qpk + (long)bh * 32 * 2048;
    const uint32_t* kb = kpk + (long)bh * 32 * 2048;
    const uint32_t* vb = vpk + (long)bh * 1024 * 64;

    /* combined K+V tile load into buffer p (one commit group) */
    auto load_kv = [&](int j0, int p) {
        #pragma unroll
        for (int ss = 0; ss < 4; ss++) {
            int c = ss * 128 + t;
            int dp = c >> 4, cw = (c & 15) << 2;
            cpasync16(sbase + (KH_OFF + p * 2304 + dp * HST + cw) * 4,
                      kb + (long)dp * 2048 + j0 + cw);
        }
        #pragma unroll
        for (int ss = 0; ss < 4; ss++) {
            int c = ss * 128 + t;
            int jp = c >> 4, cw = (c & 15) << 2;
            cpasync16(sbase + (VH_OFF + p * 2304 + jp * HST + cw) * 4,
                      vb + ((long)(j0 >> 1) + jp) * 64 + cw);
        }
        CP_COMMIT();
    };

    load_kv(0, 0);
    load_kv(64, 1);

    /* Q fragments: direct gmem gather into 16 registers (one-time).
       aq[kbk][*] holds exactly the words QH[(kbk*8+tg)*HST + ...] did. */
    uint32_t aq[4][4];
    {
        int r0 = i0 + iw + g;
        #pragma unroll
        for (int kbk = 0; kbk < 4; kbk++) {
            const uint32_t* q0 = qb + (long)(kbk * 8 + tg) * 2048 + r0;
            const uint32_t* q1 = qb + (long)(kbk * 8 + 4 + tg) * 2048 + r0;
            aq[kbk][0] = q0[0];
            aq[kbk][1] = q0[8];
            aq[kbk][2] = q1[0];
            aq[kbk][3] = q1[8];
        }
    }

    float m_s[2], l_s[2];
    float o[8][4];
    m_s[0] = m_s[1] = -1e30f;
    l_s[0] = l_s[1] = 0.f;
    #pragma unroll
    for (int nt = 0; nt < 8; nt++)
        #pragma unroll
        for (int r = 0; r < 4; r++) o[nt][r] = 0.f;

    const int T = NPOS / 64;
    for (int ti = 0; ti < T; ti++) {
        int p = ti & 1;
        if (ti + 1 < T) { CP_WAIT(1); } else { CP_WAIT(0); }
        __syncthreads();                       /* tile ti landed; buf p ready */

        const uint32_t* KH = sm4 + KH_OFF + p * 2304;
        const uint32_t* VH = sm4 + VH_OFF + p * 2304;

        /* ---- S = Q^T K : warp 16i x 64j ---- */
        float sa[8][4];
        #pragma unroll
        for (int nt = 0; nt < 8; nt++)
            #pragma unroll
            for (int r = 0; r < 4; r++) sa[nt][r] = 0.f;

        #pragma unroll
        for (int kbk = 0; kbk < 4; kbk++) {
            int q0 = (kbk * 8 + tg) * HST;
            int q1 = (kbk * 8 + 4 + tg) * HST;
            #pragma unroll
            for (int nt = 0; nt < 8; nt++) {
                uint32_t b0 = KH[q0 + nt * 8 + g];
                uint32_t b1 = KH[q1 + nt * 8 + g];
                mma_f16(sa[nt][0], sa[nt][1], sa[nt][2], sa[nt][3],
                        aq[kbk][0], aq[kbk][1], aq[kbk][2], aq[kbk][3],
                        b0, b1);
            }
        }

        /* ---- online softmax (R14 numerics verbatim) ---- */
        {
            float mx0 = -1e30f, mx1 = -1e30f;
            #pragma unroll
            for (int nt = 0; nt < 8; nt++) {
                mx0 = fmaxf(mx0, fmaxf(sa[nt][0], sa[nt][1]));
                mx1 = fmaxf(mx1, fmaxf(sa[nt][2], sa[nt][3]));
            }
            mx0 = fmaxf(mx0, __shfl_xor_sync(0xffffffffu, mx0, 1));
            mx0 = fmaxf(mx0, __shfl_xor_sync(0xffffffffu, mx0, 2));
            mx1 = fmaxf(mx1, __shfl_xor_sync(0xffffffffu, mx1, 1));
            mx1 = fmaxf(mx1, __shfl_xor_sync(0xffffffffu, mx1, 2));
            float mn0 = fmaxf(m_s[0], mx0);
            float mn1 = fmaxf(m_s[1], mx1);
            float s0 = 0.f, s1 = 0.f;
            int r0 = iw + g;
            #pragma unroll
            for (int nt = 0; nt < 8; nt++) {
                float p0 = __expf(sa[nt][0] - mn0);
                float p1 = __expf(sa[nt][1] - mn0);
                float p2 = __expf(sa[nt][2] - mn1);
                float p3 = __expf(sa[nt][3] - mn1);
                s0 += p0 + p1;  s1 += p2 + p3;
                int jp = nt * 4 + tg;
                PH[jp * HST + r0]     = pk_h2(p0, p1);
                PH[jp * HST + r0 + 8] = pk_h2(p2, p3);
            }
            s0 += __shfl_xor_sync(0xffffffffu, s0, 1);
            s0 += __shfl_xor_sync(0xffffffffu, s0, 2);
            s1 += __shfl_xor_sync(0xffffffffu, s1, 1);
            s1 += __shfl_xor_sync(0xffffffffu, s1, 2);
            float al0 = __expf(m_s[0] - mn0);
            float al1 = __expf(m_s[1] - mn1);
            l_s[0] = l_s[0] * al0 + s0;  m_s[0] = mn0;
            l_s[1] = l_s[1] * al1 + s1;  m_s[1] = mn1;
            #pragma unroll
            for (int nt = 0; nt < 8; nt++) {
                o[nt][0] *= al0; o[nt][1] *= al0;
                o[nt][2] *= al1; o[nt][3] *= al1;
            }
        }
        __syncwarp();                          /* P columns are warp-local */

        /* ---- O += P V^T : warp 16i x 64d ---- */
        #pragma unroll
        for (int jb = 0; jb < 4; jb++) {
            int r0 = iw + g;
            int p0r = (jb * 8 + tg) * HST;
            int p1r = (jb * 8 + 4 + tg) * HST;
            uint32_t a0 = PH[p0r + r0];
            uint32_t a1 = PH[p0r + r0 + 8];
            uint32_t a2 = PH[p1r + r0];
            uint32_t a3 = PH[p1r + r0 + 8];
            #pragma unroll
            for (int nt = 0; nt < 8; nt++) {
                uint32_t b0 = VH[p0r + nt * 8 + g];
                uint32_t b1 = VH[p1r + nt * 8 + g];
                mma_f16(o[nt][0], o[nt][1], o[nt][2], o[nt][3],
                        a0, a1, a2, a3, b0, b1);
            }
        }
        __syncthreads();                       /* all warps done with buf p */
        if (ti + 2 < T) load_kv((ti + 2) * 64, p);
    }

    /* ---- epilogue: normalize, tf32-round, transpose via retired smem ---- */
    {
        float inv0 = 1.f / l_s[0], inv1 = 1.f / l_s[1];
        int r0 = iw + g;
        #pragma unroll
        for (int nt = 0; nt < 8; nt++) {
            int d0 = nt * 8 + 2 * tg;
            sm4[d0 * 68 + r0]           = f2tf(o[nt][0] * inv0);
            sm4[(d0 + 1) * 68 + r0]     = f2tf(o[nt][1] * inv0);
            sm4[d0 * 68 + r0 + 8]       = f2tf(o[nt][2] * inv1);
            sm4[(d0 + 1) * 68 + r0 + 8] = f2tf(o[nt][3] * inv1);
        }
    }
    __syncthreads();
    uint32_t* aop = aoh + ((long)b * 256 + (long)h * 32) * NPOS + i0;
    #pragma unroll
    for (int ss = 0; ss < 4; ss++) {
        int lin = ss * 128 + t;
        int dp = lin >> 4, i4 = (lin & 15) << 2;
        uint4 wv;
        wv.x = pk_h2(__uint_as_float(sm4[(2 * dp) * 68 + i4 + 0]),
                     __uint_as_float(sm4[(2 * dp + 1) * 68 + i4 + 0]));
        wv.y = pk_h2(__uint_as_float(sm4[(2 * dp) * 68 + i4 + 1]),
                     __uint_as_float(sm4[(2 * dp + 1) * 68 + i4 + 1]));
        wv.z = pk_h2(__uint_as_float(sm4[(2 * dp) * 68 + i4 + 2]),
                     __uint_as_float(sm4[(2 * dp + 1) * 68 + i4 + 2]));
        wv.w = pk_h2(__uint_as_float(sm4[(2 * dp) * 68 + i4 + 3]),
                     __uint_as_float(sm4[(2 * dp + 1) * 68 + i4 + 3]));
        *(uint4*)(aop + (long)dp * NPOS + i4) = wv;
    }
}

/* ===================================================================== */
extern "C" void kernel_launch(void* const* d_in, const int* in_sizes, int n_in,
                              void* d_out, int out_size) {
    const float* x    = (const float*)d_in[0];
    const float* g    = (const float*)d_in[1];
    const float* Wqkv = (const float*)d_in[2];
    const float* Wout = (const float*)d_in[3];
    const float* bout = (const float*)d_in[4];
    float* out = (float*)d_out;

    uint32_t *xnh, *aoh, *wqh, *woh, *qpk, *kpk, *vpk;
    cudaGetSymbolAddress((void**)&xnh, g_xnh);
    cudaGetSymbolAddress((void**)&aoh, g_aoh);
    cudaGetSymbolAddress((void**)&wqh, g_wqh);
    cudaGetSymbolAddress((void**)&woh, g_woh);
    cudaGetSymbolAddress((void**)&qpk, g_qpk);
    cudaGetSymbolAddress((void**)&kpk, g_kpk);
    cudaGetSymbolAddress((void**)&vpk, g_vpk);

    /* 0. one-time weight prepack */
    pack_w<<<(QKV_ROWS * 256) / 256, 256>>>(Wqkv, wqh, QKV_ROWS, CDIM);
    pack_w<<<(CDIM * 256) / 256, 256>>>(Wout, woh, CDIM, HIDDEN);

    /* 1. LayerNorm -> packed half2 */
    ln_kernel<<<(BATCH * NPOS) / 64, 512>>>(x, g, xnh);

    /* 2. QKV projection with fused pack epilogue */
    cudaFuncSetAttribute(gemm_qkv,
                         cudaFuncAttributeMaxDynamicSharedMemorySize, GEMM16_SMEM);
    gemm_qkv<<<dim3(QKV_ROWS / 128, NPOS / 128, BATCH), 256, GEMM16_SMEM>>>(
        wqh, xnh, qpk, kpk, vpk, QKV_ROWS, CDIM);

    /* 3. fused fp16 attention (double-buffered K/V, Q in regs) */
    size_t smem = ATTN_SMEM_WORDS * sizeof(uint32_t);   /* 46080 B */
    cudaFuncSetAttribute(attn_f16,
                         cudaFuncAttributeMaxDynamicSharedMemorySize, (int)smem);
    attn_f16<<<dim3(NPOS / 64, BATCH * HEADS), 128, smem>>>(qpk, kpk, vpk, aoh);

    /* 4. output projection + bias (fp32 out) */
    cudaFuncSetAttribute(gemm_f16,
                         cudaFuncAttributeMaxDynamicSharedMemorySize, GEMM16_SMEM);
    gemm_f16<<<dim3(HIDDEN / 128, NPOS / 128, BATCH), 256, GEMM16_SMEM>>>(
        woh, aoh, out, bout, HIDDEN, CDIM);
}